// round 6
// baseline (speedup 1.0000x reference)
#include <cuda_runtime.h>

#define NQ 262144
#define MB 4096
#define PI_F 3.14159265358979323846f

// ------------------------- device scratch (no allocs) -----------------------
__device__ __align__(16) float g_h[(size_t)NQ * 128];
__device__ __align__(16) float g_x[(size_t)NQ * 128];
__device__ __align__(16) float g_benc[MB * 128];
__device__ __align__(16) float g_kvp[12 * 32 * 1024];  // per (l,h,tile) partial kv
__device__ __align__(16) float g_ksp[12 * 32 * 32];    // per (l,h,tile) partial ksum
__device__ __align__(16) float g_kv[12 * 1024];
__device__ __align__(16) float g_ksum[384];            // [l*128 + h*32 + e]
__device__ __align__(16) float g_C[3 * 16384];         // folded kv @ Wo, [l][j][o]

__device__ __forceinline__ float geluf(float u) {
    return 0.5f * u * (1.0f + erff(u * 0.70710678118654752f));
}

// ---------------------------------------------------------------------------
// Positional encoder: dst[p][:] = sin(mfe(pts[p]) @ W + b). 64 pts / CTA.
// ---------------------------------------------------------------------------
__global__ void __launch_bounds__(256) encode_kernel(
    const float* __restrict__ pts, const float* __restrict__ w,
    const float* __restrict__ b, int which)
{
    __shared__ float sW[3840];
    __shared__ float sB[128];
    __shared__ float sF[64 * 32];
    int t = threadIdx.x;
    for (int i = t; i < 960; i += 256) ((float4*)sW)[i] = ((const float4*)w)[i];
    if (t < 128) sB[t] = b[t];
    size_t pt0 = (size_t)blockIdx.x * 64;
    if (t < 64) {
        float2 xy = ((const float2*)pts)[pt0 + t];
        float* F = sF + t * 32;
        #pragma unroll
        for (int c = 0; c < 2; ++c) {
            float v = c ? xy.y : xy.x;
            float a15 = v - 1.5f, a45 = v - 4.5f, pv = PI_F * v;
            F[0 + c] = v;           F[2 + c] = v * v;
            F[4 + c] = a15 * a15;   F[6 + c] = a45 * a45;
            F[8 + c]  = 1.f / (1.f + expf(-v));
            F[10 + c] = 1.f / (1.f + expf(-a15));
            F[12 + c] = 1.f / (1.f + expf(-a45));
            F[14 + c] = a15;        F[16 + c] = a45;
            F[18 + c] = sinf(pv);          F[20 + c] = cosf(pv);
            F[22 + c] = sinf(pv * 0.25f);  F[24 + c] = cosf(pv * 0.25f);
            F[26 + c] = sinf(pv * 0.5f);   F[28 + c] = cosf(pv * 0.5f);
        }
    }
    __syncthreads();
    int wid = t >> 5, lane = t & 31;
    int m0 = wid * 8, jc = lane * 4;
    float acc[8][4];
    #pragma unroll
    for (int i = 0; i < 8; ++i) { acc[i][0]=acc[i][1]=acc[i][2]=acc[i][3]=0.f; }
    #pragma unroll 2
    for (int k = 0; k < 30; ++k) {
        float4 b4 = *(const float4*)(sW + k * 128 + jc);
        #pragma unroll
        for (int i = 0; i < 8; ++i) {
            float a = sF[(m0 + i) * 32 + k];
            acc[i][0] = fmaf(a, b4.x, acc[i][0]);
            acc[i][1] = fmaf(a, b4.y, acc[i][1]);
            acc[i][2] = fmaf(a, b4.z, acc[i][2]);
            acc[i][3] = fmaf(a, b4.w, acc[i][3]);
        }
    }
    float b0 = sB[jc], b1 = sB[jc+1], b2 = sB[jc+2], b3 = sB[jc+3];
    float* dst = which ? g_benc : g_h;
    #pragma unroll
    for (int i = 0; i < 8; ++i) {
        float4 o;
        o.x = sinf(acc[i][0] + b0); o.y = sinf(acc[i][1] + b1);
        o.z = sinf(acc[i][2] + b2); o.w = sinf(acc[i][3] + b3);
        *(float4*)(dst + (pt0 + m0 + i) * 128 + jc) = o;
    }
}

// ---------------------------------------------------------------------------
// Boundary k/v: per (tile of 128 rows, lh = l*4+h) partial kv and ksum.
// kh = (e@Wk + bk)^2 ; vh = e@Wv + bv ; kv += kh^T vh ; ksum += sum kh.
// ---------------------------------------------------------------------------
#define BKV_SMEM (34372 * 4)
__global__ void __launch_bounds__(256) bkv_kernel(
    const float* __restrict__ Wk_g, const float* __restrict__ bk_g,
    const float* __restrict__ Wv_g, const float* __restrict__ bv_g)
{
    extern __shared__ float sm[];
    float* sE  = sm;              // 128 x 132
    float* sWk = sE + 16896;      // 4096
    float* sWv = sWk + 4100;      // 4096 (pad 4 to split banks)
    float* sKh = sWv + 4096;      // 128 x 36
    float* sVh = sKh + 4608;      // 128 x 36
    float* sbk = sVh + 4608;      // 32
    float* sbv = sbk + 32;        // 32
    int t = threadIdx.x;
    int tile = blockIdx.x, lh = blockIdx.y;
    {
        const float4* src = (const float4*)(g_benc + (size_t)tile * 128 * 128);
        for (int i = t; i < 4096; i += 256) {
            int r = i >> 5, c = i & 31;
            *(float4*)(sE + r * 132 + c * 4) = src[i];
        }
    }
    for (int i = t; i < 1024; i += 256) {
        ((float4*)sWk)[i] = ((const float4*)(Wk_g + (size_t)lh * 4096))[i];
        ((float4*)sWv)[i] = ((const float4*)(Wv_g + (size_t)lh * 4096))[i];
    }
    if (t < 32) { sbk[t] = bk_g[lh * 32 + t]; sbv[t] = bv_g[lh * 32 + t]; }
    __syncthreads();
    {
        int m = t >> 1, kind = t & 1;
        const float* W  = kind ? sWv : sWk;
        const float* sb = kind ? sbv : sbk;
        float4 acc[8];
        #pragma unroll
        for (int g = 0; g < 8; ++g) acc[g] = make_float4(0.f, 0.f, 0.f, 0.f);
        for (int d = 0; d < 128; ++d) {
            float v = sE[m * 132 + d];
            #pragma unroll
            for (int g = 0; g < 8; ++g) {
                float4 w4 = *(const float4*)(W + d * 32 + g * 4);
                acc[g].x = fmaf(v, w4.x, acc[g].x);
                acc[g].y = fmaf(v, w4.y, acc[g].y);
                acc[g].z = fmaf(v, w4.z, acc[g].z);
                acc[g].w = fmaf(v, w4.w, acc[g].w);
            }
        }
        float* dst = (kind ? sVh : sKh) + m * 36;
        #pragma unroll
        for (int g = 0; g < 8; ++g) {
            float4 a = acc[g];
            a.x += sb[g*4+0]; a.y += sb[g*4+1]; a.z += sb[g*4+2]; a.w += sb[g*4+3];
            if (!kind) { a.x *= a.x; a.y *= a.y; a.z *= a.z; a.w *= a.w; }
            *(float4*)(dst + g * 4) = a;
        }
    }
    __syncthreads();
    {
        int e = t >> 3, c4 = (t & 7) * 4;
        float4 acc = make_float4(0.f, 0.f, 0.f, 0.f);
        for (int m = 0; m < 128; ++m) {
            float kh = sKh[m * 36 + e];
            float4 v4 = *(const float4*)(sVh + m * 36 + c4);
            acc.x = fmaf(kh, v4.x, acc.x); acc.y = fmaf(kh, v4.y, acc.y);
            acc.z = fmaf(kh, v4.z, acc.z); acc.w = fmaf(kh, v4.w, acc.w);
        }
        *(float4*)(g_kvp + ((size_t)lh * 32 + tile) * 1024 + e * 32 + c4) = acc;
        if (t < 32) {
            float s = 0.f;
            for (int m = 0; m < 128; ++m) s += sKh[m * 36 + t];
            g_ksp[((size_t)lh * 32 + tile) * 32 + t] = s;
        }
    }
}

__global__ void __launch_bounds__(256) kvreduce_kernel()
{
    int lh = blockIdx.x, t = threadIdx.x;
    for (int idx = t; idx < 1024; idx += 256) {
        float s = 0.f;
        for (int tile = 0; tile < 32; ++tile)
            s += g_kvp[((size_t)lh * 32 + tile) * 1024 + idx];
        g_kv[lh * 1024 + idx] = s;
    }
    if (t < 32) {
        float s = 0.f;
        for (int tile = 0; tile < 32; ++tile)
            s += g_ksp[((size_t)lh * 32 + tile) * 32 + t];
        g_ksum[lh * 32 + t] = s;
    }
}

// C[l][j=h*32+e][o] = sum_ep kv[l][h][e][ep] * Wo[l][h*32+ep][o]
__global__ void __launch_bounds__(256) cfold_kernel(const float* __restrict__ Wo_g)
{
    int l = blockIdx.x, t = threadIdx.x;
    int j = t >> 1, oc = (t & 1) * 64;
    int h = j >> 5, e = j & 31;
    float acc[64];
    #pragma unroll
    for (int o = 0; o < 64; ++o) acc[o] = 0.f;
    for (int ep = 0; ep < 32; ++ep) {
        float kv = g_kv[(l * 4 + h) * 1024 + e * 32 + ep];
        const float4* wr = (const float4*)(Wo_g + ((size_t)(l * 128 + h * 32 + ep)) * 128 + oc);
        #pragma unroll
        for (int g = 0; g < 16; ++g) {
            float4 w4 = __ldg(wr + g);
            acc[g*4+0] = fmaf(kv, w4.x, acc[g*4+0]);
            acc[g*4+1] = fmaf(kv, w4.y, acc[g*4+1]);
            acc[g*4+2] = fmaf(kv, w4.z, acc[g*4+2]);
            acc[g*4+3] = fmaf(kv, w4.w, acc[g*4+3]);
        }
    }
    float4* dst = (float4*)(g_C + (size_t)l * 16384 + j * 128 + oc);
    #pragma unroll
    for (int g = 0; g < 16; ++g)
        dst[g] = make_float4(acc[g*4], acc[g*4+1], acc[g*4+2], acc[g*4+3]);
}

// ---------------------------------------------------------------------------
// Attention layer (queries): Q' = z * (h@Wq + bq)^2 ; x = h + Q'@C + bo.
// ---------------------------------------------------------------------------
#define ATTN_SMEM (33152 * 4)
__global__ void __launch_bounds__(256) attn_kernel(
    const float* __restrict__ Wq_l, const float* __restrict__ bq_l,
    const float* __restrict__ bo_l, int l)
{
    extern __shared__ float sm[];
    float* sH  = sm;            // 64 x 128
    float* sQ  = sH + 8192;     // 64 x 128
    float* sW  = sQ + 8192;     // 128 x 128 (Wq-concat, then C)
    float* sKs = sW + 16384;    // 128
    float* sBq = sKs + 128;
    float* sBo = sBq + 128;
    int t = threadIdx.x;
    size_t pt0 = (size_t)blockIdx.x * 64;
    {
        const float4* src = (const float4*)(g_h + pt0 * 128);
        for (int i = t; i < 2048; i += 256) ((float4*)sH)[i] = src[i];
    }
    for (int i = t; i < 4096; i += 256) {
        int h = i >> 10, r = i & 1023, d = r >> 3, g = r & 7;
        ((float4*)sW)[d * 32 + h * 8 + g] = ((const float4*)Wq_l)[i];
    }
    if (t < 128) { sKs[t] = g_ksum[l * 128 + t]; sBq[t] = bq_l[t]; sBo[t] = bo_l[t]; }
    __syncthreads();
    int wid = t >> 5, lane = t & 31;
    int m0 = wid * 8, jc = lane * 4;
    float acc[8][4];
    #pragma unroll
    for (int i = 0; i < 8; ++i) { acc[i][0]=acc[i][1]=acc[i][2]=acc[i][3]=0.f; }
    #pragma unroll 2
    for (int d = 0; d < 128; ++d) {
        float4 b4 = *(const float4*)(sW + d * 128 + jc);
        #pragma unroll
        for (int i = 0; i < 8; ++i) {
            float a = sH[(m0 + i) * 128 + d];
            acc[i][0] = fmaf(a, b4.x, acc[i][0]);
            acc[i][1] = fmaf(a, b4.y, acc[i][1]);
            acc[i][2] = fmaf(a, b4.z, acc[i][2]);
            acc[i][3] = fmaf(a, b4.w, acc[i][3]);
        }
    }
    {
        float k0 = sKs[jc], k1 = sKs[jc+1], k2 = sKs[jc+2], k3 = sKs[jc+3];
        float b0 = sBq[jc], b1 = sBq[jc+1], b2 = sBq[jc+2], b3 = sBq[jc+3];
        #pragma unroll
        for (int i = 0; i < 8; ++i) {
            float q0 = acc[i][0] + b0; q0 *= q0;
            float q1 = acc[i][1] + b1; q1 *= q1;
            float q2 = acc[i][2] + b2; q2 *= q2;
            float q3 = acc[i][3] + b3; q3 *= q3;
            float p = q0*k0 + q1*k1 + q2*k2 + q3*k3;
            p += __shfl_xor_sync(0xffffffffu, p, 1);
            p += __shfl_xor_sync(0xffffffffu, p, 2);
            p += __shfl_xor_sync(0xffffffffu, p, 4);
            float z = 1.0f / (p + 1e-6f);
            *(float4*)(sQ + (m0 + i) * 128 + jc) = make_float4(q0*z, q1*z, q2*z, q3*z);
        }
    }
    __syncthreads();
    {
        const float4* src = (const float4*)(g_C + (size_t)l * 16384);
        for (int i = t; i < 4096; i += 256) ((float4*)sW)[i] = src[i];
    }
    __syncthreads();
    float acc2[8][4];
    #pragma unroll
    for (int i = 0; i < 8; ++i) { acc2[i][0]=acc2[i][1]=acc2[i][2]=acc2[i][3]=0.f; }
    #pragma unroll 2
    for (int j = 0; j < 128; ++j) {
        float4 b4 = *(const float4*)(sW + j * 128 + jc);
        #pragma unroll
        for (int i = 0; i < 8; ++i) {
            float a = sQ[(m0 + i) * 128 + j];
            acc2[i][0] = fmaf(a, b4.x, acc2[i][0]);
            acc2[i][1] = fmaf(a, b4.y, acc2[i][1]);
            acc2[i][2] = fmaf(a, b4.z, acc2[i][2]);
            acc2[i][3] = fmaf(a, b4.w, acc2[i][3]);
        }
    }
    float o0 = sBo[jc], o1 = sBo[jc+1], o2 = sBo[jc+2], o3 = sBo[jc+3];
    #pragma unroll
    for (int i = 0; i < 8; ++i) {
        float4 hv = *(const float4*)(sH + (m0 + i) * 128 + jc);
        float4 o = make_float4(hv.x + acc2[i][0] + o0, hv.y + acc2[i][1] + o1,
                               hv.z + acc2[i][2] + o2, hv.w + acc2[i][3] + o3);
        *(float4*)(g_x + (pt0 + m0 + i) * 128 + jc) = o;
    }
}

// ---------------------------------------------------------------------------
// FFN layer: h = x + gelu(x@W1 + b1) @ W2 + b2
// ---------------------------------------------------------------------------
#define FFN_SMEM (33024 * 4)
__global__ void __launch_bounds__(256) ffn_kernel(
    const float* __restrict__ W1_l, const float* __restrict__ b1_l,
    const float* __restrict__ W2_l, const float* __restrict__ b2_l)
{
    extern __shared__ float sm[];
    float* sX  = sm;
    float* sT  = sX + 8192;
    float* sW  = sT + 8192;
    float* sB1 = sW + 16384;
    float* sB2 = sB1 + 128;
    int t = threadIdx.x;
    size_t pt0 = (size_t)blockIdx.x * 64;
    {
        const float4* src = (const float4*)(g_x + pt0 * 128);
        for (int i = t; i < 2048; i += 256) ((float4*)sX)[i] = src[i];
    }
    for (int i = t; i < 4096; i += 256) ((float4*)sW)[i] = ((const float4*)W1_l)[i];
    if (t < 128) { sB1[t] = b1_l[t]; sB2[t] = b2_l[t]; }
    __syncthreads();
    int wid = t >> 5, lane = t & 31;
    int m0 = wid * 8, jc = lane * 4;
    float acc[8][4];
    #pragma unroll
    for (int i = 0; i < 8; ++i) { acc[i][0]=acc[i][1]=acc[i][2]=acc[i][3]=0.f; }
    #pragma unroll 2
    for (int d = 0; d < 128; ++d) {
        float4 b4 = *(const float4*)(sW + d * 128 + jc);
        #pragma unroll
        for (int i = 0; i < 8; ++i) {
            float a = sX[(m0 + i) * 128 + d];
            acc[i][0] = fmaf(a, b4.x, acc[i][0]);
            acc[i][1] = fmaf(a, b4.y, acc[i][1]);
            acc[i][2] = fmaf(a, b4.z, acc[i][2]);
            acc[i][3] = fmaf(a, b4.w, acc[i][3]);
        }
    }
    {
        float b0 = sB1[jc], b1 = sB1[jc+1], b2 = sB1[jc+2], b3 = sB1[jc+3];
        #pragma unroll
        for (int i = 0; i < 8; ++i) {
            float4 o = make_float4(geluf(acc[i][0] + b0), geluf(acc[i][1] + b1),
                                   geluf(acc[i][2] + b2), geluf(acc[i][3] + b3));
            *(float4*)(sT + (m0 + i) * 128 + jc) = o;
        }
    }
    __syncthreads();
    for (int i = t; i < 4096; i += 256) ((float4*)sW)[i] = ((const float4*)W2_l)[i];
    __syncthreads();
    float acc2[8][4];
    #pragma unroll
    for (int i = 0; i < 8; ++i) { acc2[i][0]=acc2[i][1]=acc2[i][2]=acc2[i][3]=0.f; }
    #pragma unroll 2
    for (int d = 0; d < 128; ++d) {
        float4 b4 = *(const float4*)(sW + d * 128 + jc);
        #pragma unroll
        for (int i = 0; i < 8; ++i) {
            float a = sT[(m0 + i) * 128 + d];
            acc2[i][0] = fmaf(a, b4.x, acc2[i][0]);
            acc2[i][1] = fmaf(a, b4.y, acc2[i][1]);
            acc2[i][2] = fmaf(a, b4.z, acc2[i][2]);
            acc2[i][3] = fmaf(a, b4.w, acc2[i][3]);
        }
    }
    float c0 = sB2[jc], c1 = sB2[jc+1], c2 = sB2[jc+2], c3 = sB2[jc+3];
    #pragma unroll
    for (int i = 0; i < 8; ++i) {
        float4 xv = *(const float4*)(sX + (m0 + i) * 128 + jc);
        float4 o = make_float4(xv.x + acc2[i][0] + c0, xv.y + acc2[i][1] + c1,
                               xv.z + acc2[i][2] + c2, xv.w + acc2[i][3] + c3);
        *(float4*)(g_h + (pt0 + m0 + i) * 128 + jc) = o;
    }
}

// ---------------------------------------------------------------------------
// Final projector: out = gelu(h @ pw1 + pb1) @ pw2 + pb2
// ---------------------------------------------------------------------------
#define FIN_SMEM (20812 * 4)
__global__ void __launch_bounds__(256) final_kernel(
    const float* __restrict__ pw1, const float* __restrict__ pb1,
    const float* __restrict__ pw2, const float* __restrict__ pb2,
    float* __restrict__ out)
{
    extern __shared__ float sm[];
    float* sH   = sm;
    float* sW1  = sH + 8192;     // 128 x 64
    float* sT   = sW1 + 8192;    // 64 x 65
    float* spw2 = sT + 4160;     // 192
    float* spb1 = spw2 + 192;    // 64
    float* spb2 = spb1 + 64;     // 3
    int t = threadIdx.x;
    size_t pt0 = (size_t)blockIdx.x * 64;
    {
        const float4* src = (const float4*)(g_h + pt0 * 128);
        for (int i = t; i < 2048; i += 256) ((float4*)sH)[i] = src[i];
    }
    for (int i = t; i < 2048; i += 256) ((float4*)sW1)[i] = ((const float4*)pw1)[i];
    if (t < 192) spw2[t] = pw2[t];
    if (t < 64)  spb1[t] = pb1[t];
    if (t < 3)   spb2[t] = pb2[t];
    __syncthreads();
    int wid = t >> 5, lane = t & 31;
    int m0 = wid * 8, jc = lane * 2;
    float acc[8][2];
    #pragma unroll
    for (int i = 0; i < 8; ++i) { acc[i][0] = acc[i][1] = 0.f; }
    #pragma unroll 2
    for (int k = 0; k < 128; ++k) {
        float2 b2v = *(const float2*)(sW1 + k * 64 + jc);
        #pragma unroll
        for (int i = 0; i < 8; ++i) {
            float a = sH[(m0 + i) * 128 + k];
            acc[i][0] = fmaf(a, b2v.x, acc[i][0]);
            acc[i][1] = fmaf(a, b2v.y, acc[i][1]);
        }
    }
    float c0 = spb1[jc], c1 = spb1[jc + 1];
    #pragma unroll
    for (int i = 0; i < 8; ++i) {
        sT[(m0 + i) * 65 + jc]     = geluf(acc[i][0] + c0);
        sT[(m0 + i) * 65 + jc + 1] = geluf(acc[i][1] + c1);
    }
    __syncthreads();
    if (t < 192) {
        int n = t / 3, c = t - n * 3;
        float s = spb2[c];
        #pragma unroll 4
        for (int k = 0; k < 64; ++k) s = fmaf(sT[n * 65 + k], spw2[k * 3 + c], s);
        out[(pt0 + n) * 3 + c] = s;
    }
}

// ---------------------------------------------------------------------------
extern "C" void kernel_launch(void* const* d_in, const int* in_sizes, int n_in,
                              void* d_out, int out_size)
{
    const float* qp    = (const float*)d_in[0];
    const float* bp    = (const float*)d_in[1];
    const float* pe_w  = (const float*)d_in[2];
    const float* pe_b  = (const float*)d_in[3];
    const float* bpe_w = (const float*)d_in[4];
    const float* bpe_b = (const float*)d_in[5];
    const float* Wq    = (const float*)d_in[6];
    const float* bq    = (const float*)d_in[7];
    const float* Wk    = (const float*)d_in[8];
    const float* bk    = (const float*)d_in[9];
    const float* Wv    = (const float*)d_in[10];
    const float* bv    = (const float*)d_in[11];
    const float* Wo    = (const float*)d_in[12];
    const float* bo    = (const float*)d_in[13];
    const float* W1    = (const float*)d_in[14];
    const float* b1    = (const float*)d_in[15];
    const float* W2    = (const float*)d_in[16];
    const float* b2    = (const float*)d_in[17];
    const float* pw1   = (const float*)d_in[18];
    const float* pb1   = (const float*)d_in[19];
    const float* pw2   = (const float*)d_in[20];
    const float* pb2   = (const float*)d_in[21];
    float* out = (float*)d_out;

    cudaFuncSetAttribute(bkv_kernel,   cudaFuncAttributeMaxDynamicSharedMemorySize, BKV_SMEM);
    cudaFuncSetAttribute(attn_kernel,  cudaFuncAttributeMaxDynamicSharedMemorySize, ATTN_SMEM);
    cudaFuncSetAttribute(ffn_kernel,   cudaFuncAttributeMaxDynamicSharedMemorySize, FFN_SMEM);
    cudaFuncSetAttribute(final_kernel, cudaFuncAttributeMaxDynamicSharedMemorySize, FIN_SMEM);

    encode_kernel<<<64,   256>>>(bp, bpe_w, bpe_b, 1);
    encode_kernel<<<4096, 256>>>(qp, pe_w,  pe_b,  0);
    bkv_kernel<<<dim3(32, 12), 256, BKV_SMEM>>>(Wk, bk, Wv, bv);
    kvreduce_kernel<<<12, 256>>>();
    cfold_kernel<<<3, 256>>>(Wo);
    for (int l = 0; l < 3; ++l) {
        attn_kernel<<<4096, 256, ATTN_SMEM>>>(Wq + (size_t)l * 16384, bq + l * 128, bo + l * 128, l);
        ffn_kernel <<<4096, 256, FFN_SMEM>>>(W1 + (size_t)l * 16384, b1 + l * 128,
                                             W2 + (size_t)l * 16384, b2 + l * 128);
    }
    final_kernel<<<4096, 256, FIN_SMEM>>>(pw1, pb1, pw2, pb2, out);
}

// round 7
// speedup vs baseline: 1.0019x; 1.0019x over previous
#include <cuda_runtime.h>

#define NQ 262144
#define MB 4096
#define PI_F 3.14159265358979323846f

// ------------------------- device scratch (no allocs) -----------------------
__device__ __align__(16) float g_h[(size_t)NQ * 128];
__device__ __align__(16) float g_x[(size_t)NQ * 128];
__device__ __align__(16) float g_benc[MB * 128];
__device__ __align__(16) float g_kvp[12 * 32 * 1024];  // per (l,h,tile) partial kv
__device__ __align__(16) float g_ksp[12 * 32 * 32];    // per (l,h,tile) partial ksum
__device__ __align__(16) float g_kv[12 * 1024];
__device__ __align__(16) float g_ksum[384];            // [l*128 + h*32 + e]
__device__ __align__(16) float g_C[3 * 16384];         // folded kv @ Wo, [l][j][o]

__device__ __forceinline__ float geluf(float u) {
    return 0.5f * u * (1.0f + erff(u * 0.70710678118654752f));
}

// ---------------------------------------------------------------------------
// Positional encoder: dst[p][:] = sin(mfe(pts[p]) @ W + b). 64 pts / CTA.
// ---------------------------------------------------------------------------
__global__ void __launch_bounds__(256) encode_kernel(
    const float* __restrict__ pts, const float* __restrict__ w,
    const float* __restrict__ b, int which)
{
    __shared__ float sW[3840];
    __shared__ float sB[128];
    __shared__ float sF[64 * 32];
    int t = threadIdx.x;
    for (int i = t; i < 960; i += 256) ((float4*)sW)[i] = ((const float4*)w)[i];
    if (t < 128) sB[t] = b[t];
    size_t pt0 = (size_t)blockIdx.x * 64;
    if (t < 64) {
        float2 xy = ((const float2*)pts)[pt0 + t];
        float* F = sF + t * 32;
        #pragma unroll
        for (int c = 0; c < 2; ++c) {
            float v = c ? xy.y : xy.x;
            float a15 = v - 1.5f, a45 = v - 4.5f, pv = PI_F * v;
            F[0 + c] = v;           F[2 + c] = v * v;
            F[4 + c] = a15 * a15;   F[6 + c] = a45 * a45;
            F[8 + c]  = 1.f / (1.f + expf(-v));
            F[10 + c] = 1.f / (1.f + expf(-a15));
            F[12 + c] = 1.f / (1.f + expf(-a45));
            F[14 + c] = a15;        F[16 + c] = a45;
            F[18 + c] = sinf(pv);          F[20 + c] = cosf(pv);
            F[22 + c] = sinf(pv * 0.25f);  F[24 + c] = cosf(pv * 0.25f);
            F[26 + c] = sinf(pv * 0.5f);   F[28 + c] = cosf(pv * 0.5f);
        }
    }
    __syncthreads();
    int wid = t >> 5, lane = t & 31;
    int m0 = wid * 8, jc = lane * 4;
    float acc[8][4];
    #pragma unroll
    for (int i = 0; i < 8; ++i) { acc[i][0]=acc[i][1]=acc[i][2]=acc[i][3]=0.f; }
    #pragma unroll 2
    for (int k = 0; k < 30; ++k) {
        float4 b4 = *(const float4*)(sW + k * 128 + jc);
        #pragma unroll
        for (int i = 0; i < 8; ++i) {
            float a = sF[(m0 + i) * 32 + k];
            acc[i][0] = fmaf(a, b4.x, acc[i][0]);
            acc[i][1] = fmaf(a, b4.y, acc[i][1]);
            acc[i][2] = fmaf(a, b4.z, acc[i][2]);
            acc[i][3] = fmaf(a, b4.w, acc[i][3]);
        }
    }
    float b0 = sB[jc], b1 = sB[jc+1], b2 = sB[jc+2], b3 = sB[jc+3];
    float* dst = which ? g_benc : g_h;
    #pragma unroll
    for (int i = 0; i < 8; ++i) {
        float4 o;
        o.x = sinf(acc[i][0] + b0); o.y = sinf(acc[i][1] + b1);
        o.z = sinf(acc[i][2] + b2); o.w = sinf(acc[i][3] + b3);
        *(float4*)(dst + (pt0 + m0 + i) * 128 + jc) = o;
    }
}

// ---------------------------------------------------------------------------
// Boundary k/v: per (tile of 128 rows, lh = l*4+h) partial kv and ksum.
// kh = (e@Wk + bk)^2 ; vh = e@Wv + bv ; kv += kh^T vh ; ksum += sum kh.
// ---------------------------------------------------------------------------
#define BKV_SMEM (34372 * 4)
__global__ void __launch_bounds__(256) bkv_kernel(
    const float* __restrict__ Wk_g, const float* __restrict__ bk_g,
    const float* __restrict__ Wv_g, const float* __restrict__ bv_g)
{
    extern __shared__ float sm[];
    float* sE  = sm;              // 128 x 132
    float* sWk = sE + 16896;      // 4096
    float* sWv = sWk + 4100;      // 4096 (pad 4 to split banks)
    float* sKh = sWv + 4096;      // 128 x 36
    float* sVh = sKh + 4608;      // 128 x 36
    float* sbk = sVh + 4608;      // 32
    float* sbv = sbk + 32;        // 32
    int t = threadIdx.x;
    int tile = blockIdx.x, lh = blockIdx.y;
    {
        const float4* src = (const float4*)(g_benc + (size_t)tile * 128 * 128);
        for (int i = t; i < 4096; i += 256) {
            int r = i >> 5, c = i & 31;
            *(float4*)(sE + r * 132 + c * 4) = src[i];
        }
    }
    for (int i = t; i < 1024; i += 256) {
        ((float4*)sWk)[i] = ((const float4*)(Wk_g + (size_t)lh * 4096))[i];
        ((float4*)sWv)[i] = ((const float4*)(Wv_g + (size_t)lh * 4096))[i];
    }
    if (t < 32) { sbk[t] = bk_g[lh * 32 + t]; sbv[t] = bv_g[lh * 32 + t]; }
    __syncthreads();
    {
        int m = t >> 1, kind = t & 1;
        const float* W  = kind ? sWv : sWk;
        const float* sb = kind ? sbv : sbk;
        float4 acc[8];
        #pragma unroll
        for (int g = 0; g < 8; ++g) acc[g] = make_float4(0.f, 0.f, 0.f, 0.f);
        for (int d = 0; d < 128; ++d) {
            float v = sE[m * 132 + d];
            #pragma unroll
            for (int g = 0; g < 8; ++g) {
                float4 w4 = *(const float4*)(W + d * 32 + g * 4);
                acc[g].x = fmaf(v, w4.x, acc[g].x);
                acc[g].y = fmaf(v, w4.y, acc[g].y);
                acc[g].z = fmaf(v, w4.z, acc[g].z);
                acc[g].w = fmaf(v, w4.w, acc[g].w);
            }
        }
        float* dst = (kind ? sVh : sKh) + m * 36;
        #pragma unroll
        for (int g = 0; g < 8; ++g) {
            float4 a = acc[g];
            a.x += sb[g*4+0]; a.y += sb[g*4+1]; a.z += sb[g*4+2]; a.w += sb[g*4+3];
            if (!kind) { a.x *= a.x; a.y *= a.y; a.z *= a.z; a.w *= a.w; }
            *(float4*)(dst + g * 4) = a;
        }
    }
    __syncthreads();
    {
        int e = t >> 3, c4 = (t & 7) * 4;
        float4 acc = make_float4(0.f, 0.f, 0.f, 0.f);
        for (int m = 0; m < 128; ++m) {
            float kh = sKh[m * 36 + e];
            float4 v4 = *(const float4*)(sVh + m * 36 + c4);
            acc.x = fmaf(kh, v4.x, acc.x); acc.y = fmaf(kh, v4.y, acc.y);
            acc.z = fmaf(kh, v4.z, acc.z); acc.w = fmaf(kh, v4.w, acc.w);
        }
        *(float4*)(g_kvp + ((size_t)lh * 32 + tile) * 1024 + e * 32 + c4) = acc;
        if (t < 32) {
            float s = 0.f;
            for (int m = 0; m < 128; ++m) s += sKh[m * 36 + t];
            g_ksp[((size_t)lh * 32 + tile) * 32 + t] = s;
        }
    }
}

__global__ void __launch_bounds__(256) kvreduce_kernel()
{
    int lh = blockIdx.x, t = threadIdx.x;
    for (int idx = t; idx < 1024; idx += 256) {
        float s = 0.f;
        for (int tile = 0; tile < 32; ++tile)
            s += g_kvp[((size_t)lh * 32 + tile) * 1024 + idx];
        g_kv[lh * 1024 + idx] = s;
    }
    if (t < 32) {
        float s = 0.f;
        for (int tile = 0; tile < 32; ++tile)
            s += g_ksp[((size_t)lh * 32 + tile) * 32 + t];
        g_ksum[lh * 32 + t] = s;
    }
}

// C[l][j=h*32+e][o] = sum_ep kv[l][h][e][ep] * Wo[l][h*32+ep][o]
__global__ void __launch_bounds__(256) cfold_kernel(const float* __restrict__ Wo_g)
{
    int l = blockIdx.x, t = threadIdx.x;
    int j = t >> 1, oc = (t & 1) * 64;
    int h = j >> 5, e = j & 31;
    float acc[64];
    #pragma unroll
    for (int o = 0; o < 64; ++o) acc[o] = 0.f;
    for (int ep = 0; ep < 32; ++ep) {
        float kv = g_kv[(l * 4 + h) * 1024 + e * 32 + ep];
        const float4* wr = (const float4*)(Wo_g + ((size_t)(l * 128 + h * 32 + ep)) * 128 + oc);
        #pragma unroll
        for (int g = 0; g < 16; ++g) {
            float4 w4 = __ldg(wr + g);
            acc[g*4+0] = fmaf(kv, w4.x, acc[g*4+0]);
            acc[g*4+1] = fmaf(kv, w4.y, acc[g*4+1]);
            acc[g*4+2] = fmaf(kv, w4.z, acc[g*4+2]);
            acc[g*4+3] = fmaf(kv, w4.w, acc[g*4+3]);
        }
    }
    float4* dst = (float4*)(g_C + (size_t)l * 16384 + j * 128 + oc);
    #pragma unroll
    for (int g = 0; g < 16; ++g)
        dst[g] = make_float4(acc[g*4], acc[g*4+1], acc[g*4+2], acc[g*4+3]);
}

// ---------------------------------------------------------------------------
// Attention layer (queries): Q' = z * (h@Wq + bq)^2 ; x = h + Q'@C + bo.
// ---------------------------------------------------------------------------
#define ATTN_SMEM (33152 * 4)
__global__ void __launch_bounds__(256) attn_kernel(
    const float* __restrict__ Wq_l, const float* __restrict__ bq_l,
    const float* __restrict__ bo_l, int l)
{
    extern __shared__ float sm[];
    float* sH  = sm;            // 64 x 128
    float* sQ  = sH + 8192;     // 64 x 128
    float* sW  = sQ + 8192;     // 128 x 128 (Wq-concat, then C)
    float* sKs = sW + 16384;    // 128
    float* sBq = sKs + 128;
    float* sBo = sBq + 128;
    int t = threadIdx.x;
    size_t pt0 = (size_t)blockIdx.x * 64;
    {
        const float4* src = (const float4*)(g_h + pt0 * 128);
        for (int i = t; i < 2048; i += 256) ((float4*)sH)[i] = src[i];
    }
    for (int i = t; i < 4096; i += 256) {
        int h = i >> 10, r = i & 1023, d = r >> 3, g = r & 7;
        ((float4*)sW)[d * 32 + h * 8 + g] = ((const float4*)Wq_l)[i];
    }
    if (t < 128) { sKs[t] = g_ksum[l * 128 + t]; sBq[t] = bq_l[t]; sBo[t] = bo_l[t]; }
    __syncthreads();
    int wid = t >> 5, lane = t & 31;
    int m0 = wid * 8, jc = lane * 4;
    float acc[8][4];
    #pragma unroll
    for (int i = 0; i < 8; ++i) { acc[i][0]=acc[i][1]=acc[i][2]=acc[i][3]=0.f; }
    #pragma unroll 2
    for (int d = 0; d < 128; ++d) {
        float4 b4 = *(const float4*)(sW + d * 128 + jc);
        #pragma unroll
        for (int i = 0; i < 8; ++i) {
            float a = sH[(m0 + i) * 128 + d];
            acc[i][0] = fmaf(a, b4.x, acc[i][0]);
            acc[i][1] = fmaf(a, b4.y, acc[i][1]);
            acc[i][2] = fmaf(a, b4.z, acc[i][2]);
            acc[i][3] = fmaf(a, b4.w, acc[i][3]);
        }
    }
    {
        float k0 = sKs[jc], k1 = sKs[jc+1], k2 = sKs[jc+2], k3 = sKs[jc+3];
        float b0 = sBq[jc], b1 = sBq[jc+1], b2 = sBq[jc+2], b3 = sBq[jc+3];
        #pragma unroll
        for (int i = 0; i < 8; ++i) {
            float q0 = acc[i][0] + b0; q0 *= q0;
            float q1 = acc[i][1] + b1; q1 *= q1;
            float q2 = acc[i][2] + b2; q2 *= q2;
            float q3 = acc[i][3] + b3; q3 *= q3;
            float p = q0*k0 + q1*k1 + q2*k2 + q3*k3;
            p += __shfl_xor_sync(0xffffffffu, p, 1);
            p += __shfl_xor_sync(0xffffffffu, p, 2);
            p += __shfl_xor_sync(0xffffffffu, p, 4);
            float z = 1.0f / (p + 1e-6f);
            *(float4*)(sQ + (m0 + i) * 128 + jc) = make_float4(q0*z, q1*z, q2*z, q3*z);
        }
    }
    __syncthreads();
    {
        const float4* src = (const float4*)(g_C + (size_t)l * 16384);
        for (int i = t; i < 4096; i += 256) ((float4*)sW)[i] = src[i];
    }
    __syncthreads();
    float acc2[8][4];
    #pragma unroll
    for (int i = 0; i < 8; ++i) { acc2[i][0]=acc2[i][1]=acc2[i][2]=acc2[i][3]=0.f; }
    #pragma unroll 2
    for (int j = 0; j < 128; ++j) {
        float4 b4 = *(const float4*)(sW + j * 128 + jc);
        #pragma unroll
        for (int i = 0; i < 8; ++i) {
            float a = sQ[(m0 + i) * 128 + j];
            acc2[i][0] = fmaf(a, b4.x, acc2[i][0]);
            acc2[i][1] = fmaf(a, b4.y, acc2[i][1]);
            acc2[i][2] = fmaf(a, b4.z, acc2[i][2]);
            acc2[i][3] = fmaf(a, b4.w, acc2[i][3]);
        }
    }
    float o0 = sBo[jc], o1 = sBo[jc+1], o2 = sBo[jc+2], o3 = sBo[jc+3];
    #pragma unroll
    for (int i = 0; i < 8; ++i) {
        float4 hv = *(const float4*)(sH + (m0 + i) * 128 + jc);
        float4 o = make_float4(hv.x + acc2[i][0] + o0, hv.y + acc2[i][1] + o1,
                               hv.z + acc2[i][2] + o2, hv.w + acc2[i][3] + o3);
        *(float4*)(g_x + (pt0 + m0 + i) * 128 + jc) = o;
    }
}

// ---------------------------------------------------------------------------
// FFN layer: h = x + gelu(x@W1 + b1) @ W2 + b2
// ---------------------------------------------------------------------------
#define FFN_SMEM (33024 * 4)
__global__ void __launch_bounds__(256) ffn_kernel(
    const float* __restrict__ W1_l, const float* __restrict__ b1_l,
    const float* __restrict__ W2_l, const float* __restrict__ b2_l)
{
    extern __shared__ float sm[];
    float* sX  = sm;
    float* sT  = sX + 8192;
    float* sW  = sT + 8192;
    float* sB1 = sW + 16384;
    float* sB2 = sB1 + 128;
    int t = threadIdx.x;
    size_t pt0 = (size_t)blockIdx.x * 64;
    {
        const float4* src = (const float4*)(g_x + pt0 * 128);
        for (int i = t; i < 2048; i += 256) ((float4*)sX)[i] = src[i];
    }
    for (int i = t; i < 4096; i += 256) ((float4*)sW)[i] = ((const float4*)W1_l)[i];
    if (t < 128) { sB1[t] = b1_l[t]; sB2[t] = b2_l[t]; }
    __syncthreads();
    int wid = t >> 5, lane = t & 31;
    int m0 = wid * 8, jc = lane * 4;
    float acc[8][4];
    #pragma unroll
    for (int i = 0; i < 8; ++i) { acc[i][0]=acc[i][1]=acc[i][2]=acc[i][3]=0.f; }
    #pragma unroll 2
    for (int d = 0; d < 128; ++d) {
        float4 b4 = *(const float4*)(sW + d * 128 + jc);
        #pragma unroll
        for (int i = 0; i < 8; ++i) {
            float a = sX[(m0 + i) * 128 + d];
            acc[i][0] = fmaf(a, b4.x, acc[i][0]);
            acc[i][1] = fmaf(a, b4.y, acc[i][1]);
            acc[i][2] = fmaf(a, b4.z, acc[i][2]);
            acc[i][3] = fmaf(a, b4.w, acc[i][3]);
        }
    }
    {
        float b0 = sB1[jc], b1 = sB1[jc+1], b2 = sB1[jc+2], b3 = sB1[jc+3];
        #pragma unroll
        for (int i = 0; i < 8; ++i) {
            float4 o = make_float4(geluf(acc[i][0] + b0), geluf(acc[i][1] + b1),
                                   geluf(acc[i][2] + b2), geluf(acc[i][3] + b3));
            *(float4*)(sT + (m0 + i) * 128 + jc) = o;
        }
    }
    __syncthreads();
    for (int i = t; i < 4096; i += 256) ((float4*)sW)[i] = ((const float4*)W2_l)[i];
    __syncthreads();
    float acc2[8][4];
    #pragma unroll
    for (int i = 0; i < 8; ++i) { acc2[i][0]=acc2[i][1]=acc2[i][2]=acc2[i][3]=0.f; }
    #pragma unroll 2
    for (int d = 0; d < 128; ++d) {
        float4 b4 = *(const float4*)(sW + d * 128 + jc);
        #pragma unroll
        for (int i = 0; i < 8; ++i) {
            float a = sT[(m0 + i) * 128 + d];
            acc2[i][0] = fmaf(a, b4.x, acc2[i][0]);
            acc2[i][1] = fmaf(a, b4.y, acc2[i][1]);
            acc2[i][2] = fmaf(a, b4.z, acc2[i][2]);
            acc2[i][3] = fmaf(a, b4.w, acc2[i][3]);
        }
    }
    float c0 = sB2[jc], c1 = sB2[jc+1], c2 = sB2[jc+2], c3 = sB2[jc+3];
    #pragma unroll
    for (int i = 0; i < 8; ++i) {
        float4 xv = *(const float4*)(sX + (m0 + i) * 128 + jc);
        float4 o = make_float4(xv.x + acc2[i][0] + c0, xv.y + acc2[i][1] + c1,
                               xv.z + acc2[i][2] + c2, xv.w + acc2[i][3] + c3);
        *(float4*)(g_h + (pt0 + m0 + i) * 128 + jc) = o;
    }
}

// ---------------------------------------------------------------------------
// Final projector: out = gelu(h @ pw1 + pb1) @ pw2 + pb2
// ---------------------------------------------------------------------------
#define FIN_SMEM (20812 * 4)
__global__ void __launch_bounds__(256) final_kernel(
    const float* __restrict__ pw1, const float* __restrict__ pb1,
    const float* __restrict__ pw2, const float* __restrict__ pb2,
    float* __restrict__ out)
{
    extern __shared__ float sm[];
    float* sH   = sm;
    float* sW1  = sH + 8192;     // 128 x 64
    float* sT   = sW1 + 8192;    // 64 x 65
    float* spw2 = sT + 4160;     // 192
    float* spb1 = spw2 + 192;    // 64
    float* spb2 = spb1 + 64;     // 3
    int t = threadIdx.x;
    size_t pt0 = (size_t)blockIdx.x * 64;
    {
        const float4* src = (const float4*)(g_h + pt0 * 128);
        for (int i = t; i < 2048; i += 256) ((float4*)sH)[i] = src[i];
    }
    for (int i = t; i < 2048; i += 256) ((float4*)sW1)[i] = ((const float4*)pw1)[i];
    if (t < 192) spw2[t] = pw2[t];
    if (t < 64)  spb1[t] = pb1[t];
    if (t < 3)   spb2[t] = pb2[t];
    __syncthreads();
    int wid = t >> 5, lane = t & 31;
    int m0 = wid * 8, jc = lane * 2;
    float acc[8][2];
    #pragma unroll
    for (int i = 0; i < 8; ++i) { acc[i][0] = acc[i][1] = 0.f; }
    #pragma unroll 2
    for (int k = 0; k < 128; ++k) {
        float2 b2v = *(const float2*)(sW1 + k * 64 + jc);
        #pragma unroll
        for (int i = 0; i < 8; ++i) {
            float a = sH[(m0 + i) * 128 + k];
            acc[i][0] = fmaf(a, b2v.x, acc[i][0]);
            acc[i][1] = fmaf(a, b2v.y, acc[i][1]);
        }
    }
    float c0 = spb1[jc], c1 = spb1[jc + 1];
    #pragma unroll
    for (int i = 0; i < 8; ++i) {
        sT[(m0 + i) * 65 + jc]     = geluf(acc[i][0] + c0);
        sT[(m0 + i) * 65 + jc + 1] = geluf(acc[i][1] + c1);
    }
    __syncthreads();
    if (t < 192) {
        int n = t / 3, c = t - n * 3;
        float s = spb2[c];
        #pragma unroll 4
        for (int k = 0; k < 64; ++k) s = fmaf(sT[n * 65 + k], spw2[k * 3 + c], s);
        out[(pt0 + n) * 3 + c] = s;
    }
}

// ---------------------------------------------------------------------------
extern "C" void kernel_launch(void* const* d_in, const int* in_sizes, int n_in,
                              void* d_out, int out_size)
{
    const float* qp    = (const float*)d_in[0];
    const float* bp    = (const float*)d_in[1];
    const float* pe_w  = (const float*)d_in[2];
    const float* pe_b  = (const float*)d_in[3];
    const float* bpe_w = (const float*)d_in[4];
    const float* bpe_b = (const float*)d_in[5];
    const float* Wq    = (const float*)d_in[6];
    const float* bq    = (const float*)d_in[7];
    const float* Wk    = (const float*)d_in[8];
    const float* bk    = (const float*)d_in[9];
    const float* Wv    = (const float*)d_in[10];
    const float* bv    = (const float*)d_in[11];
    const float* Wo    = (const float*)d_in[12];
    const float* bo    = (const float*)d_in[13];
    const float* W1    = (const float*)d_in[14];
    const float* b1    = (const float*)d_in[15];
    const float* W2    = (const float*)d_in[16];
    const float* b2    = (const float*)d_in[17];
    const float* pw1   = (const float*)d_in[18];
    const float* pb1   = (const float*)d_in[19];
    const float* pw2   = (const float*)d_in[20];
    const float* pb2   = (const float*)d_in[21];
    float* out = (float*)d_out;

    cudaFuncSetAttribute(bkv_kernel,   cudaFuncAttributeMaxDynamicSharedMemorySize, BKV_SMEM);
    cudaFuncSetAttribute(attn_kernel,  cudaFuncAttributeMaxDynamicSharedMemorySize, ATTN_SMEM);
    cudaFuncSetAttribute(ffn_kernel,   cudaFuncAttributeMaxDynamicSharedMemorySize, FFN_SMEM);
    cudaFuncSetAttribute(final_kernel, cudaFuncAttributeMaxDynamicSharedMemorySize, FIN_SMEM);

    encode_kernel<<<64,   256>>>(bp, bpe_w, bpe_b, 1);
    encode_kernel<<<4096, 256>>>(qp, pe_w,  pe_b,  0);
    bkv_kernel<<<dim3(32, 12), 256, BKV_SMEM>>>(Wk, bk, Wv, bv);
    kvreduce_kernel<<<12, 256>>>();
    cfold_kernel<<<3, 256>>>(Wo);
    for (int l = 0; l < 3; ++l) {
        attn_kernel<<<4096, 256, ATTN_SMEM>>>(Wq + (size_t)l * 16384, bq + l * 128, bo + l * 128, l);
        ffn_kernel <<<4096, 256, FFN_SMEM>>>(W1 + (size_t)l * 16384, b1 + l * 128,
                                             W2 + (size_t)l * 16384, b2 + l * 128);
    }
    final_kernel<<<4096, 256, FIN_SMEM>>>(pw1, pb1, pw2, pb2, out);
}

// round 8
// speedup vs baseline: 1.0036x; 1.0017x over previous
#include <cuda_runtime.h>

#define NQ 262144
#define MB 4096
#define PI_F 3.14159265358979323846f

// ------------------------- device scratch (no allocs) -----------------------
__device__ __align__(16) float g_h[(size_t)NQ * 128];
__device__ __align__(16) float g_x[(size_t)NQ * 128];
__device__ __align__(16) float g_benc[MB * 128];
__device__ __align__(16) float g_kvp[12 * 32 * 1024];  // per (l,h,tile) partial kv
__device__ __align__(16) float g_ksp[12 * 32 * 32];    // per (l,h,tile) partial ksum
__device__ __align__(16) float g_kv[12 * 1024];
__device__ __align__(16) float g_ksum[384];            // [l*128 + h*32 + e]
__device__ __align__(16) float g_C[3 * 16384];         // folded kv @ Wo, [l][j][o]

__device__ __forceinline__ float geluf(float u) {
    return 0.5f * u * (1.0f + erff(u * 0.70710678118654752f));
}

// ---------------------------------------------------------------------------
// Positional encoder: dst[p][:] = sin(mfe(pts[p]) @ W + b). 64 pts / CTA.
// ---------------------------------------------------------------------------
__global__ void __launch_bounds__(256) encode_kernel(
    const float* __restrict__ pts, const float* __restrict__ w,
    const float* __restrict__ b, int which)
{
    __shared__ float sW[3840];
    __shared__ float sB[128];
    __shared__ float sF[64 * 32];
    int t = threadIdx.x;
    for (int i = t; i < 960; i += 256) ((float4*)sW)[i] = ((const float4*)w)[i];
    if (t < 128) sB[t] = b[t];
    size_t pt0 = (size_t)blockIdx.x * 64;
    if (t < 64) {
        float2 xy = ((const float2*)pts)[pt0 + t];
        float* F = sF + t * 32;
        #pragma unroll
        for (int c = 0; c < 2; ++c) {
            float v = c ? xy.y : xy.x;
            float a15 = v - 1.5f, a45 = v - 4.5f, pv = PI_F * v;
            F[0 + c] = v;           F[2 + c] = v * v;
            F[4 + c] = a15 * a15;   F[6 + c] = a45 * a45;
            F[8 + c]  = 1.f / (1.f + expf(-v));
            F[10 + c] = 1.f / (1.f + expf(-a15));
            F[12 + c] = 1.f / (1.f + expf(-a45));
            F[14 + c] = a15;        F[16 + c] = a45;
            F[18 + c] = sinf(pv);          F[20 + c] = cosf(pv);
            F[22 + c] = sinf(pv * 0.25f);  F[24 + c] = cosf(pv * 0.25f);
            F[26 + c] = sinf(pv * 0.5f);   F[28 + c] = cosf(pv * 0.5f);
        }
    }
    __syncthreads();
    int wid = t >> 5, lane = t & 31;
    int m0 = wid * 8, jc = lane * 4;
    float acc[8][4];
    #pragma unroll
    for (int i = 0; i < 8; ++i) { acc[i][0]=acc[i][1]=acc[i][2]=acc[i][3]=0.f; }
    #pragma unroll 2
    for (int k = 0; k < 30; ++k) {
        float4 b4 = *(const float4*)(sW + k * 128 + jc);
        #pragma unroll
        for (int i = 0; i < 8; ++i) {
            float a = sF[(m0 + i) * 32 + k];
            acc[i][0] = fmaf(a, b4.x, acc[i][0]);
            acc[i][1] = fmaf(a, b4.y, acc[i][1]);
            acc[i][2] = fmaf(a, b4.z, acc[i][2]);
            acc[i][3] = fmaf(a, b4.w, acc[i][3]);
        }
    }
    float b0 = sB[jc], b1 = sB[jc+1], b2 = sB[jc+2], b3 = sB[jc+3];
    float* dst = which ? g_benc : g_h;
    #pragma unroll
    for (int i = 0; i < 8; ++i) {
        float4 o;
        o.x = sinf(acc[i][0] + b0); o.y = sinf(acc[i][1] + b1);
        o.z = sinf(acc[i][2] + b2); o.w = sinf(acc[i][3] + b3);
        *(float4*)(dst + (pt0 + m0 + i) * 128 + jc) = o;
    }
}

// ---------------------------------------------------------------------------
// Boundary k/v: per (tile of 128 rows, lh = l*4+h) partial kv and ksum.
// kh = (e@Wk + bk)^2 ; vh = e@Wv + bv ; kv += kh^T vh ; ksum += sum kh.
// ---------------------------------------------------------------------------
#define BKV_SMEM (34372 * 4)
__global__ void __launch_bounds__(256) bkv_kernel(
    const float* __restrict__ Wk_g, const float* __restrict__ bk_g,
    const float* __restrict__ Wv_g, const float* __restrict__ bv_g)
{
    extern __shared__ float sm[];
    float* sE  = sm;              // 128 x 132
    float* sWk = sE + 16896;      // 4096
    float* sWv = sWk + 4100;      // 4096 (pad 4 to split banks)
    float* sKh = sWv + 4096;      // 128 x 36
    float* sVh = sKh + 4608;      // 128 x 36
    float* sbk = sVh + 4608;      // 32
    float* sbv = sbk + 32;        // 32
    int t = threadIdx.x;
    int tile = blockIdx.x, lh = blockIdx.y;
    {
        const float4* src = (const float4*)(g_benc + (size_t)tile * 128 * 128);
        for (int i = t; i < 4096; i += 256) {
            int r = i >> 5, c = i & 31;
            *(float4*)(sE + r * 132 + c * 4) = src[i];
        }
    }
    for (int i = t; i < 1024; i += 256) {
        ((float4*)sWk)[i] = ((const float4*)(Wk_g + (size_t)lh * 4096))[i];
        ((float4*)sWv)[i] = ((const float4*)(Wv_g + (size_t)lh * 4096))[i];
    }
    if (t < 32) { sbk[t] = bk_g[lh * 32 + t]; sbv[t] = bv_g[lh * 32 + t]; }
    __syncthreads();
    {
        int m = t >> 1, kind = t & 1;
        const float* W  = kind ? sWv : sWk;
        const float* sb = kind ? sbv : sbk;
        float4 acc[8];
        #pragma unroll
        for (int g = 0; g < 8; ++g) acc[g] = make_float4(0.f, 0.f, 0.f, 0.f);
        for (int d = 0; d < 128; ++d) {
            float v = sE[m * 132 + d];
            #pragma unroll
            for (int g = 0; g < 8; ++g) {
                float4 w4 = *(const float4*)(W + d * 32 + g * 4);
                acc[g].x = fmaf(v, w4.x, acc[g].x);
                acc[g].y = fmaf(v, w4.y, acc[g].y);
                acc[g].z = fmaf(v, w4.z, acc[g].z);
                acc[g].w = fmaf(v, w4.w, acc[g].w);
            }
        }
        float* dst = (kind ? sVh : sKh) + m * 36;
        #pragma unroll
        for (int g = 0; g < 8; ++g) {
            float4 a = acc[g];
            a.x += sb[g*4+0]; a.y += sb[g*4+1]; a.z += sb[g*4+2]; a.w += sb[g*4+3];
            if (!kind) { a.x *= a.x; a.y *= a.y; a.z *= a.z; a.w *= a.w; }
            *(float4*)(dst + g * 4) = a;
        }
    }
    __syncthreads();
    {
        int e = t >> 3, c4 = (t & 7) * 4;
        float4 acc = make_float4(0.f, 0.f, 0.f, 0.f);
        for (int m = 0; m < 128; ++m) {
            float kh = sKh[m * 36 + e];
            float4 v4 = *(const float4*)(sVh + m * 36 + c4);
            acc.x = fmaf(kh, v4.x, acc.x); acc.y = fmaf(kh, v4.y, acc.y);
            acc.z = fmaf(kh, v4.z, acc.z); acc.w = fmaf(kh, v4.w, acc.w);
        }
        *(float4*)(g_kvp + ((size_t)lh * 32 + tile) * 1024 + e * 32 + c4) = acc;
        if (t < 32) {
            float s = 0.f;
            for (int m = 0; m < 128; ++m) s += sKh[m * 36 + t];
            g_ksp[((size_t)lh * 32 + tile) * 32 + t] = s;
        }
    }
}

__global__ void __launch_bounds__(256) kvreduce_kernel()
{
    int lh = blockIdx.x, t = threadIdx.x;
    for (int idx = t; idx < 1024; idx += 256) {
        float s = 0.f;
        for (int tile = 0; tile < 32; ++tile)
            s += g_kvp[((size_t)lh * 32 + tile) * 1024 + idx];
        g_kv[lh * 1024 + idx] = s;
    }
    if (t < 32) {
        float s = 0.f;
        for (int tile = 0; tile < 32; ++tile)
            s += g_ksp[((size_t)lh * 32 + tile) * 32 + t];
        g_ksum[lh * 32 + t] = s;
    }
}

// C[l][j=h*32+e][o] = sum_ep kv[l][h][e][ep] * Wo[l][h*32+ep][o]
__global__ void __launch_bounds__(256) cfold_kernel(const float* __restrict__ Wo_g)
{
    int l = blockIdx.x, t = threadIdx.x;
    int j = t >> 1, oc = (t & 1) * 64;
    int h = j >> 5, e = j & 31;
    float acc[64];
    #pragma unroll
    for (int o = 0; o < 64; ++o) acc[o] = 0.f;
    for (int ep = 0; ep < 32; ++ep) {
        float kv = g_kv[(l * 4 + h) * 1024 + e * 32 + ep];
        const float4* wr = (const float4*)(Wo_g + ((size_t)(l * 128 + h * 32 + ep)) * 128 + oc);
        #pragma unroll
        for (int g = 0; g < 16; ++g) {
            float4 w4 = __ldg(wr + g);
            acc[g*4+0] = fmaf(kv, w4.x, acc[g*4+0]);
            acc[g*4+1] = fmaf(kv, w4.y, acc[g*4+1]);
            acc[g*4+2] = fmaf(kv, w4.z, acc[g*4+2]);
            acc[g*4+3] = fmaf(kv, w4.w, acc[g*4+3]);
        }
    }
    float4* dst = (float4*)(g_C + (size_t)l * 16384 + j * 128 + oc);
    #pragma unroll
    for (int g = 0; g < 16; ++g)
        dst[g] = make_float4(acc[g*4], acc[g*4+1], acc[g*4+2], acc[g*4+3]);
}

// ---------------------------------------------------------------------------
// Attention layer (queries): Q' = z * (h@Wq + bq)^2 ; x = h + Q'@C + bo.
// ---------------------------------------------------------------------------
#define ATTN_SMEM (33152 * 4)
__global__ void __launch_bounds__(256) attn_kernel(
    const float* __restrict__ Wq_l, const float* __restrict__ bq_l,
    const float* __restrict__ bo_l, int l)
{
    extern __shared__ float sm[];
    float* sH  = sm;            // 64 x 128
    float* sQ  = sH + 8192;     // 64 x 128
    float* sW  = sQ + 8192;     // 128 x 128 (Wq-concat, then C)
    float* sKs = sW + 16384;    // 128
    float* sBq = sKs + 128;
    float* sBo = sBq + 128;
    int t = threadIdx.x;
    size_t pt0 = (size_t)blockIdx.x * 64;
    {
        const float4* src = (const float4*)(g_h + pt0 * 128);
        for (int i = t; i < 2048; i += 256) ((float4*)sH)[i] = src[i];
    }
    for (int i = t; i < 4096; i += 256) {
        int h = i >> 10, r = i & 1023, d = r >> 3, g = r & 7;
        ((float4*)sW)[d * 32 + h * 8 + g] = ((const float4*)Wq_l)[i];
    }
    if (t < 128) { sKs[t] = g_ksum[l * 128 + t]; sBq[t] = bq_l[t]; sBo[t] = bo_l[t]; }
    __syncthreads();
    int wid = t >> 5, lane = t & 31;
    int m0 = wid * 8, jc = lane * 4;
    float acc[8][4];
    #pragma unroll
    for (int i = 0; i < 8; ++i) { acc[i][0]=acc[i][1]=acc[i][2]=acc[i][3]=0.f; }
    #pragma unroll 2
    for (int d = 0; d < 128; ++d) {
        float4 b4 = *(const float4*)(sW + d * 128 + jc);
        #pragma unroll
        for (int i = 0; i < 8; ++i) {
            float a = sH[(m0 + i) * 128 + d];
            acc[i][0] = fmaf(a, b4.x, acc[i][0]);
            acc[i][1] = fmaf(a, b4.y, acc[i][1]);
            acc[i][2] = fmaf(a, b4.z, acc[i][2]);
            acc[i][3] = fmaf(a, b4.w, acc[i][3]);
        }
    }
    {
        float k0 = sKs[jc], k1 = sKs[jc+1], k2 = sKs[jc+2], k3 = sKs[jc+3];
        float b0 = sBq[jc], b1 = sBq[jc+1], b2 = sBq[jc+2], b3 = sBq[jc+3];
        #pragma unroll
        for (int i = 0; i < 8; ++i) {
            float q0 = acc[i][0] + b0; q0 *= q0;
            float q1 = acc[i][1] + b1; q1 *= q1;
            float q2 = acc[i][2] + b2; q2 *= q2;
            float q3 = acc[i][3] + b3; q3 *= q3;
            float p = q0*k0 + q1*k1 + q2*k2 + q3*k3;
            p += __shfl_xor_sync(0xffffffffu, p, 1);
            p += __shfl_xor_sync(0xffffffffu, p, 2);
            p += __shfl_xor_sync(0xffffffffu, p, 4);
            float z = 1.0f / (p + 1e-6f);
            *(float4*)(sQ + (m0 + i) * 128 + jc) = make_float4(q0*z, q1*z, q2*z, q3*z);
        }
    }
    __syncthreads();
    {
        const float4* src = (const float4*)(g_C + (size_t)l * 16384);
        for (int i = t; i < 4096; i += 256) ((float4*)sW)[i] = src[i];
    }
    __syncthreads();
    float acc2[8][4];
    #pragma unroll
    for (int i = 0; i < 8; ++i) { acc2[i][0]=acc2[i][1]=acc2[i][2]=acc2[i][3]=0.f; }
    #pragma unroll 2
    for (int j = 0; j < 128; ++j) {
        float4 b4 = *(const float4*)(sW + j * 128 + jc);
        #pragma unroll
        for (int i = 0; i < 8; ++i) {
            float a = sQ[(m0 + i) * 128 + j];
            acc2[i][0] = fmaf(a, b4.x, acc2[i][0]);
            acc2[i][1] = fmaf(a, b4.y, acc2[i][1]);
            acc2[i][2] = fmaf(a, b4.z, acc2[i][2]);
            acc2[i][3] = fmaf(a, b4.w, acc2[i][3]);
        }
    }
    float o0 = sBo[jc], o1 = sBo[jc+1], o2 = sBo[jc+2], o3 = sBo[jc+3];
    #pragma unroll
    for (int i = 0; i < 8; ++i) {
        float4 hv = *(const float4*)(sH + (m0 + i) * 128 + jc);
        float4 o = make_float4(hv.x + acc2[i][0] + o0, hv.y + acc2[i][1] + o1,
                               hv.z + acc2[i][2] + o2, hv.w + acc2[i][3] + o3);
        *(float4*)(g_x + (pt0 + m0 + i) * 128 + jc) = o;
    }
}

// ---------------------------------------------------------------------------
// FFN layer: h = x + gelu(x@W1 + b1) @ W2 + b2
// ---------------------------------------------------------------------------
#define FFN_SMEM (33024 * 4)
__global__ void __launch_bounds__(256) ffn_kernel(
    const float* __restrict__ W1_l, const float* __restrict__ b1_l,
    const float* __restrict__ W2_l, const float* __restrict__ b2_l)
{
    extern __shared__ float sm[];
    float* sX  = sm;
    float* sT  = sX + 8192;
    float* sW  = sT + 8192;
    float* sB1 = sW + 16384;
    float* sB2 = sB1 + 128;
    int t = threadIdx.x;
    size_t pt0 = (size_t)blockIdx.x * 64;
    {
        const float4* src = (const float4*)(g_x + pt0 * 128);
        for (int i = t; i < 2048; i += 256) ((float4*)sX)[i] = src[i];
    }
    for (int i = t; i < 4096; i += 256) ((float4*)sW)[i] = ((const float4*)W1_l)[i];
    if (t < 128) { sB1[t] = b1_l[t]; sB2[t] = b2_l[t]; }
    __syncthreads();
    int wid = t >> 5, lane = t & 31;
    int m0 = wid * 8, jc = lane * 4;
    float acc[8][4];
    #pragma unroll
    for (int i = 0; i < 8; ++i) { acc[i][0]=acc[i][1]=acc[i][2]=acc[i][3]=0.f; }
    #pragma unroll 2
    for (int d = 0; d < 128; ++d) {
        float4 b4 = *(const float4*)(sW + d * 128 + jc);
        #pragma unroll
        for (int i = 0; i < 8; ++i) {
            float a = sX[(m0 + i) * 128 + d];
            acc[i][0] = fmaf(a, b4.x, acc[i][0]);
            acc[i][1] = fmaf(a, b4.y, acc[i][1]);
            acc[i][2] = fmaf(a, b4.z, acc[i][2]);
            acc[i][3] = fmaf(a, b4.w, acc[i][3]);
        }
    }
    {
        float b0 = sB1[jc], b1 = sB1[jc+1], b2 = sB1[jc+2], b3 = sB1[jc+3];
        #pragma unroll
        for (int i = 0; i < 8; ++i) {
            float4 o = make_float4(geluf(acc[i][0] + b0), geluf(acc[i][1] + b1),
                                   geluf(acc[i][2] + b2), geluf(acc[i][3] + b3));
            *(float4*)(sT + (m0 + i) * 128 + jc) = o;
        }
    }
    __syncthreads();
    for (int i = t; i < 4096; i += 256) ((float4*)sW)[i] = ((const float4*)W2_l)[i];
    __syncthreads();
    float acc2[8][4];
    #pragma unroll
    for (int i = 0; i < 8; ++i) { acc2[i][0]=acc2[i][1]=acc2[i][2]=acc2[i][3]=0.f; }
    #pragma unroll 2
    for (int d = 0; d < 128; ++d) {
        float4 b4 = *(const float4*)(sW + d * 128 + jc);
        #pragma unroll
        for (int i = 0; i < 8; ++i) {
            float a = sT[(m0 + i) * 128 + d];
            acc2[i][0] = fmaf(a, b4.x, acc2[i][0]);
            acc2[i][1] = fmaf(a, b4.y, acc2[i][1]);
            acc2[i][2] = fmaf(a, b4.z, acc2[i][2]);
            acc2[i][3] = fmaf(a, b4.w, acc2[i][3]);
        }
    }
    float c0 = sB2[jc], c1 = sB2[jc+1], c2 = sB2[jc+2], c3 = sB2[jc+3];
    #pragma unroll
    for (int i = 0; i < 8; ++i) {
        float4 xv = *(const float4*)(sX + (m0 + i) * 128 + jc);
        float4 o = make_float4(xv.x + acc2[i][0] + c0, xv.y + acc2[i][1] + c1,
                               xv.z + acc2[i][2] + c2, xv.w + acc2[i][3] + c3);
        *(float4*)(g_h + (pt0 + m0 + i) * 128 + jc) = o;
    }
}

// ---------------------------------------------------------------------------
// Final projector: out = gelu(h @ pw1 + pb1) @ pw2 + pb2
// ---------------------------------------------------------------------------
#define FIN_SMEM (20812 * 4)
__global__ void __launch_bounds__(256) final_kernel(
    const float* __restrict__ pw1, const float* __restrict__ pb1,
    const float* __restrict__ pw2, const float* __restrict__ pb2,
    float* __restrict__ out)
{
    extern __shared__ float sm[];
    float* sH   = sm;
    float* sW1  = sH + 8192;     // 128 x 64
    float* sT   = sW1 + 8192;    // 64 x 65
    float* spw2 = sT + 4160;     // 192
    float* spb1 = spw2 + 192;    // 64
    float* spb2 = spb1 + 64;     // 3
    int t = threadIdx.x;
    size_t pt0 = (size_t)blockIdx.x * 64;
    {
        const float4* src = (const float4*)(g_h + pt0 * 128);
        for (int i = t; i < 2048; i += 256) ((float4*)sH)[i] = src[i];
    }
    for (int i = t; i < 2048; i += 256) ((float4*)sW1)[i] = ((const float4*)pw1)[i];
    if (t < 192) spw2[t] = pw2[t];
    if (t < 64)  spb1[t] = pb1[t];
    if (t < 3)   spb2[t] = pb2[t];
    __syncthreads();
    int wid = t >> 5, lane = t & 31;
    int m0 = wid * 8, jc = lane * 2;
    float acc[8][2];
    #pragma unroll
    for (int i = 0; i < 8; ++i) { acc[i][0] = acc[i][1] = 0.f; }
    #pragma unroll 2
    for (int k = 0; k < 128; ++k) {
        float2 b2v = *(const float2*)(sW1 + k * 64 + jc);
        #pragma unroll
        for (int i = 0; i < 8; ++i) {
            float a = sH[(m0 + i) * 128 + k];
            acc[i][0] = fmaf(a, b2v.x, acc[i][0]);
            acc[i][1] = fmaf(a, b2v.y, acc[i][1]);
        }
    }
    float c0 = spb1[jc], c1 = spb1[jc + 1];
    #pragma unroll
    for (int i = 0; i < 8; ++i) {
        sT[(m0 + i) * 65 + jc]     = geluf(acc[i][0] + c0);
        sT[(m0 + i) * 65 + jc + 1] = geluf(acc[i][1] + c1);
    }
    __syncthreads();
    if (t < 192) {
        int n = t / 3, c = t - n * 3;
        float s = spb2[c];
        #pragma unroll 4
        for (int k = 0; k < 64; ++k) s = fmaf(sT[n * 65 + k], spw2[k * 3 + c], s);
        out[(pt0 + n) * 3 + c] = s;
    }
}

// ---------------------------------------------------------------------------
extern "C" void kernel_launch(void* const* d_in, const int* in_sizes, int n_in,
                              void* d_out, int out_size)
{
    const float* qp    = (const float*)d_in[0];
    const float* bp    = (const float*)d_in[1];
    const float* pe_w  = (const float*)d_in[2];
    const float* pe_b  = (const float*)d_in[3];
    const float* bpe_w = (const float*)d_in[4];
    const float* bpe_b = (const float*)d_in[5];
    const float* Wq    = (const float*)d_in[6];
    const float* bq    = (const float*)d_in[7];
    const float* Wk    = (const float*)d_in[8];
    const float* bk    = (const float*)d_in[9];
    const float* Wv    = (const float*)d_in[10];
    const float* bv    = (const float*)d_in[11];
    const float* Wo    = (const float*)d_in[12];
    const float* bo    = (const float*)d_in[13];
    const float* W1    = (const float*)d_in[14];
    const float* b1    = (const float*)d_in[15];
    const float* W2    = (const float*)d_in[16];
    const float* b2    = (const float*)d_in[17];
    const float* pw1   = (const float*)d_in[18];
    const float* pb1   = (const float*)d_in[19];
    const float* pw2   = (const float*)d_in[20];
    const float* pb2   = (const float*)d_in[21];
    float* out = (float*)d_out;

    cudaFuncSetAttribute(bkv_kernel,   cudaFuncAttributeMaxDynamicSharedMemorySize, BKV_SMEM);
    cudaFuncSetAttribute(attn_kernel,  cudaFuncAttributeMaxDynamicSharedMemorySize, ATTN_SMEM);
    cudaFuncSetAttribute(ffn_kernel,   cudaFuncAttributeMaxDynamicSharedMemorySize, FFN_SMEM);
    cudaFuncSetAttribute(final_kernel, cudaFuncAttributeMaxDynamicSharedMemorySize, FIN_SMEM);

    encode_kernel<<<64,   256>>>(bp, bpe_w, bpe_b, 1);
    encode_kernel<<<4096, 256>>>(qp, pe_w,  pe_b,  0);
    bkv_kernel<<<dim3(32, 12), 256, BKV_SMEM>>>(Wk, bk, Wv, bv);
    kvreduce_kernel<<<12, 256>>>();
    cfold_kernel<<<3, 256>>>(Wo);
    for (int l = 0; l < 3; ++l) {
        attn_kernel<<<4096, 256, ATTN_SMEM>>>(Wq + (size_t)l * 16384, bq + l * 128, bo + l * 128, l);
        ffn_kernel <<<4096, 256, FFN_SMEM>>>(W1 + (size_t)l * 16384, b1 + l * 128,
                                             W2 + (size_t)l * 16384, b2 + l * 128);
    }
    final_kernel<<<4096, 256, FIN_SMEM>>>(pw1, pb1, pw2, pb2, out);
}

// round 12
// speedup vs baseline: 1.8992x; 1.8924x over previous
#include <cuda_runtime.h>
#include <cuda_bf16.h>
#include <cstdint>

#define NQ 262144
#define MB 4096
#define PI_F 3.14159265358979323846f

extern __shared__ char smem_raw[];

// ------------------------- device scratch (no allocs) -----------------------
__device__ __align__(16) float g_h[(size_t)NQ * 128];
__device__ __align__(16) float g_x[(size_t)NQ * 128];
__device__ __align__(16) float g_benc[MB * 128];
__device__ __align__(16) float g_kvp[12 * 32 * 1024];
__device__ __align__(16) float g_ksp[12 * 32 * 32];
__device__ __align__(16) float g_kv[12 * 1024];
__device__ __align__(16) float g_ksum[384];
__device__ __align__(16) float g_C[3 * 16384];
// pre-split weights: [inv=l*2+mode][tile=B1h,B1l,B2h,B2l][n*128+k] bf16
__device__ __align__(16) __nv_bfloat16 g_ws[6 * 4 * 16384];

__device__ __forceinline__ float geluf(float u) {
    return 0.5f * u * (1.0f + erff(u * 0.70710678118654752f));
}

// split fp32 pair into bf16-hi pair and bf16-lo pair (packed uint32 each)
__device__ __forceinline__ void cvt_pair(float a, float b, uint32_t& hi, uint32_t& lo) {
    __nv_bfloat16 ah = __float2bfloat16_rn(a), bh = __float2bfloat16_rn(b);
    float ar = a - __bfloat162float(ah), br = b - __bfloat162float(bh);
    __nv_bfloat16 al = __float2bfloat16_rn(ar), bl = __float2bfloat16_rn(br);
    hi = (uint32_t)__bfloat16_as_ushort(ah) | ((uint32_t)__bfloat16_as_ushort(bh) << 16);
    lo = (uint32_t)__bfloat16_as_ushort(al) | ((uint32_t)__bfloat16_as_ushort(bl) << 16);
}

__device__ __forceinline__ void mma16816(float* d, const uint32_t* a,
                                         uint32_t b0, uint32_t b1) {
    asm volatile(
        "mma.sync.aligned.m16n8k16.row.col.f32.bf16.bf16.f32 "
        "{%0,%1,%2,%3}, {%4,%5,%6,%7}, {%8,%9}, {%0,%1,%2,%3};"
        : "+f"(d[0]), "+f"(d[1]), "+f"(d[2]), "+f"(d[3])
        : "r"(a[0]), "r"(a[1]), "r"(a[2]), "r"(a[3]), "r"(b0), "r"(b1));
}

// ---------------------------------------------------------------------------
// Positional encoder (fp32): dst[p][:] = sin(mfe(pts[p]) @ W + b). 64 pts/CTA.
// ---------------------------------------------------------------------------
__global__ void __launch_bounds__(256) encode_kernel(
    const float* __restrict__ pts, const float* __restrict__ w,
    const float* __restrict__ b, int which)
{
    __shared__ float sW[3840];
    __shared__ float sB[128];
    __shared__ float sF[64 * 32];
    int t = threadIdx.x;
    for (int i = t; i < 960; i += 256) ((float4*)sW)[i] = ((const float4*)w)[i];
    if (t < 128) sB[t] = b[t];
    size_t pt0 = (size_t)blockIdx.x * 64;
    if (t < 64) {
        float2 xy = ((const float2*)pts)[pt0 + t];
        float* F = sF + t * 32;
        #pragma unroll
        for (int c = 0; c < 2; ++c) {
            float v = c ? xy.y : xy.x;
            float a15 = v - 1.5f, a45 = v - 4.5f, pv = PI_F * v;
            F[0 + c] = v;           F[2 + c] = v * v;
            F[4 + c] = a15 * a15;   F[6 + c] = a45 * a45;
            F[8 + c]  = 1.f / (1.f + expf(-v));
            F[10 + c] = 1.f / (1.f + expf(-a15));
            F[12 + c] = 1.f / (1.f + expf(-a45));
            F[14 + c] = a15;        F[16 + c] = a45;
            F[18 + c] = sinf(pv);          F[20 + c] = cosf(pv);
            F[22 + c] = sinf(pv * 0.25f);  F[24 + c] = cosf(pv * 0.25f);
            F[26 + c] = sinf(pv * 0.5f);   F[28 + c] = cosf(pv * 0.5f);
        }
    }
    __syncthreads();
    int wid = t >> 5, lane = t & 31;
    int m0 = wid * 8, jc = lane * 4;
    float acc[8][4];
    #pragma unroll
    for (int i = 0; i < 8; ++i) { acc[i][0]=acc[i][1]=acc[i][2]=acc[i][3]=0.f; }
    #pragma unroll 2
    for (int k = 0; k < 30; ++k) {
        float4 b4 = *(const float4*)(sW + k * 128 + jc);
        #pragma unroll
        for (int i = 0; i < 8; ++i) {
            float a = sF[(m0 + i) * 32 + k];
            acc[i][0] = fmaf(a, b4.x, acc[i][0]);
            acc[i][1] = fmaf(a, b4.y, acc[i][1]);
            acc[i][2] = fmaf(a, b4.z, acc[i][2]);
            acc[i][3] = fmaf(a, b4.w, acc[i][3]);
        }
    }
    float b0 = sB[jc], b1 = sB[jc+1], b2 = sB[jc+2], b3 = sB[jc+3];
    float* dst = which ? g_benc : g_h;
    #pragma unroll
    for (int i = 0; i < 8; ++i) {
        float4 o;
        o.x = sinf(acc[i][0] + b0); o.y = sinf(acc[i][1] + b1);
        o.z = sinf(acc[i][2] + b2); o.w = sinf(acc[i][3] + b3);
        *(float4*)(dst + (pt0 + m0 + i) * 128 + jc) = o;
    }
}

// ---------------------------------------------------------------------------
// Boundary kv (fp32, tiny): per (tile, lh) partial kv / ksum.
// ---------------------------------------------------------------------------
#define BKV_SMEM (34372 * 4)
__global__ void __launch_bounds__(256) bkv_kernel(
    const float* __restrict__ Wk_g, const float* __restrict__ bk_g,
    const float* __restrict__ Wv_g, const float* __restrict__ bv_g)
{
    float* sm = (float*)smem_raw;
    float* sE  = sm;
    float* sWk = sE + 16896;
    float* sWv = sWk + 4100;
    float* sKh = sWv + 4096;
    float* sVh = sKh + 4608;
    float* sbk = sVh + 4608;
    float* sbv = sbk + 32;
    int t = threadIdx.x;
    int tile = blockIdx.x, lh = blockIdx.y;
    {
        const float4* src = (const float4*)(g_benc + (size_t)tile * 128 * 128);
        for (int i = t; i < 4096; i += 256) {
            int r = i >> 5, c = i & 31;
            *(float4*)(sE + r * 132 + c * 4) = src[i];
        }
    }
    for (int i = t; i < 1024; i += 256) {
        ((float4*)sWk)[i] = ((const float4*)(Wk_g + (size_t)lh * 4096))[i];
        ((float4*)sWv)[i] = ((const float4*)(Wv_g + (size_t)lh * 4096))[i];
    }
    if (t < 32) { sbk[t] = bk_g[lh * 32 + t]; sbv[t] = bv_g[lh * 32 + t]; }
    __syncthreads();
    {
        int m = t >> 1, kind = t & 1;
        const float* W  = kind ? sWv : sWk;
        const float* sb = kind ? sbv : sbk;
        float4 acc[8];
        #pragma unroll
        for (int g = 0; g < 8; ++g) acc[g] = make_float4(0.f, 0.f, 0.f, 0.f);
        for (int d = 0; d < 128; ++d) {
            float v = sE[m * 132 + d];
            #pragma unroll
            for (int g = 0; g < 8; ++g) {
                float4 w4 = *(const float4*)(W + d * 32 + g * 4);
                acc[g].x = fmaf(v, w4.x, acc[g].x);
                acc[g].y = fmaf(v, w4.y, acc[g].y);
                acc[g].z = fmaf(v, w4.z, acc[g].z);
                acc[g].w = fmaf(v, w4.w, acc[g].w);
            }
        }
        float* dst = (kind ? sVh : sKh) + m * 36;
        #pragma unroll
        for (int g = 0; g < 8; ++g) {
            float4 a = acc[g];
            a.x += sb[g*4+0]; a.y += sb[g*4+1]; a.z += sb[g*4+2]; a.w += sb[g*4+3];
            if (!kind) { a.x *= a.x; a.y *= a.y; a.z *= a.z; a.w *= a.w; }
            *(float4*)(dst + g * 4) = a;
        }
    }
    __syncthreads();
    {
        int e = t >> 3, c4 = (t & 7) * 4;
        float4 acc = make_float4(0.f, 0.f, 0.f, 0.f);
        for (int m = 0; m < 128; ++m) {
            float kh = sKh[m * 36 + e];
            float4 v4 = *(const float4*)(sVh + m * 36 + c4);
            acc.x = fmaf(kh, v4.x, acc.x); acc.y = fmaf(kh, v4.y, acc.y);
            acc.z = fmaf(kh, v4.z, acc.z); acc.w = fmaf(kh, v4.w, acc.w);
        }
        *(float4*)(g_kvp + ((size_t)lh * 32 + tile) * 1024 + e * 32 + c4) = acc;
        if (t < 32) {
            float s = 0.f;
            for (int m = 0; m < 128; ++m) s += sKh[m * 36 + t];
            g_ksp[((size_t)lh * 32 + tile) * 32 + t] = s;
        }
    }
}

__global__ void __launch_bounds__(256) kvreduce_kernel()
{
    int lh = blockIdx.x, t = threadIdx.x;
    for (int idx = t; idx < 1024; idx += 256) {
        float s = 0.f;
        for (int tile = 0; tile < 32; ++tile)
            s += g_kvp[((size_t)lh * 32 + tile) * 1024 + idx];
        g_kv[lh * 1024 + idx] = s;
    }
    if (t < 32) {
        float s = 0.f;
        for (int tile = 0; tile < 32; ++tile)
            s += g_ksp[((size_t)lh * 32 + tile) * 32 + t];
        g_ksum[lh * 32 + t] = s;
    }
}

__global__ void __launch_bounds__(256) cfold_kernel(const float* __restrict__ Wo_g)
{
    int l = blockIdx.x, t = threadIdx.x;
    int j = t >> 1, oc = (t & 1) * 64;
    int h = j >> 5, e = j & 31;
    float acc[64];
    #pragma unroll
    for (int o = 0; o < 64; ++o) acc[o] = 0.f;
    for (int ep = 0; ep < 32; ++ep) {
        float kv = g_kv[(l * 4 + h) * 1024 + e * 32 + ep];
        const float4* wr = (const float4*)(Wo_g + ((size_t)(l * 128 + h * 32 + ep)) * 128 + oc);
        #pragma unroll
        for (int g = 0; g < 16; ++g) {
            float4 w4 = __ldg(wr + g);
            acc[g*4+0] = fmaf(kv, w4.x, acc[g*4+0]);
            acc[g*4+1] = fmaf(kv, w4.y, acc[g*4+1]);
            acc[g*4+2] = fmaf(kv, w4.z, acc[g*4+2]);
            acc[g*4+3] = fmaf(kv, w4.w, acc[g*4+3]);
        }
    }
    float4* dst = (float4*)(g_C + (size_t)l * 16384 + j * 128 + oc);
    #pragma unroll
    for (int g = 0; g < 16; ++g)
        dst[g] = make_float4(acc[g*4], acc[g*4+1], acc[g*4+2], acc[g*4+3]);
}

// ---------------------------------------------------------------------------
// wprep: pre-split weights to bf16 hi/lo, transposed to [n][k]. grid (2, 6).
// ---------------------------------------------------------------------------
__global__ void __launch_bounds__(256) wprep_kernel(
    const float* __restrict__ Wq, const float* __restrict__ W1,
    const float* __restrict__ W2)
{
    int b = blockIdx.x, inv = blockIdx.y;
    int l = inv >> 1, mode = inv & 1;
    __nv_bfloat16* dh = g_ws + ((size_t)(inv * 4 + b * 2)) * 16384;
    __nv_bfloat16* dl = dh + 16384;
    for (int i = threadIdx.x; i < 16384; i += 256) {
        int n = i >> 7, k = i & 127;
        float v;
        if (b == 0)
            v = mode ? W1[(size_t)l * 16384 + k * 128 + n]
                     : Wq[(size_t)l * 16384 + (n >> 5) * 4096 + k * 32 + (n & 31)];
        else
            v = mode ? W2[(size_t)l * 16384 + k * 128 + n]
                     : g_C[(size_t)l * 16384 + k * 128 + n];
        __nv_bfloat16 hi = __float2bfloat16_rn(v);
        __nv_bfloat16 lo = __float2bfloat16_rn(v - __bfloat162float(hi));
        dh[i] = hi; dl[i] = lo;
    }
}

// ---------------------------------------------------------------------------
// Layer kernel: mma.sync m16n8k16 bf16x3 compensated, two chained GEMMs.
// CTA = 128 points. Warp w: rows (w&3)*32..+32, cols (w>>2)*64..+64.
// smem tiles [row/n][k] bf16 with 272-byte row stride (conflict-free frags).
// ---------------------------------------------------------------------------
#define TS 272                       // smem row stride in bytes
#define TILE_B (128 * TS)            // 34816
#define LAY_SMEM (6 * TILE_B + 1536) // 210432

__device__ __forceinline__ void do_gemm(
    float d[2][8][4], const char* A, const char* Alo,
    const char* B, const char* Blo, int rowbase, int colbase, int g, int tg)
{
    #pragma unroll
    for (int p = 0; p < 3; ++p) {
        const char* Ap = (p == 2) ? Alo : A;
        const char* Bp = (p == 1) ? Blo : B;
        #pragma unroll
        for (int ks = 0; ks < 8; ++ks) {
            int kb = ks * 32 + tg * 4;
            uint32_t a[2][4];
            #pragma unroll
            for (int mt = 0; mt < 2; ++mt) {
                const char* ap = Ap + (rowbase + mt * 16 + g) * TS + kb;
                a[mt][0] = *(const uint32_t*)(ap);
                a[mt][1] = *(const uint32_t*)(ap + 8 * TS);
                a[mt][2] = *(const uint32_t*)(ap + 16);
                a[mt][3] = *(const uint32_t*)(ap + 8 * TS + 16);
            }
            #pragma unroll
            for (int nt = 0; nt < 8; ++nt) {
                const char* bp = Bp + (colbase + nt * 8 + g) * TS + kb;
                uint32_t b0 = *(const uint32_t*)(bp);
                uint32_t b1 = *(const uint32_t*)(bp + 16);
                mma16816(d[0][nt], a[0], b0, b1);
                mma16816(d[1][nt], a[1], b0, b1);
            }
        }
    }
}

__global__ void __launch_bounds__(256) layer_mma(
    int mode, int l, const float* __restrict__ b1p, const float* __restrict__ b2p)
{
    char* sm = smem_raw;
    char* sAhi = sm;
    char* sAlo = sm + TILE_B;
    char* sB1h = sm + 2 * TILE_B;
    char* sB1l = sm + 3 * TILE_B;
    char* sB2h = sm + 4 * TILE_B;
    char* sB2l = sm + 5 * TILE_B;
    float* fB1 = (float*)(sm + 6 * TILE_B);
    float* fB2 = fB1 + 128;
    float* fKs = fB2 + 128;

    int t = threadIdx.x, wid = t >> 5, lane = t & 31;
    int g = lane >> 2, tg = lane & 3;
    const float* ain  = mode ? (const float*)g_x : (const float*)g_h;
    float*       aout = mode ? (float*)g_h : (float*)g_x;
    size_t pt0 = (size_t)blockIdx.x * 128;

    // ---- stage A (fp32 -> bf16 hi/lo, row-major stride TS) ----
    {
        const float* src = ain + pt0 * 128;
        #pragma unroll 4
        for (int it = 0; it < 16; ++it) {
            int i4 = t + it * 256;
            int row = i4 >> 5, c4 = (i4 & 31) * 4;
            float4 v = *(const float4*)(src + row * 128 + c4);
            uint32_t h0, l0, h1, l1;
            cvt_pair(v.x, v.y, h0, l0);
            cvt_pair(v.z, v.w, h1, l1);
            *(unsigned long long*)(sAhi + row * TS + c4 * 2) =
                ((unsigned long long)h1 << 32) | h0;
            *(unsigned long long*)(sAlo + row * TS + c4 * 2) =
                ((unsigned long long)l1 << 32) | l0;
        }
    }
    // ---- stage B tiles (pre-split bf16, copy with stride TS) ----
    {
        const __nv_bfloat16* ws = g_ws + (size_t)(l * 2 + mode) * 4 * 16384;
        #pragma unroll
        for (int tile = 0; tile < 4; ++tile) {
            char* dst = sB1h + tile * TILE_B;
            const __nv_bfloat16* src = ws + tile * 16384;
            #pragma unroll 2
            for (int it = 0; it < 8; ++it) {
                int idx = t + it * 256;
                int n = idx >> 4, c = idx & 15;
                *(uint4*)(dst + n * TS + c * 16) = *(const uint4*)(src + n * 128 + c * 8);
            }
        }
    }
    if (t < 128) {
        fB1[t] = b1p[t];
        fB2[t] = b2p[t];
        if (mode == 0) fKs[t] = g_ksum[l * 128 + t];
    }
    __syncthreads();

    int rowbase = (wid & 3) * 32, colbase = (wid >> 2) * 64;

    // ---- GEMM 1 ----
    float d[2][8][4];
    #pragma unroll
    for (int mt = 0; mt < 2; ++mt)
        #pragma unroll
        for (int nt = 0; nt < 8; ++nt)
            { d[mt][nt][0]=0.f; d[mt][nt][1]=0.f; d[mt][nt][2]=0.f; d[mt][nt][3]=0.f; }
    do_gemm(d, sAhi, sAlo, sB1h, sB1l, rowbase, colbase, g, tg);

    // ---- epilogue 1 ----
    if (mode == 0) {
        float s[2][2][2];   // [mt][j(row)][head]
        #pragma unroll
        for (int mt = 0; mt < 2; ++mt)
            { s[mt][0][0]=0.f; s[mt][0][1]=0.f; s[mt][1][0]=0.f; s[mt][1][1]=0.f; }
        #pragma unroll
        for (int nt = 0; nt < 8; ++nt) {
            int c = colbase + nt * 8 + tg * 2;
            float2 bb = *(const float2*)(fB1 + c);
            float2 kk = *(const float2*)(fKs + c);
            int hh = nt >> 2;
            #pragma unroll
            for (int mt = 0; mt < 2; ++mt) {
                float u0 = d[mt][nt][0] + bb.x; u0 *= u0; d[mt][nt][0] = u0;
                float u1 = d[mt][nt][1] + bb.y; u1 *= u1; d[mt][nt][1] = u1;
                float u2 = d[mt][nt][2] + bb.x; u2 *= u2; d[mt][nt][2] = u2;
                float u3 = d[mt][nt][3] + bb.y; u3 *= u3; d[mt][nt][3] = u3;
                s[mt][0][hh] = fmaf(u0, kk.x, fmaf(u1, kk.y, s[mt][0][hh]));
                s[mt][1][hh] = fmaf(u2, kk.x, fmaf(u3, kk.y, s[mt][1][hh]));
            }
        }
        float z[2][2][2];
        #pragma unroll
        for (int mt = 0; mt < 2; ++mt)
            #pragma unroll
            for (int j = 0; j < 2; ++j)
                #pragma unroll
                for (int hh = 0; hh < 2; ++hh) {
                    float v = s[mt][j][hh];
                    v += __shfl_xor_sync(0xffffffffu, v, 1);
                    v += __shfl_xor_sync(0xffffffffu, v, 2);
                    z[mt][j][hh] = 1.0f / (v + 1e-6f);
                }
        #pragma unroll
        for (int nt = 0; nt < 8; ++nt) {
            int hh = nt >> 2;
            #pragma unroll
            for (int mt = 0; mt < 2; ++mt) {
                d[mt][nt][0] *= z[mt][0][hh];
                d[mt][nt][1] *= z[mt][0][hh];
                d[mt][nt][2] *= z[mt][1][hh];
                d[mt][nt][3] *= z[mt][1][hh];
            }
        }
    } else {
        #pragma unroll
        for (int nt = 0; nt < 8; ++nt) {
            int c = colbase + nt * 8 + tg * 2;
            float2 bb = *(const float2*)(fB1 + c);
            #pragma unroll
            for (int mt = 0; mt < 2; ++mt) {
                d[mt][nt][0] = geluf(d[mt][nt][0] + bb.x);
                d[mt][nt][1] = geluf(d[mt][nt][1] + bb.y);
                d[mt][nt][2] = geluf(d[mt][nt][2] + bb.x);
                d[mt][nt][3] = geluf(d[mt][nt][3] + bb.y);
            }
        }
    }
    __syncthreads();   // all warps done reading A before overwrite

    // ---- write A' (hi/lo) back to smem ----
    #pragma unroll
    for (int mt = 0; mt < 2; ++mt) {
        #pragma unroll
        for (int j = 0; j < 2; ++j) {
            int row = rowbase + mt * 16 + g + j * 8;
            #pragma unroll
            for (int nt = 0; nt < 8; ++nt) {
                int cb = (colbase + nt * 8 + tg * 2) * 2;
                uint32_t hi, lo;
                cvt_pair(d[mt][nt][2 * j], d[mt][nt][2 * j + 1], hi, lo);
                *(uint32_t*)(sAhi + row * TS + cb) = hi;
                *(uint32_t*)(sAlo + row * TS + cb) = lo;
            }
        }
    }
    __syncthreads();

    // ---- GEMM 2 ----
    #pragma unroll
    for (int mt = 0; mt < 2; ++mt)
        #pragma unroll
        for (int nt = 0; nt < 8; ++nt)
            { d[mt][nt][0]=0.f; d[mt][nt][1]=0.f; d[mt][nt][2]=0.f; d[mt][nt][3]=0.f; }
    do_gemm(d, sAhi, sAlo, sB2h, sB2l, rowbase, colbase, g, tg);

    // ---- epilogue 2: out = residual + D + bias2 ----
    #pragma unroll
    for (int mt = 0; mt < 2; ++mt) {
        #pragma unroll
        for (int j = 0; j < 2; ++j) {
            int row = rowbase + mt * 16 + g + j * 8;
            const float* res = ain + (pt0 + row) * 128;
            float* dst = aout + (pt0 + row) * 128;
            #pragma unroll
            for (int nt = 0; nt < 8; ++nt) {
                int c = colbase + nt * 8 + tg * 2;
                float2 rv = *(const float2*)(res + c);
                float2 bb = *(const float2*)(fB2 + c);
                float2 o;
                o.x = rv.x + d[mt][nt][2 * j]     + bb.x;
                o.y = rv.y + d[mt][nt][2 * j + 1] + bb.y;
                *(float2*)(dst + c) = o;
            }
        }
    }
}

// ---------------------------------------------------------------------------
// Final projector (fp32): out = gelu(h @ pw1 + pb1) @ pw2 + pb2
// ---------------------------------------------------------------------------
#define FIN_SMEM (20812 * 4)
__global__ void __launch_bounds__(256) final_kernel(
    const float* __restrict__ pw1, const float* __restrict__ pb1,
    const float* __restrict__ pw2, const float* __restrict__ pb2,
    float* __restrict__ out)
{
    float* sm = (float*)smem_raw;
    float* sH   = sm;
    float* sW1  = sH + 8192;
    float* sT   = sW1 + 8192;
    float* spw2 = sT + 4160;
    float* spb1 = spw2 + 192;
    float* spb2 = spb1 + 64;
    int t = threadIdx.x;
    size_t pt0 = (size_t)blockIdx.x * 64;
    {
        const float4* src = (const float4*)(g_h + pt0 * 128);
        for (int i = t; i < 2048; i += 256) ((float4*)sH)[i] = src[i];
    }
    for (int i = t; i < 2048; i += 256) ((float4*)sW1)[i] = ((const float4*)pw1)[i];
    if (t < 192) spw2[t] = pw2[t];
    if (t < 64)  spb1[t] = pb1[t];
    if (t < 3)   spb2[t] = pb2[t];
    __syncthreads();
    int wid = t >> 5, lane = t & 31;
    int m0 = wid * 8, jc = lane * 2;
    float acc[8][2];
    #pragma unroll
    for (int i = 0; i < 8; ++i) { acc[i][0] = acc[i][1] = 0.f; }
    #pragma unroll 2
    for (int k = 0; k < 128; ++k) {
        float2 b2v = *(const float2*)(sW1 + k * 64 + jc);
        #pragma unroll
        for (int i = 0; i < 8; ++i) {
            float a = sH[(m0 + i) * 128 + k];
            acc[i][0] = fmaf(a, b2v.x, acc[i][0]);
            acc[i][1] = fmaf(a, b2v.y, acc[i][1]);
        }
    }
    float c0 = spb1[jc], c1 = spb1[jc + 1];
    #pragma unroll
    for (int i = 0; i < 8; ++i) {
        sT[(m0 + i) * 65 + jc]     = geluf(acc[i][0] + c0);
        sT[(m0 + i) * 65 + jc + 1] = geluf(acc[i][1] + c1);
    }
    __syncthreads();
    if (t < 192) {
        int n = t / 3, c = t - n * 3;
        float s = spb2[c];
        #pragma unroll 4
        for (int k = 0; k < 64; ++k) s = fmaf(sT[n * 65 + k], spw2[k * 3 + c], s);
        out[(pt0 + n) * 3 + c] = s;
    }
}

// ---------------------------------------------------------------------------
extern "C" void kernel_launch(void* const* d_in, const int* in_sizes, int n_in,
                              void* d_out, int out_size)
{
    const float* qp    = (const float*)d_in[0];
    const float* bp    = (const float*)d_in[1];
    const float* pe_w  = (const float*)d_in[2];
    const float* pe_b  = (const float*)d_in[3];
    const float* bpe_w = (const float*)d_in[4];
    const float* bpe_b = (const float*)d_in[5];
    const float* Wq    = (const float*)d_in[6];
    const float* bq    = (const float*)d_in[7];
    const float* Wk    = (const float*)d_in[8];
    const float* bk    = (const float*)d_in[9];
    const float* Wv    = (const float*)d_in[10];
    const float* bv    = (const float*)d_in[11];
    const float* Wo    = (const float*)d_in[12];
    const float* bo    = (const float*)d_in[13];
    const float* W1    = (const float*)d_in[14];
    const float* b1    = (const float*)d_in[15];
    const float* W2    = (const float*)d_in[16];
    const float* b2    = (const float*)d_in[17];
    const float* pw1   = (const float*)d_in[18];
    const float* pb1   = (const float*)d_in[19];
    const float* pw2   = (const float*)d_in[20];
    const float* pb2   = (const float*)d_in[21];
    float* out = (float*)d_out;

    cudaFuncSetAttribute(bkv_kernel,   cudaFuncAttributeMaxDynamicSharedMemorySize, BKV_SMEM);
    cudaFuncSetAttribute(layer_mma,    cudaFuncAttributeMaxDynamicSharedMemorySize, LAY_SMEM);
    cudaFuncSetAttribute(final_kernel, cudaFuncAttributeMaxDynamicSharedMemorySize, FIN_SMEM);

    encode_kernel<<<64,   256>>>(bp, bpe_w, bpe_b, 1);
    encode_kernel<<<4096, 256>>>(qp, pe_w,  pe_b,  0);
    bkv_kernel<<<dim3(32, 12), 256, BKV_SMEM>>>(Wk, bk, Wv, bv);
    kvreduce_kernel<<<12, 256>>>();
    cfold_kernel<<<3, 256>>>(Wo);
    wprep_kernel<<<dim3(2, 6), 256>>>(Wq, W1, W2);
    for (int l = 0; l < 3; ++l) {
        layer_mma<<<2048, 256, LAY_SMEM>>>(0, l, bq + l * 128, bo + l * 128);
        layer_mma<<<2048, 256, LAY_SMEM>>>(1, l, b1 + l * 128, b2 + l * 128);
    }
    final_kernel<<<4096, 256, FIN_SMEM>>>(pw1, pb1, pw2, pb2, out);
}

// round 13
// speedup vs baseline: 2.0477x; 1.0782x over previous
#include <cuda_runtime.h>
#include <cuda_bf16.h>
#include <cstdint>

#define NQ 262144
#define MB 4096
#define PI_F 3.14159265358979323846f

extern __shared__ char smem_raw[];

// ------------------------- device scratch (no allocs) -----------------------
__device__ __align__(16) float g_h[(size_t)NQ * 128];
__device__ __align__(16) float g_x[(size_t)NQ * 128];
__device__ __align__(16) float g_benc[MB * 128];
__device__ __align__(16) float g_kvp[12 * 32 * 1024];
__device__ __align__(16) float g_ksp[12 * 32 * 32];
__device__ __align__(16) float g_kv[12 * 1024];
__device__ __align__(16) float g_ksum[384];
__device__ __align__(16) float g_C[3 * 16384];
// pre-split weights: [inv=l*2+mode][tile=B1h,B1l,B2h,B2l][n*128+k] bf16
__device__ __align__(16) __nv_bfloat16 g_ws[6 * 4 * 16384];

__device__ __forceinline__ float geluf(float u) {
    return 0.5f * u * (1.0f + erff(u * 0.70710678118654752f));
}

__device__ __forceinline__ void cp_async16(void* dst_smem, const void* src) {
    uint32_t d = (uint32_t)__cvta_generic_to_shared(dst_smem);
    asm volatile("cp.async.cg.shared.global [%0], [%1], 16;" :: "r"(d), "l"(src));
}
__device__ __forceinline__ void cp_async_commit() {
    asm volatile("cp.async.commit_group;");
}
__device__ __forceinline__ void cp_async_wait_all() {
    asm volatile("cp.async.wait_group 0;");
}

// split fp32 pair into bf16-hi pair and bf16-lo pair (packed uint32 each)
__device__ __forceinline__ void cvt_pair(float a, float b, uint32_t& hi, uint32_t& lo) {
    __nv_bfloat16 ah = __float2bfloat16_rn(a), bh = __float2bfloat16_rn(b);
    float ar = a - __bfloat162float(ah), br = b - __bfloat162float(bh);
    __nv_bfloat16 al = __float2bfloat16_rn(ar), bl = __float2bfloat16_rn(br);
    hi = (uint32_t)__bfloat16_as_ushort(ah) | ((uint32_t)__bfloat16_as_ushort(bh) << 16);
    lo = (uint32_t)__bfloat16_as_ushort(al) | ((uint32_t)__bfloat16_as_ushort(bl) << 16);
}

__device__ __forceinline__ void mma16816(float* d, const uint32_t* a,
                                         uint32_t b0, uint32_t b1) {
    asm volatile(
        "mma.sync.aligned.m16n8k16.row.col.f32.bf16.bf16.f32 "
        "{%0,%1,%2,%3}, {%4,%5,%6,%7}, {%8,%9}, {%0,%1,%2,%3};"
        : "+f"(d[0]), "+f"(d[1]), "+f"(d[2]), "+f"(d[3])
        : "r"(a[0]), "r"(a[1]), "r"(a[2]), "r"(a[3]), "r"(b0), "r"(b1));
}

// ---------------------------------------------------------------------------
// Positional encoder (fp32): dst[p][:] = sin(mfe(pts[p]) @ W + b). 64 pts/CTA.
// ---------------------------------------------------------------------------
__global__ void __launch_bounds__(256) encode_kernel(
    const float* __restrict__ pts, const float* __restrict__ w,
    const float* __restrict__ b, int which)
{
    __shared__ float sW[3840];
    __shared__ float sB[128];
    __shared__ float sF[64 * 32];
    int t = threadIdx.x;
    for (int i = t; i < 960; i += 256) ((float4*)sW)[i] = ((const float4*)w)[i];
    if (t < 128) sB[t] = b[t];
    size_t pt0 = (size_t)blockIdx.x * 64;
    if (t < 64) {
        float2 xy = ((const float2*)pts)[pt0 + t];
        float* F = sF + t * 32;
        #pragma unroll
        for (int c = 0; c < 2; ++c) {
            float v = c ? xy.y : xy.x;
            float a15 = v - 1.5f, a45 = v - 4.5f, pv = PI_F * v;
            F[0 + c] = v;           F[2 + c] = v * v;
            F[4 + c] = a15 * a15;   F[6 + c] = a45 * a45;
            F[8 + c]  = 1.f / (1.f + expf(-v));
            F[10 + c] = 1.f / (1.f + expf(-a15));
            F[12 + c] = 1.f / (1.f + expf(-a45));
            F[14 + c] = a15;        F[16 + c] = a45;
            F[18 + c] = sinf(pv);          F[20 + c] = cosf(pv);
            F[22 + c] = sinf(pv * 0.25f);  F[24 + c] = cosf(pv * 0.25f);
            F[26 + c] = sinf(pv * 0.5f);   F[28 + c] = cosf(pv * 0.5f);
        }
    }
    __syncthreads();
    int wid = t >> 5, lane = t & 31;
    int m0 = wid * 8, jc = lane * 4;
    float acc[8][4];
    #pragma unroll
    for (int i = 0; i < 8; ++i) { acc[i][0]=acc[i][1]=acc[i][2]=acc[i][3]=0.f; }
    #pragma unroll 2
    for (int k = 0; k < 30; ++k) {
        float4 b4 = *(const float4*)(sW + k * 128 + jc);
        #pragma unroll
        for (int i = 0; i < 8; ++i) {
            float a = sF[(m0 + i) * 32 + k];
            acc[i][0] = fmaf(a, b4.x, acc[i][0]);
            acc[i][1] = fmaf(a, b4.y, acc[i][1]);
            acc[i][2] = fmaf(a, b4.z, acc[i][2]);
            acc[i][3] = fmaf(a, b4.w, acc[i][3]);
        }
    }
    float b0 = sB[jc], b1 = sB[jc+1], b2 = sB[jc+2], b3 = sB[jc+3];
    float* dst = which ? g_benc : g_h;
    #pragma unroll
    for (int i = 0; i < 8; ++i) {
        float4 o;
        o.x = sinf(acc[i][0] + b0); o.y = sinf(acc[i][1] + b1);
        o.z = sinf(acc[i][2] + b2); o.w = sinf(acc[i][3] + b3);
        *(float4*)(dst + (pt0 + m0 + i) * 128 + jc) = o;
    }
}

// ---------------------------------------------------------------------------
// Boundary kv (fp32, tiny): per (tile, lh) partial kv / ksum.
// ---------------------------------------------------------------------------
#define BKV_SMEM (34372 * 4)
__global__ void __launch_bounds__(256) bkv_kernel(
    const float* __restrict__ Wk_g, const float* __restrict__ bk_g,
    const float* __restrict__ Wv_g, const float* __restrict__ bv_g)
{
    float* sm = (float*)smem_raw;
    float* sE  = sm;
    float* sWk = sE + 16896;
    float* sWv = sWk + 4100;
    float* sKh = sWv + 4096;
    float* sVh = sKh + 4608;
    float* sbk = sVh + 4608;
    float* sbv = sbk + 32;
    int t = threadIdx.x;
    int tile = blockIdx.x, lh = blockIdx.y;
    {
        const float4* src = (const float4*)(g_benc + (size_t)tile * 128 * 128);
        for (int i = t; i < 4096; i += 256) {
            int r = i >> 5, c = i & 31;
            *(float4*)(sE + r * 132 + c * 4) = src[i];
        }
    }
    for (int i = t; i < 1024; i += 256) {
        ((float4*)sWk)[i] = ((const float4*)(Wk_g + (size_t)lh * 4096))[i];
        ((float4*)sWv)[i] = ((const float4*)(Wv_g + (size_t)lh * 4096))[i];
    }
    if (t < 32) { sbk[t] = bk_g[lh * 32 + t]; sbv[t] = bv_g[lh * 32 + t]; }
    __syncthreads();
    {
        int m = t >> 1, kind = t & 1;
        const float* W  = kind ? sWv : sWk;
        const float* sb = kind ? sbv : sbk;
        float4 acc[8];
        #pragma unroll
        for (int g = 0; g < 8; ++g) acc[g] = make_float4(0.f, 0.f, 0.f, 0.f);
        for (int d = 0; d < 128; ++d) {
            float v = sE[m * 132 + d];
            #pragma unroll
            for (int g = 0; g < 8; ++g) {
                float4 w4 = *(const float4*)(W + d * 32 + g * 4);
                acc[g].x = fmaf(v, w4.x, acc[g].x);
                acc[g].y = fmaf(v, w4.y, acc[g].y);
                acc[g].z = fmaf(v, w4.z, acc[g].z);
                acc[g].w = fmaf(v, w4.w, acc[g].w);
            }
        }
        float* dst = (kind ? sVh : sKh) + m * 36;
        #pragma unroll
        for (int g = 0; g < 8; ++g) {
            float4 a = acc[g];
            a.x += sb[g*4+0]; a.y += sb[g*4+1]; a.z += sb[g*4+2]; a.w += sb[g*4+3];
            if (!kind) { a.x *= a.x; a.y *= a.y; a.z *= a.z; a.w *= a.w; }
            *(float4*)(dst + g * 4) = a;
        }
    }
    __syncthreads();
    {
        int e = t >> 3, c4 = (t & 7) * 4;
        float4 acc = make_float4(0.f, 0.f, 0.f, 0.f);
        for (int m = 0; m < 128; ++m) {
            float kh = sKh[m * 36 + e];
            float4 v4 = *(const float4*)(sVh + m * 36 + c4);
            acc.x = fmaf(kh, v4.x, acc.x); acc.y = fmaf(kh, v4.y, acc.y);
            acc.z = fmaf(kh, v4.z, acc.z); acc.w = fmaf(kh, v4.w, acc.w);
        }
        *(float4*)(g_kvp + ((size_t)lh * 32 + tile) * 1024 + e * 32 + c4) = acc;
        if (t < 32) {
            float s = 0.f;
            for (int m = 0; m < 128; ++m) s += sKh[m * 36 + t];
            g_ksp[((size_t)lh * 32 + tile) * 32 + t] = s;
        }
    }
}

__global__ void __launch_bounds__(256) kvreduce_kernel()
{
    int lh = blockIdx.x, t = threadIdx.x;
    for (int idx = t; idx < 1024; idx += 256) {
        float s = 0.f;
        for (int tile = 0; tile < 32; ++tile)
            s += g_kvp[((size_t)lh * 32 + tile) * 1024 + idx];
        g_kv[lh * 1024 + idx] = s;
    }
    if (t < 32) {
        float s = 0.f;
        for (int tile = 0; tile < 32; ++tile)
            s += g_ksp[((size_t)lh * 32 + tile) * 32 + t];
        g_ksum[lh * 32 + t] = s;
    }
}

__global__ void __launch_bounds__(256) cfold_kernel(const float* __restrict__ Wo_g)
{
    int l = blockIdx.x, t = threadIdx.x;
    int j = t >> 1, oc = (t & 1) * 64;
    int h = j >> 5, e = j & 31;
    float acc[64];
    #pragma unroll
    for (int o = 0; o < 64; ++o) acc[o] = 0.f;
    for (int ep = 0; ep < 32; ++ep) {
        float kv = g_kv[(l * 4 + h) * 1024 + e * 32 + ep];
        const float4* wr = (const float4*)(Wo_g + ((size_t)(l * 128 + h * 32 + ep)) * 128 + oc);
        #pragma unroll
        for (int g = 0; g < 16; ++g) {
            float4 w4 = __ldg(wr + g);
            acc[g*4+0] = fmaf(kv, w4.x, acc[g*4+0]);
            acc[g*4+1] = fmaf(kv, w4.y, acc[g*4+1]);
            acc[g*4+2] = fmaf(kv, w4.z, acc[g*4+2]);
            acc[g*4+3] = fmaf(kv, w4.w, acc[g*4+3]);
        }
    }
    float4* dst = (float4*)(g_C + (size_t)l * 16384 + j * 128 + oc);
    #pragma unroll
    for (int g = 0; g < 16; ++g)
        dst[g] = make_float4(acc[g*4], acc[g*4+1], acc[g*4+2], acc[g*4+3]);
}

// ---------------------------------------------------------------------------
// wprep: pre-split weights to bf16 hi/lo, transposed to [n][k]. grid (2, 6).
// ---------------------------------------------------------------------------
__global__ void __launch_bounds__(256) wprep_kernel(
    const float* __restrict__ Wq, const float* __restrict__ W1,
    const float* __restrict__ W2)
{
    int b = blockIdx.x, inv = blockIdx.y;
    int l = inv >> 1, mode = inv & 1;
    __nv_bfloat16* dh = g_ws + ((size_t)(inv * 4 + b * 2)) * 16384;
    __nv_bfloat16* dl = dh + 16384;
    for (int i = threadIdx.x; i < 16384; i += 256) {
        int n = i >> 7, k = i & 127;
        float v;
        if (b == 0)
            v = mode ? W1[(size_t)l * 16384 + k * 128 + n]
                     : Wq[(size_t)l * 16384 + (n >> 5) * 4096 + k * 32 + (n & 31)];
        else
            v = mode ? W2[(size_t)l * 16384 + k * 128 + n]
                     : g_C[(size_t)l * 16384 + k * 128 + n];
        __nv_bfloat16 hi = __float2bfloat16_rn(v);
        __nv_bfloat16 lo = __float2bfloat16_rn(v - __bfloat162float(hi));
        dh[i] = hi; dl[i] = lo;
    }
}

// ---------------------------------------------------------------------------
// Persistent layer kernel: mma.sync m16n8k16 bf16x3, two chained GEMMs.
// B tiles staged ONCE per CTA (cp.async); CTA strided-loops over point tiles.
// ---------------------------------------------------------------------------
#define TS 272                       // smem row stride in bytes
#define TILE_B (128 * TS)            // 34816
#define LAY_SMEM (6 * TILE_B + 1536) // 210432
#define NTILES 2048
#define LAY_GRID 148

__device__ __forceinline__ void do_gemm(
    float d[2][8][4], const char* A, const char* Alo,
    const char* B, const char* Blo, int rowbase, int colbase, int g, int tg)
{
    #pragma unroll
    for (int p = 0; p < 3; ++p) {
        const char* Ap = (p == 2) ? Alo : A;
        const char* Bp = (p == 1) ? Blo : B;
        #pragma unroll
        for (int ks = 0; ks < 8; ++ks) {
            int kb = ks * 32 + tg * 4;
            uint32_t a[2][4];
            #pragma unroll
            for (int mt = 0; mt < 2; ++mt) {
                const char* ap = Ap + (rowbase + mt * 16 + g) * TS + kb;
                a[mt][0] = *(const uint32_t*)(ap);
                a[mt][1] = *(const uint32_t*)(ap + 8 * TS);
                a[mt][2] = *(const uint32_t*)(ap + 16);
                a[mt][3] = *(const uint32_t*)(ap + 8 * TS + 16);
            }
            #pragma unroll
            for (int nt = 0; nt < 8; ++nt) {
                const char* bp = Bp + (colbase + nt * 8 + g) * TS + kb;
                uint32_t b0 = *(const uint32_t*)(bp);
                uint32_t b1 = *(const uint32_t*)(bp + 16);
                mma16816(d[0][nt], a[0], b0, b1);
                mma16816(d[1][nt], a[1], b0, b1);
            }
        }
    }
}

__global__ void __launch_bounds__(256) layer_mma(
    int mode, int l, const float* __restrict__ b1p, const float* __restrict__ b2p)
{
    char* sm = smem_raw;
    char* sAhi = sm;
    char* sAlo = sm + TILE_B;
    char* sB1h = sm + 2 * TILE_B;
    char* sB1l = sm + 3 * TILE_B;
    char* sB2h = sm + 4 * TILE_B;
    char* sB2l = sm + 5 * TILE_B;
    float* fB1 = (float*)(sm + 6 * TILE_B);
    float* fB2 = fB1 + 128;
    float* fKs = fB2 + 128;

    int t = threadIdx.x, wid = t >> 5, lane = t & 31;
    int g = lane >> 2, tg = lane & 3;
    const float* ain  = mode ? (const float*)g_x : (const float*)g_h;
    float*       aout = mode ? (float*)g_h : (float*)g_x;
    int rowbase = (wid & 3) * 32, colbase = (wid >> 2) * 64;

    // ---- stage all 4 B tiles once per CTA (cp.async, stride TS) ----
    {
        const __nv_bfloat16* ws = g_ws + (size_t)(l * 2 + mode) * 4 * 16384;
        #pragma unroll
        for (int tile4 = 0; tile4 < 4; ++tile4) {
            char* dst = sB1h + tile4 * TILE_B;
            const __nv_bfloat16* src = ws + tile4 * 16384;
            #pragma unroll 2
            for (int it = 0; it < 8; ++it) {
                int idx = t + it * 256;
                int n = idx >> 4, c = idx & 15;
                cp_async16(dst + n * TS + c * 16, src + n * 128 + c * 8);
            }
        }
        cp_async_commit();
    }
    if (t < 128) {
        fB1[t] = b1p[t];
        fB2[t] = b2p[t];
        fKs[t] = (mode == 0) ? g_ksum[l * 128 + t] : 0.f;
    }
    bool first = true;

    for (int tile = blockIdx.x; tile < NTILES; tile += LAY_GRID) {
        size_t pt0 = (size_t)tile * 128;

        if (!first) __syncthreads();   // prior GEMM2 reads of sA done

        // ---- stage A (fp32 -> bf16 hi/lo, row-major stride TS) ----
        {
            const float* src = ain + pt0 * 128;
            #pragma unroll 4
            for (int it = 0; it < 16; ++it) {
                int i4 = t + it * 256;
                int row = i4 >> 5, c4 = (i4 & 31) * 4;
                float4 v = *(const float4*)(src + row * 128 + c4);
                uint32_t h0, l0, h1, l1;
                cvt_pair(v.x, v.y, h0, l0);
                cvt_pair(v.z, v.w, h1, l1);
                *(unsigned long long*)(sAhi + row * TS + c4 * 2) =
                    ((unsigned long long)h1 << 32) | h0;
                *(unsigned long long*)(sAlo + row * TS + c4 * 2) =
                    ((unsigned long long)l1 << 32) | l0;
            }
        }
        if (first) { cp_async_wait_all(); first = false; }
        __syncthreads();

        // ---- GEMM 1 ----
        float d[2][8][4];
        #pragma unroll
        for (int mt = 0; mt < 2; ++mt)
            #pragma unroll
            for (int nt = 0; nt < 8; ++nt)
                { d[mt][nt][0]=0.f; d[mt][nt][1]=0.f; d[mt][nt][2]=0.f; d[mt][nt][3]=0.f; }
        do_gemm(d, sAhi, sAlo, sB1h, sB1l, rowbase, colbase, g, tg);

        // ---- epilogue 1 ----
        if (mode == 0) {
            float s[2][2][2];   // [mt][j(row)][head]
            #pragma unroll
            for (int mt = 0; mt < 2; ++mt)
                { s[mt][0][0]=0.f; s[mt][0][1]=0.f; s[mt][1][0]=0.f; s[mt][1][1]=0.f; }
            #pragma unroll
            for (int nt = 0; nt < 8; ++nt) {
                int c = colbase + nt * 8 + tg * 2;
                float2 bb = *(const float2*)(fB1 + c);
                float2 kk = *(const float2*)(fKs + c);
                int hh = nt >> 2;
                #pragma unroll
                for (int mt = 0; mt < 2; ++mt) {
                    float u0 = d[mt][nt][0] + bb.x; u0 *= u0; d[mt][nt][0] = u0;
                    float u1 = d[mt][nt][1] + bb.y; u1 *= u1; d[mt][nt][1] = u1;
                    float u2 = d[mt][nt][2] + bb.x; u2 *= u2; d[mt][nt][2] = u2;
                    float u3 = d[mt][nt][3] + bb.y; u3 *= u3; d[mt][nt][3] = u3;
                    s[mt][0][hh] = fmaf(u0, kk.x, fmaf(u1, kk.y, s[mt][0][hh]));
                    s[mt][1][hh] = fmaf(u2, kk.x, fmaf(u3, kk.y, s[mt][1][hh]));
                }
            }
            float z[2][2][2];
            #pragma unroll
            for (int mt = 0; mt < 2; ++mt)
                #pragma unroll
                for (int j = 0; j < 2; ++j)
                    #pragma unroll
                    for (int hh = 0; hh < 2; ++hh) {
                        float v = s[mt][j][hh];
                        v += __shfl_xor_sync(0xffffffffu, v, 1);
                        v += __shfl_xor_sync(0xffffffffu, v, 2);
                        z[mt][j][hh] = 1.0f / (v + 1e-6f);
                    }
            #pragma unroll
            for (int nt = 0; nt < 8; ++nt) {
                int hh = nt >> 2;
                #pragma unroll
                for (int mt = 0; mt < 2; ++mt) {
                    d[mt][nt][0] *= z[mt][0][hh];
                    d[mt][nt][1] *= z[mt][0][hh];
                    d[mt][nt][2] *= z[mt][1][hh];
                    d[mt][nt][3] *= z[mt][1][hh];
                }
            }
        } else {
            #pragma unroll
            for (int nt = 0; nt < 8; ++nt) {
                int c = colbase + nt * 8 + tg * 2;
                float2 bb = *(const float2*)(fB1 + c);
                #pragma unroll
                for (int mt = 0; mt < 2; ++mt) {
                    d[mt][nt][0] = geluf(d[mt][nt][0] + bb.x);
                    d[mt][nt][1] = geluf(d[mt][nt][1] + bb.y);
                    d[mt][nt][2] = geluf(d[mt][nt][2] + bb.x);
                    d[mt][nt][3] = geluf(d[mt][nt][3] + bb.y);
                }
            }
        }
        __syncthreads();   // all warps done reading A before overwrite

        // ---- write A' (hi/lo) back to smem ----
        #pragma unroll
        for (int mt = 0; mt < 2; ++mt) {
            #pragma unroll
            for (int j = 0; j < 2; ++j) {
                int row = rowbase + mt * 16 + g + j * 8;
                #pragma unroll
                for (int nt = 0; nt < 8; ++nt) {
                    int cb = (colbase + nt * 8 + tg * 2) * 2;
                    uint32_t hi, lo;
                    cvt_pair(d[mt][nt][2 * j], d[mt][nt][2 * j + 1], hi, lo);
                    *(uint32_t*)(sAhi + row * TS + cb) = hi;
                    *(uint32_t*)(sAlo + row * TS + cb) = lo;
                }
            }
        }
        __syncthreads();

        // ---- GEMM 2 ----
        #pragma unroll
        for (int mt = 0; mt < 2; ++mt)
            #pragma unroll
            for (int nt = 0; nt < 8; ++nt)
                { d[mt][nt][0]=0.f; d[mt][nt][1]=0.f; d[mt][nt][2]=0.f; d[mt][nt][3]=0.f; }
        do_gemm(d, sAhi, sAlo, sB2h, sB2l, rowbase, colbase, g, tg);

        // ---- epilogue 2: out = residual + D + bias2 ----
        #pragma unroll
        for (int mt = 0; mt < 2; ++mt) {
            #pragma unroll
            for (int j = 0; j < 2; ++j) {
                int row = rowbase + mt * 16 + g + j * 8;
                const float* res = ain + (pt0 + row) * 128;
                float* dst = aout + (pt0 + row) * 128;
                #pragma unroll
                for (int nt = 0; nt < 8; ++nt) {
                    int c = colbase + nt * 8 + tg * 2;
                    float2 rv = *(const float2*)(res + c);
                    float2 bb = *(const float2*)(fB2 + c);
                    float2 o;
                    o.x = rv.x + d[mt][nt][2 * j]     + bb.x;
                    o.y = rv.y + d[mt][nt][2 * j + 1] + bb.y;
                    *(float2*)(dst + c) = o;
                }
            }
        }
    }
}

// ---------------------------------------------------------------------------
// Final projector (fp32): out = gelu(h @ pw1 + pb1) @ pw2 + pb2
// ---------------------------------------------------------------------------
#define FIN_SMEM (20812 * 4)
__global__ void __launch_bounds__(256) final_kernel(
    const float* __restrict__ pw1, const float* __restrict__ pb1,
    const float* __restrict__ pw2, const float* __restrict__ pb2,
    float* __restrict__ out)
{
    float* sm = (float*)smem_raw;
    float* sH   = sm;
    float* sW1  = sH + 8192;
    float* sT   = sW1 + 8192;
    float* spw2 = sT + 4160;
    float* spb1 = spw2 + 192;
    float* spb2 = spb1 + 64;
    int t = threadIdx.x;
    size_t pt0 = (size_t)blockIdx.x * 64;
    {
        const float4* src = (const float4*)(g_h + pt0 * 128);
        for (int i = t; i < 2048; i += 256) ((float4*)sH)[i] = src[i];
    }
    for (int i = t; i < 2048; i += 256) ((float4*)sW1)[i] = ((const float4*)pw1)[i];
    if (t < 192) spw2[t] = pw2[t];
    if (t < 64)  spb1[t] = pb1[t];
    if (t < 3)   spb2[t] = pb2[t];
    __syncthreads();
    int wid = t >> 5, lane = t & 31;
    int m0 = wid * 8, jc = lane * 2;
    float acc[8][2];
    #pragma unroll
    for (int i = 0; i < 8; ++i) { acc[i][0] = acc[i][1] = 0.f; }
    #pragma unroll 2
    for (int k = 0; k < 128; ++k) {
        float2 b2v = *(const float2*)(sW1 + k * 64 + jc);
        #pragma unroll
        for (int i = 0; i < 8; ++i) {
            float a = sH[(m0 + i) * 128 + k];
            acc[i][0] = fmaf(a, b2v.x, acc[i][0]);
            acc[i][1] = fmaf(a, b2v.y, acc[i][1]);
        }
    }
    float c0 = spb1[jc], c1 = spb1[jc + 1];
    #pragma unroll
    for (int i = 0; i < 8; ++i) {
        sT[(m0 + i) * 65 + jc]     = geluf(acc[i][0] + c0);
        sT[(m0 + i) * 65 + jc + 1] = geluf(acc[i][1] + c1);
    }
    __syncthreads();
    if (t < 192) {
        int n = t / 3, c = t - n * 3;
        float s = spb2[c];
        #pragma unroll 4
        for (int k = 0; k < 64; ++k) s = fmaf(sT[n * 65 + k], spw2[k * 3 + c], s);
        out[(pt0 + n) * 3 + c] = s;
    }
}

// ---------------------------------------------------------------------------
extern "C" void kernel_launch(void* const* d_in, const int* in_sizes, int n_in,
                              void* d_out, int out_size)
{
    const float* qp    = (const float*)d_in[0];
    const float* bp    = (const float*)d_in[1];
    const float* pe_w  = (const float*)d_in[2];
    const float* pe_b  = (const float*)d_in[3];
    const float* bpe_w = (const float*)d_in[4];
    const float* bpe_b = (const float*)d_in[5];
    const float* Wq    = (const float*)d_in[6];
    const float* bq    = (const float*)d_in[7];
    const float* Wk    = (const float*)d_in[8];
    const float* bk    = (const float*)d_in[9];
    const float* Wv    = (const float*)d_in[10];
    const float* bv    = (const float*)d_in[11];
    const float* Wo    = (const float*)d_in[12];
    const float* bo    = (const float*)d_in[13];
    const float* W1    = (const float*)d_in[14];
    const float* b1    = (const float*)d_in[15];
    const float* W2    = (const float*)d_in[16];
    const float* b2    = (const float*)d_in[17];
    const float* pw1   = (const float*)d_in[18];
    const float* pb1   = (const float*)d_in[19];
    const float* pw2   = (const float*)d_in[20];
    const float* pb2   = (const float*)d_in[21];
    float* out = (float*)d_out;

    cudaFuncSetAttribute(bkv_kernel,   cudaFuncAttributeMaxDynamicSharedMemorySize, BKV_SMEM);
    cudaFuncSetAttribute(layer_mma,    cudaFuncAttributeMaxDynamicSharedMemorySize, LAY_SMEM);
    cudaFuncSetAttribute(final_kernel, cudaFuncAttributeMaxDynamicSharedMemorySize, FIN_SMEM);

    encode_kernel<<<64,   256>>>(bp, bpe_w, bpe_b, 1);
    encode_kernel<<<4096, 256>>>(qp, pe_w,  pe_b,  0);
    bkv_kernel<<<dim3(32, 12), 256, BKV_SMEM>>>(Wk, bk, Wv, bv);
    kvreduce_kernel<<<12, 256>>>();
    cfold_kernel<<<3, 256>>>(Wo);
    wprep_kernel<<<dim3(2, 6), 256>>>(Wq, W1, W2);
    for (int l = 0; l < 3; ++l) {
        layer_mma<<<LAY_GRID, 256, LAY_SMEM>>>(0, l, bq + l * 128, bo + l * 128);
        layer_mma<<<LAY_GRID, 256, LAY_SMEM>>>(1, l, b1 + l * 128, b2 + l * 128);
    }
    final_kernel<<<4096, 256, FIN_SMEM>>>(pw1, pb1, pw2, pb2, out);
}

// round 14
// speedup vs baseline: 2.0568x; 1.0045x over previous
#include <cuda_runtime.h>
#include <cuda_bf16.h>
#include <cstdint>

#define NQ 262144
#define MB 4096
#define PI_F 3.14159265358979323846f

extern __shared__ char smem_raw[];

// ------------------------- device scratch (no allocs) -----------------------
__device__ __align__(16) float g_h[(size_t)NQ * 128];
__device__ __align__(16) float g_x[(size_t)NQ * 128];
__device__ __align__(16) float g_benc[MB * 128];
__device__ __align__(16) float g_kvp[12 * 32 * 1024];
__device__ __align__(16) float g_ksp[12 * 32 * 32];
__device__ __align__(16) float g_kv[12 * 1024];
__device__ __align__(16) float g_ksum[384];
__device__ __align__(16) float g_C[3 * 16384];
// pre-split weights: [inv=l*2+mode][tile=B1h,B1l,B2h,B2l][n*128+k] bf16
__device__ __align__(16) __nv_bfloat16 g_ws[6 * 4 * 16384];

__device__ __forceinline__ float geluf(float u) {
    return 0.5f * u * (1.0f + erff(u * 0.70710678118654752f));
}

__device__ __forceinline__ void cp_async16(void* dst_smem, const void* src) {
    uint32_t d = (uint32_t)__cvta_generic_to_shared(dst_smem);
    asm volatile("cp.async.cg.shared.global [%0], [%1], 16;" :: "r"(d), "l"(src));
}
__device__ __forceinline__ void cp_async_commit() {
    asm volatile("cp.async.commit_group;");
}
__device__ __forceinline__ void cp_async_wait_all() {
    asm volatile("cp.async.wait_group 0;");
}

// split fp32 pair into bf16-hi pair and bf16-lo pair (packed uint32 each)
__device__ __forceinline__ void cvt_pair(float a, float b, uint32_t& hi, uint32_t& lo) {
    __nv_bfloat16 ah = __float2bfloat16_rn(a), bh = __float2bfloat16_rn(b);
    float ar = a - __bfloat162float(ah), br = b - __bfloat162float(bh);
    __nv_bfloat16 al = __float2bfloat16_rn(ar), bl = __float2bfloat16_rn(br);
    hi = (uint32_t)__bfloat16_as_ushort(ah) | ((uint32_t)__bfloat16_as_ushort(bh) << 16);
    lo = (uint32_t)__bfloat16_as_ushort(al) | ((uint32_t)__bfloat16_as_ushort(bl) << 16);
}

__device__ __forceinline__ void mma16816(float* d, const uint32_t* a,
                                         uint32_t b0, uint32_t b1) {
    asm volatile(
        "mma.sync.aligned.m16n8k16.row.col.f32.bf16.bf16.f32 "
        "{%0,%1,%2,%3}, {%4,%5,%6,%7}, {%8,%9}, {%0,%1,%2,%3};"
        : "+f"(d[0]), "+f"(d[1]), "+f"(d[2]), "+f"(d[3])
        : "r"(a[0]), "r"(a[1]), "r"(a[2]), "r"(a[3]), "r"(b0), "r"(b1));
}

// ---------------------------------------------------------------------------
// Positional encoder (fp32): dst[p][:] = sin(mfe(pts[p]) @ W + b). 64 pts/CTA.
// ---------------------------------------------------------------------------
__global__ void __launch_bounds__(256) encode_kernel(
    const float* __restrict__ pts, const float* __restrict__ w,
    const float* __restrict__ b, int which)
{
    __shared__ float sW[3840];
    __shared__ float sB[128];
    __shared__ float sF[64 * 32];
    int t = threadIdx.x;
    for (int i = t; i < 960; i += 256) ((float4*)sW)[i] = ((const float4*)w)[i];
    if (t < 128) sB[t] = b[t];
    size_t pt0 = (size_t)blockIdx.x * 64;
    if (t < 64) {
        float2 xy = ((const float2*)pts)[pt0 + t];
        float* F = sF + t * 32;
        #pragma unroll
        for (int c = 0; c < 2; ++c) {
            float v = c ? xy.y : xy.x;
            float a15 = v - 1.5f, a45 = v - 4.5f, pv = PI_F * v;
            F[0 + c] = v;           F[2 + c] = v * v;
            F[4 + c] = a15 * a15;   F[6 + c] = a45 * a45;
            F[8 + c]  = 1.f / (1.f + expf(-v));
            F[10 + c] = 1.f / (1.f + expf(-a15));
            F[12 + c] = 1.f / (1.f + expf(-a45));
            F[14 + c] = a15;        F[16 + c] = a45;
            F[18 + c] = sinf(pv);          F[20 + c] = cosf(pv);
            F[22 + c] = sinf(pv * 0.25f);  F[24 + c] = cosf(pv * 0.25f);
            F[26 + c] = sinf(pv * 0.5f);   F[28 + c] = cosf(pv * 0.5f);
        }
    }
    __syncthreads();
    int wid = t >> 5, lane = t & 31;
    int m0 = wid * 8, jc = lane * 4;
    float acc[8][4];
    #pragma unroll
    for (int i = 0; i < 8; ++i) { acc[i][0]=acc[i][1]=acc[i][2]=acc[i][3]=0.f; }
    #pragma unroll 2
    for (int k = 0; k < 30; ++k) {
        float4 b4 = *(const float4*)(sW + k * 128 + jc);
        #pragma unroll
        for (int i = 0; i < 8; ++i) {
            float a = sF[(m0 + i) * 32 + k];
            acc[i][0] = fmaf(a, b4.x, acc[i][0]);
            acc[i][1] = fmaf(a, b4.y, acc[i][1]);
            acc[i][2] = fmaf(a, b4.z, acc[i][2]);
            acc[i][3] = fmaf(a, b4.w, acc[i][3]);
        }
    }
    float b0 = sB[jc], b1 = sB[jc+1], b2 = sB[jc+2], b3 = sB[jc+3];
    float* dst = which ? g_benc : g_h;
    #pragma unroll
    for (int i = 0; i < 8; ++i) {
        float4 o;
        o.x = sinf(acc[i][0] + b0); o.y = sinf(acc[i][1] + b1);
        o.z = sinf(acc[i][2] + b2); o.w = sinf(acc[i][3] + b3);
        *(float4*)(dst + (pt0 + m0 + i) * 128 + jc) = o;
    }
}

// ---------------------------------------------------------------------------
// Boundary kv (fp32, tiny): per (tile, lh) partial kv / ksum.
// ---------------------------------------------------------------------------
#define BKV_SMEM (34372 * 4)
__global__ void __launch_bounds__(256) bkv_kernel(
    const float* __restrict__ Wk_g, const float* __restrict__ bk_g,
    const float* __restrict__ Wv_g, const float* __restrict__ bv_g)
{
    float* sm = (float*)smem_raw;
    float* sE  = sm;
    float* sWk = sE + 16896;
    float* sWv = sWk + 4100;
    float* sKh = sWv + 4096;
    float* sVh = sKh + 4608;
    float* sbk = sVh + 4608;
    float* sbv = sbk + 32;
    int t = threadIdx.x;
    int tile = blockIdx.x, lh = blockIdx.y;
    {
        const float4* src = (const float4*)(g_benc + (size_t)tile * 128 * 128);
        for (int i = t; i < 4096; i += 256) {
            int r = i >> 5, c = i & 31;
            *(float4*)(sE + r * 132 + c * 4) = src[i];
        }
    }
    for (int i = t; i < 1024; i += 256) {
        ((float4*)sWk)[i] = ((const float4*)(Wk_g + (size_t)lh * 4096))[i];
        ((float4*)sWv)[i] = ((const float4*)(Wv_g + (size_t)lh * 4096))[i];
    }
    if (t < 32) { sbk[t] = bk_g[lh * 32 + t]; sbv[t] = bv_g[lh * 32 + t]; }
    __syncthreads();
    {
        int m = t >> 1, kind = t & 1;
        const float* W  = kind ? sWv : sWk;
        const float* sb = kind ? sbv : sbk;
        float4 acc[8];
        #pragma unroll
        for (int g = 0; g < 8; ++g) acc[g] = make_float4(0.f, 0.f, 0.f, 0.f);
        for (int d = 0; d < 128; ++d) {
            float v = sE[m * 132 + d];
            #pragma unroll
            for (int g = 0; g < 8; ++g) {
                float4 w4 = *(const float4*)(W + d * 32 + g * 4);
                acc[g].x = fmaf(v, w4.x, acc[g].x);
                acc[g].y = fmaf(v, w4.y, acc[g].y);
                acc[g].z = fmaf(v, w4.z, acc[g].z);
                acc[g].w = fmaf(v, w4.w, acc[g].w);
            }
        }
        float* dst = (kind ? sVh : sKh) + m * 36;
        #pragma unroll
        for (int g = 0; g < 8; ++g) {
            float4 a = acc[g];
            a.x += sb[g*4+0]; a.y += sb[g*4+1]; a.z += sb[g*4+2]; a.w += sb[g*4+3];
            if (!kind) { a.x *= a.x; a.y *= a.y; a.z *= a.z; a.w *= a.w; }
            *(float4*)(dst + g * 4) = a;
        }
    }
    __syncthreads();
    {
        int e = t >> 3, c4 = (t & 7) * 4;
        float4 acc = make_float4(0.f, 0.f, 0.f, 0.f);
        for (int m = 0; m < 128; ++m) {
            float kh = sKh[m * 36 + e];
            float4 v4 = *(const float4*)(sVh + m * 36 + c4);
            acc.x = fmaf(kh, v4.x, acc.x); acc.y = fmaf(kh, v4.y, acc.y);
            acc.z = fmaf(kh, v4.z, acc.z); acc.w = fmaf(kh, v4.w, acc.w);
        }
        *(float4*)(g_kvp + ((size_t)lh * 32 + tile) * 1024 + e * 32 + c4) = acc;
        if (t < 32) {
            float s = 0.f;
            for (int m = 0; m < 128; ++m) s += sKh[m * 36 + t];
            g_ksp[((size_t)lh * 32 + tile) * 32 + t] = s;
        }
    }
}

__global__ void __launch_bounds__(256) kvreduce_kernel()
{
    int lh = blockIdx.x, t = threadIdx.x;
    for (int idx = t; idx < 1024; idx += 256) {
        float s = 0.f;
        for (int tile = 0; tile < 32; ++tile)
            s += g_kvp[((size_t)lh * 32 + tile) * 1024 + idx];
        g_kv[lh * 1024 + idx] = s;
    }
    if (t < 32) {
        float s = 0.f;
        for (int tile = 0; tile < 32; ++tile)
            s += g_ksp[((size_t)lh * 32 + tile) * 32 + t];
        g_ksum[lh * 32 + t] = s;
    }
}

__global__ void __launch_bounds__(256) cfold_kernel(const float* __restrict__ Wo_g)
{
    int l = blockIdx.x, t = threadIdx.x;
    int j = t >> 1, oc = (t & 1) * 64;
    int h = j >> 5, e = j & 31;
    float acc[64];
    #pragma unroll
    for (int o = 0; o < 64; ++o) acc[o] = 0.f;
    for (int ep = 0; ep < 32; ++ep) {
        float kv = g_kv[(l * 4 + h) * 1024 + e * 32 + ep];
        const float4* wr = (const float4*)(Wo_g + ((size_t)(l * 128 + h * 32 + ep)) * 128 + oc);
        #pragma unroll
        for (int g = 0; g < 16; ++g) {
            float4 w4 = __ldg(wr + g);
            acc[g*4+0] = fmaf(kv, w4.x, acc[g*4+0]);
            acc[g*4+1] = fmaf(kv, w4.y, acc[g*4+1]);
            acc[g*4+2] = fmaf(kv, w4.z, acc[g*4+2]);
            acc[g*4+3] = fmaf(kv, w4.w, acc[g*4+3]);
        }
    }
    float4* dst = (float4*)(g_C + (size_t)l * 16384 + j * 128 + oc);
    #pragma unroll
    for (int g = 0; g < 16; ++g)
        dst[g] = make_float4(acc[g*4], acc[g*4+1], acc[g*4+2], acc[g*4+3]);
}

// ---------------------------------------------------------------------------
// wprep: pre-split weights to bf16 hi/lo, transposed to [n][k]. grid (2, 6).
// ---------------------------------------------------------------------------
__global__ void __launch_bounds__(256) wprep_kernel(
    const float* __restrict__ Wq, const float* __restrict__ W1,
    const float* __restrict__ W2)
{
    int b = blockIdx.x, inv = blockIdx.y;
    int l = inv >> 1, mode = inv & 1;
    __nv_bfloat16* dh = g_ws + ((size_t)(inv * 4 + b * 2)) * 16384;
    __nv_bfloat16* dl = dh + 16384;
    for (int i = threadIdx.x; i < 16384; i += 256) {
        int n = i >> 7, k = i & 127;
        float v;
        if (b == 0)
            v = mode ? W1[(size_t)l * 16384 + k * 128 + n]
                     : Wq[(size_t)l * 16384 + (n >> 5) * 4096 + k * 32 + (n & 31)];
        else
            v = mode ? W2[(size_t)l * 16384 + k * 128 + n]
                     : g_C[(size_t)l * 16384 + k * 128 + n];
        __nv_bfloat16 hi = __float2bfloat16_rn(v);
        __nv_bfloat16 lo = __float2bfloat16_rn(v - __bfloat162float(hi));
        dh[i] = hi; dl[i] = lo;
    }
}

// ---------------------------------------------------------------------------
// Persistent layer kernel: mma.sync m16n8k16 bf16x3, two chained GEMMs.
// Fragment-reuse: per k-step, A/B hi+lo fragments are loaded from smem ONCE
// and all 3 compensation passes issue from registers (48 LDS -> 48 MMA).
// ---------------------------------------------------------------------------
#define TS 272                       // smem row stride in bytes
#define TILE_B (128 * TS)            // 34816
#define LAY_SMEM (6 * TILE_B + 1536) // 210432
#define NTILES 2048
#define LAY_GRID 148

__device__ __forceinline__ void do_gemm(
    float d[2][8][4], const char* Ahi, const char* Alo,
    const char* Bhi, const char* Blo, int rowbase, int colbase, int g, int tg)
{
    #pragma unroll
    for (int ks = 0; ks < 8; ++ks) {
        int kb = ks * 32 + tg * 4;
        uint32_t ah[2][4], al[2][4];
        #pragma unroll
        for (int mt = 0; mt < 2; ++mt) {
            const char* aph = Ahi + (rowbase + mt * 16 + g) * TS + kb;
            const char* apl = Alo + (rowbase + mt * 16 + g) * TS + kb;
            ah[mt][0] = *(const uint32_t*)(aph);
            ah[mt][1] = *(const uint32_t*)(aph + 8 * TS);
            ah[mt][2] = *(const uint32_t*)(aph + 16);
            ah[mt][3] = *(const uint32_t*)(aph + 8 * TS + 16);
            al[mt][0] = *(const uint32_t*)(apl);
            al[mt][1] = *(const uint32_t*)(apl + 8 * TS);
            al[mt][2] = *(const uint32_t*)(apl + 16);
            al[mt][3] = *(const uint32_t*)(apl + 8 * TS + 16);
        }
        uint32_t bh[8][2], bl[8][2];
        #pragma unroll
        for (int nt = 0; nt < 8; ++nt) {
            const char* bph = Bhi + (colbase + nt * 8 + g) * TS + kb;
            const char* bpl = Blo + (colbase + nt * 8 + g) * TS + kb;
            bh[nt][0] = *(const uint32_t*)(bph);
            bh[nt][1] = *(const uint32_t*)(bph + 16);
            bl[nt][0] = *(const uint32_t*)(bpl);
            bl[nt][1] = *(const uint32_t*)(bpl + 16);
        }
        // pass 1: Ahi x Bhi
        #pragma unroll
        for (int nt = 0; nt < 8; ++nt) {
            mma16816(d[0][nt], ah[0], bh[nt][0], bh[nt][1]);
            mma16816(d[1][nt], ah[1], bh[nt][0], bh[nt][1]);
        }
        // pass 2: Ahi x Blo
        #pragma unroll
        for (int nt = 0; nt < 8; ++nt) {
            mma16816(d[0][nt], ah[0], bl[nt][0], bl[nt][1]);
            mma16816(d[1][nt], ah[1], bl[nt][0], bl[nt][1]);
        }
        // pass 3: Alo x Bhi
        #pragma unroll
        for (int nt = 0; nt < 8; ++nt) {
            mma16816(d[0][nt], al[0], bh[nt][0], bh[nt][1]);
            mma16816(d[1][nt], al[1], bh[nt][0], bh[nt][1]);
        }
    }
}

__global__ void __launch_bounds__(256) layer_mma(
    int mode, int l, const float* __restrict__ b1p, const float* __restrict__ b2p)
{
    char* sm = smem_raw;
    char* sAhi = sm;
    char* sAlo = sm + TILE_B;
    char* sB1h = sm + 2 * TILE_B;
    char* sB1l = sm + 3 * TILE_B;
    char* sB2h = sm + 4 * TILE_B;
    char* sB2l = sm + 5 * TILE_B;
    float* fB1 = (float*)(sm + 6 * TILE_B);
    float* fB2 = fB1 + 128;
    float* fKs = fB2 + 128;

    int t = threadIdx.x, wid = t >> 5, lane = t & 31;
    int g = lane >> 2, tg = lane & 3;
    const float* ain  = mode ? (const float*)g_x : (const float*)g_h;
    float*       aout = mode ? (float*)g_h : (float*)g_x;
    int rowbase = (wid & 3) * 32, colbase = (wid >> 2) * 64;

    // ---- stage all 4 B tiles once per CTA (cp.async, stride TS) ----
    {
        const __nv_bfloat16* ws = g_ws + (size_t)(l * 2 + mode) * 4 * 16384;
        #pragma unroll
        for (int tile4 = 0; tile4 < 4; ++tile4) {
            char* dst = sB1h + tile4 * TILE_B;
            const __nv_bfloat16* src = ws + tile4 * 16384;
            #pragma unroll 2
            for (int it = 0; it < 8; ++it) {
                int idx = t + it * 256;
                int n = idx >> 4, c = idx & 15;
                cp_async16(dst + n * TS + c * 16, src + n * 128 + c * 8);
            }
        }
        cp_async_commit();
    }
    if (t < 128) {
        fB1[t] = b1p[t];
        fB2[t] = b2p[t];
        fKs[t] = (mode == 0) ? g_ksum[l * 128 + t] : 0.f;
    }
    bool first = true;

    for (int tile = blockIdx.x; tile < NTILES; tile += LAY_GRID) {
        size_t pt0 = (size_t)tile * 128;

        if (!first) __syncthreads();   // prior GEMM2 reads of sA done

        // ---- stage A (fp32 -> bf16 hi/lo, row-major stride TS) ----
        {
            const float* src = ain + pt0 * 128;
            #pragma unroll 4
            for (int it = 0; it < 16; ++it) {
                int i4 = t + it * 256;
                int row = i4 >> 5, c4 = (i4 & 31) * 4;
                float4 v = *(const float4*)(src + row * 128 + c4);
                uint32_t h0, l0, h1, l1;
                cvt_pair(v.x, v.y, h0, l0);
                cvt_pair(v.z, v.w, h1, l1);
                *(unsigned long long*)(sAhi + row * TS + c4 * 2) =
                    ((unsigned long long)h1 << 32) | h0;
                *(unsigned long long*)(sAlo + row * TS + c4 * 2) =
                    ((unsigned long long)l1 << 32) | l0;
            }
        }
        if (first) { cp_async_wait_all(); first = false; }
        __syncthreads();

        // ---- GEMM 1 ----
        float d[2][8][4];
        #pragma unroll
        for (int mt = 0; mt < 2; ++mt)
            #pragma unroll
            for (int nt = 0; nt < 8; ++nt)
                { d[mt][nt][0]=0.f; d[mt][nt][1]=0.f; d[mt][nt][2]=0.f; d[mt][nt][3]=0.f; }
        do_gemm(d, sAhi, sAlo, sB1h, sB1l, rowbase, colbase, g, tg);

        // ---- epilogue 1 ----
        if (mode == 0) {
            float s[2][2][2];   // [mt][j(row)][head]
            #pragma unroll
            for (int mt = 0; mt < 2; ++mt)
                { s[mt][0][0]=0.f; s[mt][0][1]=0.f; s[mt][1][0]=0.f; s[mt][1][1]=0.f; }
            #pragma unroll
            for (int nt = 0; nt < 8; ++nt) {
                int c = colbase + nt * 8 + tg * 2;
                float2 bb = *(const float2*)(fB1 + c);
                float2 kk = *(const float2*)(fKs + c);
                int hh = nt >> 2;
                #pragma unroll
                for (int mt = 0; mt < 2; ++mt) {
                    float u0 = d[mt][nt][0] + bb.x; u0 *= u0; d[mt][nt][0] = u0;
                    float u1 = d[mt][nt][1] + bb.y; u1 *= u1; d[mt][nt][1] = u1;
                    float u2 = d[mt][nt][2] + bb.x; u2 *= u2; d[mt][nt][2] = u2;
                    float u3 = d[mt][nt][3] + bb.y; u3 *= u3; d[mt][nt][3] = u3;
                    s[mt][0][hh] = fmaf(u0, kk.x, fmaf(u1, kk.y, s[mt][0][hh]));
                    s[mt][1][hh] = fmaf(u2, kk.x, fmaf(u3, kk.y, s[mt][1][hh]));
                }
            }
            float z[2][2][2];
            #pragma unroll
            for (int mt = 0; mt < 2; ++mt)
                #pragma unroll
                for (int j = 0; j < 2; ++j)
                    #pragma unroll
                    for (int hh = 0; hh < 2; ++hh) {
                        float v = s[mt][j][hh];
                        v += __shfl_xor_sync(0xffffffffu, v, 1);
                        v += __shfl_xor_sync(0xffffffffu, v, 2);
                        z[mt][j][hh] = 1.0f / (v + 1e-6f);
                    }
            #pragma unroll
            for (int nt = 0; nt < 8; ++nt) {
                int hh = nt >> 2;
                #pragma unroll
                for (int mt = 0; mt < 2; ++mt) {
                    d[mt][nt][0] *= z[mt][0][hh];
                    d[mt][nt][1] *= z[mt][0][hh];
                    d[mt][nt][2] *= z[mt][1][hh];
                    d[mt][nt][3] *= z[mt][1][hh];
                }
            }
        } else {
            #pragma unroll
            for (int nt = 0; nt < 8; ++nt) {
                int c = colbase + nt * 8 + tg * 2;
                float2 bb = *(const float2*)(fB1 + c);
                #pragma unroll
                for (int mt = 0; mt < 2; ++mt) {
                    d[mt][nt][0] = geluf(d[mt][nt][0] + bb.x);
                    d[mt][nt][1] = geluf(d[mt][nt][1] + bb.y);
                    d[mt][nt][2] = geluf(d[mt][nt][2] + bb.x);
                    d[mt][nt][3] = geluf(d[mt][nt][3] + bb.y);
                }
            }
        }
        __syncthreads();   // all warps done reading A before overwrite

        // ---- write A' (hi/lo) back to smem ----
        #pragma unroll
        for (int mt = 0; mt < 2; ++mt) {
            #pragma unroll
            for (int j = 0; j < 2; ++j) {
                int row = rowbase + mt * 16 + g + j * 8;
                #pragma unroll
                for (int nt = 0; nt < 8; ++nt) {
                    int cb = (colbase + nt * 8 + tg * 2) * 2;
                    uint32_t hi, lo;
                    cvt_pair(d[mt][nt][2 * j], d[mt][nt][2 * j + 1], hi, lo);
                    *(uint32_t*)(sAhi + row * TS + cb) = hi;
                    *(uint32_t*)(sAlo + row * TS + cb) = lo;
                }
            }
        }
        __syncthreads();

        // ---- GEMM 2 ----
        #pragma unroll
        for (int mt = 0; mt < 2; ++mt)
            #pragma unroll
            for (int nt = 0; nt < 8; ++nt)
                { d[mt][nt][0]=0.f; d[mt][nt][1]=0.f; d[mt][nt][2]=0.f; d[mt][nt][3]=0.f; }
        do_gemm(d, sAhi, sAlo, sB2h, sB2l, rowbase, colbase, g, tg);

        // ---- epilogue 2: out = residual + D + bias2 ----
        #pragma unroll
        for (int mt = 0; mt < 2; ++mt) {
            #pragma unroll
            for (int j = 0; j < 2; ++j) {
                int row = rowbase + mt * 16 + g + j * 8;
                const float* res = ain + (pt0 + row) * 128;
                float* dst = aout + (pt0 + row) * 128;
                #pragma unroll
                for (int nt = 0; nt < 8; ++nt) {
                    int c = colbase + nt * 8 + tg * 2;
                    float2 rv = *(const float2*)(res + c);
                    float2 bb = *(const float2*)(fB2 + c);
                    float2 o;
                    o.x = rv.x + d[mt][nt][2 * j]     + bb.x;
                    o.y = rv.y + d[mt][nt][2 * j + 1] + bb.y;
                    *(float2*)(dst + c) = o;
                }
            }
        }
    }
}

// ---------------------------------------------------------------------------
// Final projector (fp32): out = gelu(h @ pw1 + pb1) @ pw2 + pb2
// ---------------------------------------------------------------------------
#define FIN_SMEM (20812 * 4)
__global__ void __launch_bounds__(256) final_kernel(
    const float* __restrict__ pw1, const float* __restrict__ pb1,
    const float* __restrict__ pw2, const float* __restrict__ pb2,
    float* __restrict__ out)
{
    float* sm = (float*)smem_raw;
    float* sH   = sm;
    float* sW1  = sH + 8192;
    float* sT   = sW1 + 8192;
    float* spw2 = sT + 4160;
    float* spb1 = spw2 + 192;
    float* spb2 = spb1 + 64;
    int t = threadIdx.x;
    size_t pt0 = (size_t)blockIdx.x * 64;
    {
        const float4* src = (const float4*)(g_h + pt0 * 128);
        for (int i = t; i < 2048; i += 256) ((float4*)sH)[i] = src[i];
    }
    for (int i = t; i < 2048; i += 256) ((float4*)sW1)[i] = ((const float4*)pw1)[i];
    if (t < 192) spw2[t] = pw2[t];
    if (t < 64)  spb1[t] = pb1[t];
    if (t < 3)   spb2[t] = pb2[t];
    __syncthreads();
    int wid = t >> 5, lane = t & 31;
    int m0 = wid * 8, jc = lane * 2;
    float acc[8][2];
    #pragma unroll
    for (int i = 0; i < 8; ++i) { acc[i][0] = acc[i][1] = 0.f; }
    #pragma unroll 2
    for (int k = 0; k < 128; ++k) {
        float2 b2v = *(const float2*)(sW1 + k * 64 + jc);
        #pragma unroll
        for (int i = 0; i < 8; ++i) {
            float a = sH[(m0 + i) * 128 + k];
            acc[i][0] = fmaf(a, b2v.x, acc[i][0]);
            acc[i][1] = fmaf(a, b2v.y, acc[i][1]);
        }
    }
    float c0 = spb1[jc], c1 = spb1[jc + 1];
    #pragma unroll
    for (int i = 0; i < 8; ++i) {
        sT[(m0 + i) * 65 + jc]     = geluf(acc[i][0] + c0);
        sT[(m0 + i) * 65 + jc + 1] = geluf(acc[i][1] + c1);
    }
    __syncthreads();
    if (t < 192) {
        int n = t / 3, c = t - n * 3;
        float s = spb2[c];
        #pragma unroll 4
        for (int k = 0; k < 64; ++k) s = fmaf(sT[n * 65 + k], spw2[k * 3 + c], s);
        out[(pt0 + n) * 3 + c] = s;
    }
}

// ---------------------------------------------------------------------------
extern "C" void kernel_launch(void* const* d_in, const int* in_sizes, int n_in,
                              void* d_out, int out_size)
{
    const float* qp    = (const float*)d_in[0];
    const float* bp    = (const float*)d_in[1];
    const float* pe_w  = (const float*)d_in[2];
    const float* pe_b  = (const float*)d_in[3];
    const float* bpe_w = (const float*)d_in[4];
    const float* bpe_b = (const float*)d_in[5];
    const float* Wq    = (const float*)d_in[6];
    const float* bq    = (const float*)d_in[7];
    const float* Wk    = (const float*)d_in[8];
    const float* bk    = (const float*)d_in[9];
    const float* Wv    = (const float*)d_in[10];
    const float* bv    = (const float*)d_in[11];
    const float* Wo    = (const float*)d_in[12];
    const float* bo    = (const float*)d_in[13];
    const float* W1    = (const float*)d_in[14];
    const float* b1    = (const float*)d_in[15];
    const float* W2    = (const float*)d_in[16];
    const float* b2    = (const float*)d_in[17];
    const float* pw1   = (const float*)d_in[18];
    const float* pb1   = (const float*)d_in[19];
    const float* pw2   = (const float*)d_in[20];
    const float* pb2   = (const float*)d_in[21];
    float* out = (float*)d_out;

    cudaFuncSetAttribute(bkv_kernel,   cudaFuncAttributeMaxDynamicSharedMemorySize, BKV_SMEM);
    cudaFuncSetAttribute(layer_mma,    cudaFuncAttributeMaxDynamicSharedMemorySize, LAY_SMEM);
    cudaFuncSetAttribute(final_kernel, cudaFuncAttributeMaxDynamicSharedMemorySize, FIN_SMEM);

    encode_kernel<<<64,   256>>>(bp, bpe_w, bpe_b, 1);
    encode_kernel<<<4096, 256>>>(qp, pe_w,  pe_b,  0);
    bkv_kernel<<<dim3(32, 12), 256, BKV_SMEM>>>(Wk, bk, Wv, bv);
    kvreduce_kernel<<<12, 256>>>();
    cfold_kernel<<<3, 256>>>(Wo);
    wprep_kernel<<<dim3(2, 6), 256>>>(Wq, W1, W2);
    for (int l = 0; l < 3; ++l) {
        layer_mma<<<LAY_GRID, 256, LAY_SMEM>>>(0, l, bq + l * 128, bo + l * 128);
        layer_mma<<<LAY_GRID, 256, LAY_SMEM>>>(1, l, b1 + l * 128, b2 + l * 128);
    }
    final_kernel<<<4096, 256, FIN_SMEM>>>(pw1, pb1, pw2, pb2, out);
}

// round 15
// speedup vs baseline: 2.4157x; 1.1745x over previous
#include <cuda_runtime.h>
#include <cuda_fp16.h>
#include <cstdint>

#define NQ 262144
#define MB 4096
#define PI_F 3.14159265358979323846f

extern __shared__ char smem_raw[];

// ------------------------- device scratch (no allocs) -----------------------
__device__ __align__(16) float g_h[(size_t)NQ * 128];
__device__ __align__(16) float g_x[(size_t)NQ * 128];
__device__ __align__(16) float g_benc[MB * 128];
__device__ __align__(16) float g_kvp[12 * 32 * 1024];
__device__ __align__(16) float g_ksp[12 * 32 * 32];
__device__ __align__(16) float g_kv[12 * 1024];
__device__ __align__(16) float g_ksum[384];
__device__ __align__(16) float g_C[3 * 16384];
// pre-split weights: [inv=l*2+mode][tile=B1h,B1l,B2h,B2l][n*128+k] fp16
__device__ __align__(16) __half g_ws[6 * 4 * 16384];

__device__ __forceinline__ float geluf(float u) {
    return 0.5f * u * (1.0f + erff(u * 0.70710678118654752f));
}

__device__ __forceinline__ void cp_async16(void* dst_smem, const void* src) {
    uint32_t d = (uint32_t)__cvta_generic_to_shared(dst_smem);
    asm volatile("cp.async.cg.shared.global [%0], [%1], 16;" :: "r"(d), "l"(src));
}
__device__ __forceinline__ void cp_async_commit() {
    asm volatile("cp.async.commit_group;");
}
__device__ __forceinline__ void cp_async_wait_all() {
    asm volatile("cp.async.wait_group 0;");
}

// pack two fp32 into one fp16x2 register (x -> low half, y -> high half)
__device__ __forceinline__ uint32_t pack_h2(float x, float y) {
    __half2 h = __float22half2_rn(make_float2(x, y));
    uint32_t u;
    memcpy(&u, &h, 4);
    return u;
}

__device__ __forceinline__ void mma16816(float* d, const uint32_t* a,
                                         uint32_t b0, uint32_t b1) {
    asm volatile(
        "mma.sync.aligned.m16n8k16.row.col.f32.f16.f16.f32 "
        "{%0,%1,%2,%3}, {%4,%5,%6,%7}, {%8,%9}, {%0,%1,%2,%3};"
        : "+f"(d[0]), "+f"(d[1]), "+f"(d[2]), "+f"(d[3])
        : "r"(a[0]), "r"(a[1]), "r"(a[2]), "r"(a[3]), "r"(b0), "r"(b1));
}

// ---------------------------------------------------------------------------
// Positional encoder (fp32): dst[p][:] = sin(mfe(pts[p]) @ W + b). 64 pts/CTA.
// ---------------------------------------------------------------------------
__global__ void __launch_bounds__(256) encode_kernel(
    const float* __restrict__ pts, const float* __restrict__ w,
    const float* __restrict__ b, int which)
{
    __shared__ float sW[3840];
    __shared__ float sB[128];
    __shared__ float sF[64 * 32];
    int t = threadIdx.x;
    for (int i = t; i < 960; i += 256) ((float4*)sW)[i] = ((const float4*)w)[i];
    if (t < 128) sB[t] = b[t];
    size_t pt0 = (size_t)blockIdx.x * 64;
    if (t < 64) {
        float2 xy = ((const float2*)pts)[pt0 + t];
        float* F = sF + t * 32;
        #pragma unroll
        for (int c = 0; c < 2; ++c) {
            float v = c ? xy.y : xy.x;
            float a15 = v - 1.5f, a45 = v - 4.5f, pv = PI_F * v;
            F[0 + c] = v;           F[2 + c] = v * v;
            F[4 + c] = a15 * a15;   F[6 + c] = a45 * a45;
            F[8 + c]  = 1.f / (1.f + expf(-v));
            F[10 + c] = 1.f / (1.f + expf(-a15));
            F[12 + c] = 1.f / (1.f + expf(-a45));
            F[14 + c] = a15;        F[16 + c] = a45;
            F[18 + c] = sinf(pv);          F[20 + c] = cosf(pv);
            F[22 + c] = sinf(pv * 0.25f);  F[24 + c] = cosf(pv * 0.25f);
            F[26 + c] = sinf(pv * 0.5f);   F[28 + c] = cosf(pv * 0.5f);
        }
    }
    __syncthreads();
    int wid = t >> 5, lane = t & 31;
    int m0 = wid * 8, jc = lane * 4;
    float acc[8][4];
    #pragma unroll
    for (int i = 0; i < 8; ++i) { acc[i][0]=acc[i][1]=acc[i][2]=acc[i][3]=0.f; }
    #pragma unroll 2
    for (int k = 0; k < 30; ++k) {
        float4 b4 = *(const float4*)(sW + k * 128 + jc);
        #pragma unroll
        for (int i = 0; i < 8; ++i) {
            float a = sF[(m0 + i) * 32 + k];
            acc[i][0] = fmaf(a, b4.x, acc[i][0]);
            acc[i][1] = fmaf(a, b4.y, acc[i][1]);
            acc[i][2] = fmaf(a, b4.z, acc[i][2]);
            acc[i][3] = fmaf(a, b4.w, acc[i][3]);
        }
    }
    float b0 = sB[jc], b1 = sB[jc+1], b2 = sB[jc+2], b3 = sB[jc+3];
    float* dst = which ? g_benc : g_h;
    #pragma unroll
    for (int i = 0; i < 8; ++i) {
        float4 o;
        o.x = sinf(acc[i][0] + b0); o.y = sinf(acc[i][1] + b1);
        o.z = sinf(acc[i][2] + b2); o.w = sinf(acc[i][3] + b3);
        *(float4*)(dst + (pt0 + m0 + i) * 128 + jc) = o;
    }
}

// ---------------------------------------------------------------------------
// Boundary kv (fp32, tiny): per (tile, lh) partial kv / ksum.
// ---------------------------------------------------------------------------
#define BKV_SMEM (34372 * 4)
__global__ void __launch_bounds__(256) bkv_kernel(
    const float* __restrict__ Wk_g, const float* __restrict__ bk_g,
    const float* __restrict__ Wv_g, const float* __restrict__ bv_g)
{
    float* sm = (float*)smem_raw;
    float* sE  = sm;
    float* sWk = sE + 16896;
    float* sWv = sWk + 4100;
    float* sKh = sWv + 4096;
    float* sVh = sKh + 4608;
    float* sbk = sVh + 4608;
    float* sbv = sbk + 32;
    int t = threadIdx.x;
    int tile = blockIdx.x, lh = blockIdx.y;
    {
        const float4* src = (const float4*)(g_benc + (size_t)tile * 128 * 128);
        for (int i = t; i < 4096; i += 256) {
            int r = i >> 5, c = i & 31;
            *(float4*)(sE + r * 132 + c * 4) = src[i];
        }
    }
    for (int i = t; i < 1024; i += 256) {
        ((float4*)sWk)[i] = ((const float4*)(Wk_g + (size_t)lh * 4096))[i];
        ((float4*)sWv)[i] = ((const float4*)(Wv_g + (size_t)lh * 4096))[i];
    }
    if (t < 32) { sbk[t] = bk_g[lh * 32 + t]; sbv[t] = bv_g[lh * 32 + t]; }
    __syncthreads();
    {
        int m = t >> 1, kind = t & 1;
        const float* W  = kind ? sWv : sWk;
        const float* sb = kind ? sbv : sbk;
        float4 acc[8];
        #pragma unroll
        for (int g = 0; g < 8; ++g) acc[g] = make_float4(0.f, 0.f, 0.f, 0.f);
        for (int d = 0; d < 128; ++d) {
            float v = sE[m * 132 + d];
            #pragma unroll
            for (int g = 0; g < 8; ++g) {
                float4 w4 = *(const float4*)(W + d * 32 + g * 4);
                acc[g].x = fmaf(v, w4.x, acc[g].x);
                acc[g].y = fmaf(v, w4.y, acc[g].y);
                acc[g].z = fmaf(v, w4.z, acc[g].z);
                acc[g].w = fmaf(v, w4.w, acc[g].w);
            }
        }
        float* dst = (kind ? sVh : sKh) + m * 36;
        #pragma unroll
        for (int g = 0; g < 8; ++g) {
            float4 a = acc[g];
            a.x += sb[g*4+0]; a.y += sb[g*4+1]; a.z += sb[g*4+2]; a.w += sb[g*4+3];
            if (!kind) { a.x *= a.x; a.y *= a.y; a.z *= a.z; a.w *= a.w; }
            *(float4*)(dst + g * 4) = a;
        }
    }
    __syncthreads();
    {
        int e = t >> 3, c4 = (t & 7) * 4;
        float4 acc = make_float4(0.f, 0.f, 0.f, 0.f);
        for (int m = 0; m < 128; ++m) {
            float kh = sKh[m * 36 + e];
            float4 v4 = *(const float4*)(sVh + m * 36 + c4);
            acc.x = fmaf(kh, v4.x, acc.x); acc.y = fmaf(kh, v4.y, acc.y);
            acc.z = fmaf(kh, v4.z, acc.z); acc.w = fmaf(kh, v4.w, acc.w);
        }
        *(float4*)(g_kvp + ((size_t)lh * 32 + tile) * 1024 + e * 32 + c4) = acc;
        if (t < 32) {
            float s = 0.f;
            for (int m = 0; m < 128; ++m) s += sKh[m * 36 + t];
            g_ksp[((size_t)lh * 32 + tile) * 32 + t] = s;
        }
    }
}

__global__ void __launch_bounds__(256) kvreduce_kernel()
{
    int lh = blockIdx.x, t = threadIdx.x;
    for (int idx = t; idx < 1024; idx += 256) {
        float s = 0.f;
        for (int tile = 0; tile < 32; ++tile)
            s += g_kvp[((size_t)lh * 32 + tile) * 1024 + idx];
        g_kv[lh * 1024 + idx] = s;
    }
    if (t < 32) {
        float s = 0.f;
        for (int tile = 0; tile < 32; ++tile)
            s += g_ksp[((size_t)lh * 32 + tile) * 32 + t];
        g_ksum[lh * 32 + t] = s;
    }
}

__global__ void __launch_bounds__(256) cfold_kernel(const float* __restrict__ Wo_g)
{
    int l = blockIdx.x, t = threadIdx.x;
    int j = t >> 1, oc = (t & 1) * 64;
    int h = j >> 5, e = j & 31;
    float acc[64];
    #pragma unroll
    for (int o = 0; o < 64; ++o) acc[o] = 0.f;
    for (int ep = 0; ep < 32; ++ep) {
        float kv = g_kv[(l * 4 + h) * 1024 + e * 32 + ep];
        const float4* wr = (const float4*)(Wo_g + ((size_t)(l * 128 + h * 32 + ep)) * 128 + oc);
        #pragma unroll
        for (int g = 0; g < 16; ++g) {
            float4 w4 = __ldg(wr + g);
            acc[g*4+0] = fmaf(kv, w4.x, acc[g*4+0]);
            acc[g*4+1] = fmaf(kv, w4.y, acc[g*4+1]);
            acc[g*4+2] = fmaf(kv, w4.z, acc[g*4+2]);
            acc[g*4+3] = fmaf(kv, w4.w, acc[g*4+3]);
        }
    }
    float4* dst = (float4*)(g_C + (size_t)l * 16384 + j * 128 + oc);
    #pragma unroll
    for (int g = 0; g < 16; ++g)
        dst[g] = make_float4(acc[g*4], acc[g*4+1], acc[g*4+2], acc[g*4+3]);
}

// ---------------------------------------------------------------------------
// wprep: pre-split weights to fp16 hi/lo, transposed to [n][k]. grid (2, 6).
// ---------------------------------------------------------------------------
__global__ void __launch_bounds__(256) wprep_kernel(
    const float* __restrict__ Wq, const float* __restrict__ W1,
    const float* __restrict__ W2)
{
    int b = blockIdx.x, inv = blockIdx.y;
    int l = inv >> 1, mode = inv & 1;
    __half* dh = g_ws + ((size_t)(inv * 4 + b * 2)) * 16384;
    __half* dl = dh + 16384;
    for (int i = threadIdx.x; i < 16384; i += 256) {
        int n = i >> 7, k = i & 127;
        float v;
        if (b == 0)
            v = mode ? W1[(size_t)l * 16384 + k * 128 + n]
                     : Wq[(size_t)l * 16384 + (n >> 5) * 4096 + k * 32 + (n & 31)];
        else
            v = mode ? W2[(size_t)l * 16384 + k * 128 + n]
                     : g_C[(size_t)l * 16384 + k * 128 + n];
        __half hi = __float2half_rn(v);
        __half lo = __float2half_rn(v - __half2float(hi));
        dh[i] = hi; dl[i] = lo;
    }
}

// ---------------------------------------------------------------------------
// Persistent layer kernel: mma.sync m16n8k16 fp16 x2 compensated.
// A = fp16(activations) (single tile); B = exact fp16 hi+lo split.
// D = A*Bhi + A*Blo  (2 MMA passes, A-quantization error ~2^-11).
// ---------------------------------------------------------------------------
#define TS 272                       // smem row stride in bytes
#define TILE_B (128 * TS)            // 34816
#define LAY_SMEM (5 * TILE_B + 1536) // 175616
#define NTILES 2048
#define LAY_GRID 148

__device__ __forceinline__ void do_gemm(
    float d[2][8][4], const char* A,
    const char* Bhi, const char* Blo, int rowbase, int colbase, int g, int tg)
{
    #pragma unroll
    for (int ks = 0; ks < 8; ++ks) {
        int kb = ks * 32 + tg * 4;
        uint32_t a[2][4];
        #pragma unroll
        for (int mt = 0; mt < 2; ++mt) {
            const char* ap = A + (rowbase + mt * 16 + g) * TS + kb;
            a[mt][0] = *(const uint32_t*)(ap);
            a[mt][1] = *(const uint32_t*)(ap + 8 * TS);
            a[mt][2] = *(const uint32_t*)(ap + 16);
            a[mt][3] = *(const uint32_t*)(ap + 8 * TS + 16);
        }
        uint32_t bh[8][2], bl[8][2];
        #pragma unroll
        for (int nt = 0; nt < 8; ++nt) {
            const char* bph = Bhi + (colbase + nt * 8 + g) * TS + kb;
            const char* bpl = Blo + (colbase + nt * 8 + g) * TS + kb;
            bh[nt][0] = *(const uint32_t*)(bph);
            bh[nt][1] = *(const uint32_t*)(bph + 16);
            bl[nt][0] = *(const uint32_t*)(bpl);
            bl[nt][1] = *(const uint32_t*)(bpl + 16);
        }
        // pass 1: A x Bhi
        #pragma unroll
        for (int nt = 0; nt < 8; ++nt) {
            mma16816(d[0][nt], a[0], bh[nt][0], bh[nt][1]);
            mma16816(d[1][nt], a[1], bh[nt][0], bh[nt][1]);
        }
        // pass 2: A x Blo
        #pragma unroll
        for (int nt = 0; nt < 8; ++nt) {
            mma16816(d[0][nt], a[0], bl[nt][0], bl[nt][1]);
            mma16816(d[1][nt], a[1], bl[nt][0], bl[nt][1]);
        }
    }
}

__global__ void __launch_bounds__(256) layer_mma(
    int mode, int l, const float* __restrict__ b1p, const float* __restrict__ b2p)
{
    char* sm = smem_raw;
    char* sA   = sm;
    char* sB1h = sm + 1 * TILE_B;
    char* sB1l = sm + 2 * TILE_B;
    char* sB2h = sm + 3 * TILE_B;
    char* sB2l = sm + 4 * TILE_B;
    float* fB1 = (float*)(sm + 5 * TILE_B);
    float* fB2 = fB1 + 128;
    float* fKs = fB2 + 128;

    int t = threadIdx.x, wid = t >> 5, lane = t & 31;
    int g = lane >> 2, tg = lane & 3;
    const float* ain  = mode ? (const float*)g_x : (const float*)g_h;
    float*       aout = mode ? (float*)g_h : (float*)g_x;
    int rowbase = (wid & 3) * 32, colbase = (wid >> 2) * 64;

    // ---- stage all 4 B tiles once per CTA (cp.async, stride TS) ----
    {
        const __half* ws = g_ws + (size_t)(l * 2 + mode) * 4 * 16384;
        #pragma unroll
        for (int tile4 = 0; tile4 < 4; ++tile4) {
            char* dst = sB1h + tile4 * TILE_B;
            const __half* src = ws + tile4 * 16384;
            #pragma unroll 2
            for (int it = 0; it < 8; ++it) {
                int idx = t + it * 256;
                int n = idx >> 4, c = idx & 15;
                cp_async16(dst + n * TS + c * 16, src + n * 128 + c * 8);
            }
        }
        cp_async_commit();
    }
    if (t < 128) {
        fB1[t] = b1p[t];
        fB2[t] = b2p[t];
        fKs[t] = (mode == 0) ? g_ksum[l * 128 + t] : 0.f;
    }
    bool first = true;

    for (int tile = blockIdx.x; tile < NTILES; tile += LAY_GRID) {
        size_t pt0 = (size_t)tile * 128;

        if (!first) __syncthreads();   // prior GEMM2 reads of sA done

        // ---- stage A (fp32 -> fp16, row-major stride TS) ----
        {
            const float* src = ain + pt0 * 128;
            #pragma unroll 4
            for (int it = 0; it < 16; ++it) {
                int i4 = t + it * 256;
                int row = i4 >> 5, c4 = (i4 & 31) * 4;
                float4 v = *(const float4*)(src + row * 128 + c4);
                uint32_t u01 = pack_h2(v.x, v.y);
                uint32_t u23 = pack_h2(v.z, v.w);
                *(unsigned long long*)(sA + row * TS + c4 * 2) =
                    ((unsigned long long)u23 << 32) | u01;
            }
        }
        if (first) { cp_async_wait_all(); first = false; }
        __syncthreads();

        // ---- GEMM 1 ----
        float d[2][8][4];
        #pragma unroll
        for (int mt = 0; mt < 2; ++mt)
            #pragma unroll
            for (int nt = 0; nt < 8; ++nt)
                { d[mt][nt][0]=0.f; d[mt][nt][1]=0.f; d[mt][nt][2]=0.f; d[mt][nt][3]=0.f; }
        do_gemm(d, sA, sB1h, sB1l, rowbase, colbase, g, tg);

        // ---- epilogue 1 ----
        if (mode == 0) {
            float s[2][2][2];   // [mt][j(row)][head]
            #pragma unroll
            for (int mt = 0; mt < 2; ++mt)
                { s[mt][0][0]=0.f; s[mt][0][1]=0.f; s[mt][1][0]=0.f; s[mt][1][1]=0.f; }
            #pragma unroll
            for (int nt = 0; nt < 8; ++nt) {
                int c = colbase + nt * 8 + tg * 2;
                float2 bb = *(const float2*)(fB1 + c);
                float2 kk = *(const float2*)(fKs + c);
                int hh = nt >> 2;
                #pragma unroll
                for (int mt = 0; mt < 2; ++mt) {
                    float u0 = d[mt][nt][0] + bb.x; u0 *= u0; d[mt][nt][0] = u0;
                    float u1 = d[mt][nt][1] + bb.y; u1 *= u1; d[mt][nt][1] = u1;
                    float u2 = d[mt][nt][2] + bb.x; u2 *= u2; d[mt][nt][2] = u2;
                    float u3 = d[mt][nt][3] + bb.y; u3 *= u3; d[mt][nt][3] = u3;
                    s[mt][0][hh] = fmaf(u0, kk.x, fmaf(u1, kk.y, s[mt][0][hh]));
                    s[mt][1][hh] = fmaf(u2, kk.x, fmaf(u3, kk.y, s[mt][1][hh]));
                }
            }
            float z[2][2][2];
            #pragma unroll
            for (int mt = 0; mt < 2; ++mt)
                #pragma unroll
                for (int j = 0; j < 2; ++j)
                    #pragma unroll
                    for (int hh = 0; hh < 2; ++hh) {
                        float v = s[mt][j][hh];
                        v += __shfl_xor_sync(0xffffffffu, v, 1);
                        v += __shfl_xor_sync(0xffffffffu, v, 2);
                        z[mt][j][hh] = 1.0f / (v + 1e-6f);
                    }
            #pragma unroll
            for (int nt = 0; nt < 8; ++nt) {
                int hh = nt >> 2;
                #pragma unroll
                for (int mt = 0; mt < 2; ++mt) {
                    d[mt][nt][0] *= z[mt][0][hh];
                    d[mt][nt][1] *= z[mt][0][hh];
                    d[mt][nt][2] *= z[mt][1][hh];
                    d[mt][nt][3] *= z[mt][1][hh];
                }
            }
        } else {
            #pragma unroll
            for (int nt = 0; nt < 8; ++nt) {
                int c = colbase + nt * 8 + tg * 2;
                float2 bb = *(const float2*)(fB1 + c);
                #pragma unroll
                for (int mt = 0; mt < 2; ++mt) {
                    d[mt][nt][0] = geluf(d[mt][nt][0] + bb.x);
                    d[mt][nt][1] = geluf(d[mt][nt][1] + bb.y);
                    d[mt][nt][2] = geluf(d[mt][nt][2] + bb.x);
                    d[mt][nt][3] = geluf(d[mt][nt][3] + bb.y);
                }
            }
        }
        __syncthreads();   // all warps done reading A before overwrite

        // ---- write A' (fp16) back to smem ----
        #pragma unroll
        for (int mt = 0; mt < 2; ++mt) {
            #pragma unroll
            for (int j = 0; j < 2; ++j) {
                int row = rowbase + mt * 16 + g + j * 8;
                #pragma unroll
                for (int nt = 0; nt < 8; ++nt) {
                    int cb = (colbase + nt * 8 + tg * 2) * 2;
                    *(uint32_t*)(sA + row * TS + cb) =
                        pack_h2(d[mt][nt][2 * j], d[mt][nt][2 * j + 1]);
                }
            }
        }
        __syncthreads();

        // ---- GEMM 2 ----
        #pragma unroll
        for (int mt = 0; mt < 2; ++mt)
            #pragma unroll
            for (int nt = 0; nt < 8; ++nt)
                { d[mt][nt][0]=0.f; d[mt][nt][1]=0.f; d[mt][nt][2]=0.f; d[mt][nt][3]=0.f; }
        do_gemm(d, sA, sB2h, sB2l, rowbase, colbase, g, tg);

        // ---- epilogue 2: out = residual + D + bias2 ----
        #pragma unroll
        for (int mt = 0; mt < 2; ++mt) {
            #pragma unroll
            for (int j = 0; j < 2; ++j) {
                int row = rowbase + mt * 16 + g + j * 8;
                const float* res = ain + (pt0 + row) * 128;
                float* dst = aout + (pt0 + row) * 128;
                #pragma unroll
                for (int nt = 0; nt < 8; ++nt) {
                    int c = colbase + nt * 8 + tg * 2;
                    float2 rv = *(const float2*)(res + c);
                    float2 bb = *(const float2*)(fB2 + c);
                    float2 o;
                    o.x = rv.x + d[mt][nt][2 * j]     + bb.x;
                    o.y = rv.y + d[mt][nt][2 * j + 1] + bb.y;
                    *(float2*)(dst + c) = o;
                }
            }
        }
    }
}

// ---------------------------------------------------------------------------
// Final projector (fp32): out = gelu(h @ pw1 + pb1) @ pw2 + pb2
// ---------------------------------------------------------------------------
#define FIN_SMEM (20812 * 4)
__global__ void __launch_bounds__(256) final_kernel(
    const float* __restrict__ pw1, const float* __restrict__ pb1,
    const float* __restrict__ pw2, const float* __restrict__ pb2,
    float* __restrict__ out)
{
    float* sm = (float*)smem_raw;
    float* sH   = sm;
    float* sW1  = sH + 8192;
    float* sT   = sW1 + 8192;
    float* spw2 = sT + 4160;
    float* spb1 = spw2 + 192;
    float* spb2 = spb1 + 64;
    int t = threadIdx.x;
    size_t pt0 = (size_t)blockIdx.x * 64;
    {
        const float4* src = (const float4*)(g_h + pt0 * 128);
        for (int i = t; i < 2048; i += 256) ((float4*)sH)[i] = src[i];
    }
    for (int i = t; i < 2048; i += 256) ((float4*)sW1)[i] = ((const float4*)pw1)[i];
    if (t < 192) spw2[t] = pw2[t];
    if (t < 64)  spb1[t] = pb1[t];
    if (t < 3)   spb2[t] = pb2[t];
    __syncthreads();
    int wid = t >> 5, lane = t & 31;
    int m0 = wid * 8, jc = lane * 2;
    float acc[8][2];
    #pragma unroll
    for (int i = 0; i < 8; ++i) { acc[i][0] = acc[i][1] = 0.f; }
    #pragma unroll 2
    for (int k = 0; k < 128; ++k) {
        float2 b2v = *(const float2*)(sW1 + k * 64 + jc);
        #pragma unroll
        for (int i = 0; i < 8; ++i) {
            float a = sH[(m0 + i) * 128 + k];
            acc[i][0] = fmaf(a, b2v.x, acc[i][0]);
            acc[i][1] = fmaf(a, b2v.y, acc[i][1]);
        }
    }
    float c0 = spb1[jc], c1 = spb1[jc + 1];
    #pragma unroll
    for (int i = 0; i < 8; ++i) {
        sT[(m0 + i) * 65 + jc]     = geluf(acc[i][0] + c0);
        sT[(m0 + i) * 65 + jc + 1] = geluf(acc[i][1] + c1);
    }
    __syncthreads();
    if (t < 192) {
        int n = t / 3, c = t - n * 3;
        float s = spb2[c];
        #pragma unroll 4
        for (int k = 0; k < 64; ++k) s = fmaf(sT[n * 65 + k], spw2[k * 3 + c], s);
        out[(pt0 + n) * 3 + c] = s;
    }
}

// ---------------------------------------------------------------------------
extern "C" void kernel_launch(void* const* d_in, const int* in_sizes, int n_in,
                              void* d_out, int out_size)
{
    const float* qp    = (const float*)d_in[0];
    const float* bp    = (const float*)d_in[1];
    const float* pe_w  = (const float*)d_in[2];
    const float* pe_b  = (const float*)d_in[3];
    const float* bpe_w = (const float*)d_in[4];
    const float* bpe_b = (const float*)d_in[5];
    const float* Wq    = (const float*)d_in[6];
    const float* bq    = (const float*)d_in[7];
    const float* Wk    = (const float*)d_in[8];
    const float* bk    = (const float*)d_in[9];
    const float* Wv    = (const float*)d_in[10];
    const float* bv    = (const float*)d_in[11];
    const float* Wo    = (const float*)d_in[12];
    const float* bo    = (const float*)d_in[13];
    const float* W1    = (const float*)d_in[14];
    const float* b1    = (const float*)d_in[15];
    const float* W2    = (const float*)d_in[16];
    const float* b2    = (const float*)d_in[17];
    const float* pw1   = (const float*)d_in[18];
    const float* pb1   = (const float*)d_in[19];
    const float* pw2   = (const float*)d_in[20];
    const float* pb2   = (const float*)d_in[21];
    float* out = (float*)d_out;

    cudaFuncSetAttribute(bkv_kernel,   cudaFuncAttributeMaxDynamicSharedMemorySize, BKV_SMEM);
    cudaFuncSetAttribute(layer_mma,    cudaFuncAttributeMaxDynamicSharedMemorySize, LAY_SMEM);
    cudaFuncSetAttribute(final_kernel, cudaFuncAttributeMaxDynamicSharedMemorySize, FIN_SMEM);

    encode_kernel<<<64,   256>>>(bp, bpe_w, bpe_b, 1);
    encode_kernel<<<4096, 256>>>(qp, pe_w,  pe_b,  0);
    bkv_kernel<<<dim3(32, 12), 256, BKV_SMEM>>>(Wk, bk, Wv, bv);
    kvreduce_kernel<<<12, 256>>>();
    cfold_kernel<<<3, 256>>>(Wo);
    wprep_kernel<<<dim3(2, 6), 256>>>(Wq, W1, W2);
    for (int l = 0; l < 3; ++l) {
        layer_mma<<<LAY_GRID, 256, LAY_SMEM>>>(0, l, bq + l * 128, bo + l * 128);
        layer_mma<<<LAY_GRID, 256, LAY_SMEM>>>(1, l, b1 + l * 128, b2 + l * 128);
    }
    final_kernel<<<4096, 256, FIN_SMEM>>>(pw1, pb1, pw2, pb2, out);
}

// round 16
// speedup vs baseline: 3.8393x; 1.5893x over previous
#include <cuda_runtime.h>
#include <cuda_fp16.h>
#include <cstdint>

#define NQ 262144
#define MB 4096
#define PI_F 3.14159265358979323846f

extern __shared__ char smem_raw[];

// ------------------------- device scratch (no allocs) -----------------------
__device__ __align__(16) float g_h[(size_t)NQ * 128];
__device__ __align__(16) float g_x[(size_t)NQ * 128];
__device__ __align__(16) float g_benc[MB * 128];
__device__ __align__(16) float g_kvp[12 * 32 * 1024];
__device__ __align__(16) float g_ksp[12 * 32 * 32];
__device__ __align__(16) float g_kv[12 * 1024];
__device__ __align__(16) float g_ksum[384];
__device__ __align__(16) float g_C[3 * 16384];
// fp16 weights: [inv=l*2+mode][tile=B1,B2][n*128+k]
__device__ __align__(16) __half g_ws[6 * 2 * 16384];

__device__ __forceinline__ float geluf(float u) {
    return 0.5f * u * (1.0f + erff(u * 0.70710678118654752f));
}

__device__ __forceinline__ void cp_async16(void* dst_smem, const void* src) {
    uint32_t d = (uint32_t)__cvta_generic_to_shared(dst_smem);
    asm volatile("cp.async.cg.shared.global [%0], [%1], 16;" :: "r"(d), "l"(src));
}
__device__ __forceinline__ void cp_async_commit() {
    asm volatile("cp.async.commit_group;");
}
__device__ __forceinline__ void cp_async_wait_all() {
    asm volatile("cp.async.wait_group 0;");
}

// pack two fp32 into one fp16x2 register (x -> low half, y -> high half)
__device__ __forceinline__ uint32_t pack_h2(float x, float y) {
    __half2 h = __float22half2_rn(make_float2(x, y));
    uint32_t u;
    memcpy(&u, &h, 4);
    return u;
}

__device__ __forceinline__ void mma16816(float* d, const uint32_t* a,
                                         uint32_t b0, uint32_t b1) {
    asm volatile(
        "mma.sync.aligned.m16n8k16.row.col.f32.f16.f16.f32 "
        "{%0,%1,%2,%3}, {%4,%5,%6,%7}, {%8,%9}, {%0,%1,%2,%3};"
        : "+f"(d[0]), "+f"(d[1]), "+f"(d[2]), "+f"(d[3])
        : "r"(a[0]), "r"(a[1]), "r"(a[2]), "r"(a[3]), "r"(b0), "r"(b1));
}

// ---------------------------------------------------------------------------
// Positional encoder (fp32): dst[p][:] = sin(mfe(pts[p]) @ W + b). 64 pts/CTA.
// ---------------------------------------------------------------------------
__global__ void __launch_bounds__(256) encode_kernel(
    const float* __restrict__ pts, const float* __restrict__ w,
    const float* __restrict__ b, int which)
{
    __shared__ float sW[3840];
    __shared__ float sB[128];
    __shared__ float sF[64 * 32];
    int t = threadIdx.x;
    for (int i = t; i < 960; i += 256) ((float4*)sW)[i] = ((const float4*)w)[i];
    if (t < 128) sB[t] = b[t];
    size_t pt0 = (size_t)blockIdx.x * 64;
    if (t < 64) {
        float2 xy = ((const float2*)pts)[pt0 + t];
        float* F = sF + t * 32;
        #pragma unroll
        for (int c = 0; c < 2; ++c) {
            float v = c ? xy.y : xy.x;
            float a15 = v - 1.5f, a45 = v - 4.5f, pv = PI_F * v;
            F[0 + c] = v;           F[2 + c] = v * v;
            F[4 + c] = a15 * a15;   F[6 + c] = a45 * a45;
            F[8 + c]  = 1.f / (1.f + expf(-v));
            F[10 + c] = 1.f / (1.f + expf(-a15));
            F[12 + c] = 1.f / (1.f + expf(-a45));
            F[14 + c] = a15;        F[16 + c] = a45;
            F[18 + c] = sinf(pv);          F[20 + c] = cosf(pv);
            F[22 + c] = sinf(pv * 0.25f);  F[24 + c] = cosf(pv * 0.25f);
            F[26 + c] = sinf(pv * 0.5f);   F[28 + c] = cosf(pv * 0.5f);
        }
    }
    __syncthreads();
    int wid = t >> 5, lane = t & 31;
    int m0 = wid * 8, jc = lane * 4;
    float acc[8][4];
    #pragma unroll
    for (int i = 0; i < 8; ++i) { acc[i][0]=acc[i][1]=acc[i][2]=acc[i][3]=0.f; }
    #pragma unroll 2
    for (int k = 0; k < 30; ++k) {
        float4 b4 = *(const float4*)(sW + k * 128 + jc);
        #pragma unroll
        for (int i = 0; i < 8; ++i) {
            float a = sF[(m0 + i) * 32 + k];
            acc[i][0] = fmaf(a, b4.x, acc[i][0]);
            acc[i][1] = fmaf(a, b4.y, acc[i][1]);
            acc[i][2] = fmaf(a, b4.z, acc[i][2]);
            acc[i][3] = fmaf(a, b4.w, acc[i][3]);
        }
    }
    float b0 = sB[jc], b1 = sB[jc+1], b2 = sB[jc+2], b3 = sB[jc+3];
    float* dst = which ? g_benc : g_h;
    #pragma unroll
    for (int i = 0; i < 8; ++i) {
        float4 o;
        o.x = sinf(acc[i][0] + b0); o.y = sinf(acc[i][1] + b1);
        o.z = sinf(acc[i][2] + b2); o.w = sinf(acc[i][3] + b3);
        *(float4*)(dst + (pt0 + m0 + i) * 128 + jc) = o;
    }
}

// ---------------------------------------------------------------------------
// Boundary kv (fp32, tiny): per (tile, lh) partial kv / ksum.
// ---------------------------------------------------------------------------
#define BKV_SMEM (34372 * 4)
__global__ void __launch_bounds__(256) bkv_kernel(
    const float* __restrict__ Wk_g, const float* __restrict__ bk_g,
    const float* __restrict__ Wv_g, const float* __restrict__ bv_g)
{
    float* sm = (float*)smem_raw;
    float* sE  = sm;
    float* sWk = sE + 16896;
    float* sWv = sWk + 4100;
    float* sKh = sWv + 4096;
    float* sVh = sKh + 4608;
    float* sbk = sVh + 4608;
    float* sbv = sbk + 32;
    int t = threadIdx.x;
    int tile = blockIdx.x, lh = blockIdx.y;
    {
        const float4* src = (const float4*)(g_benc + (size_t)tile * 128 * 128);
        for (int i = t; i < 4096; i += 256) {
            int r = i >> 5, c = i & 31;
            *(float4*)(sE + r * 132 + c * 4) = src[i];
        }
    }
    for (int i = t; i < 1024; i += 256) {
        ((float4*)sWk)[i] = ((const float4*)(Wk_g + (size_t)lh * 4096))[i];
        ((float4*)sWv)[i] = ((const float4*)(Wv_g + (size_t)lh * 4096))[i];
    }
    if (t < 32) { sbk[t] = bk_g[lh * 32 + t]; sbv[t] = bv_g[lh * 32 + t]; }
    __syncthreads();
    {
        int m = t >> 1, kind = t & 1;
        const float* W  = kind ? sWv : sWk;
        const float* sb = kind ? sbv : sbk;
        float4 acc[8];
        #pragma unroll
        for (int g = 0; g < 8; ++g) acc[g] = make_float4(0.f, 0.f, 0.f, 0.f);
        for (int d = 0; d < 128; ++d) {
            float v = sE[m * 132 + d];
            #pragma unroll
            for (int g = 0; g < 8; ++g) {
                float4 w4 = *(const float4*)(W + d * 32 + g * 4);
                acc[g].x = fmaf(v, w4.x, acc[g].x);
                acc[g].y = fmaf(v, w4.y, acc[g].y);
                acc[g].z = fmaf(v, w4.z, acc[g].z);
                acc[g].w = fmaf(v, w4.w, acc[g].w);
            }
        }
        float* dst = (kind ? sVh : sKh) + m * 36;
        #pragma unroll
        for (int g = 0; g < 8; ++g) {
            float4 a = acc[g];
            a.x += sb[g*4+0]; a.y += sb[g*4+1]; a.z += sb[g*4+2]; a.w += sb[g*4+3];
            if (!kind) { a.x *= a.x; a.y *= a.y; a.z *= a.z; a.w *= a.w; }
            *(float4*)(dst + g * 4) = a;
        }
    }
    __syncthreads();
    {
        int e = t >> 3, c4 = (t & 7) * 4;
        float4 acc = make_float4(0.f, 0.f, 0.f, 0.f);
        for (int m = 0; m < 128; ++m) {
            float kh = sKh[m * 36 + e];
            float4 v4 = *(const float4*)(sVh + m * 36 + c4);
            acc.x = fmaf(kh, v4.x, acc.x); acc.y = fmaf(kh, v4.y, acc.y);
            acc.z = fmaf(kh, v4.z, acc.z); acc.w = fmaf(kh, v4.w, acc.w);
        }
        *(float4*)(g_kvp + ((size_t)lh * 32 + tile) * 1024 + e * 32 + c4) = acc;
        if (t < 32) {
            float s = 0.f;
            for (int m = 0; m < 128; ++m) s += sKh[m * 36 + t];
            g_ksp[((size_t)lh * 32 + tile) * 32 + t] = s;
        }
    }
}

__global__ void __launch_bounds__(256) kvreduce_kernel()
{
    int lh = blockIdx.x, t = threadIdx.x;
    for (int idx = t; idx < 1024; idx += 256) {
        float s = 0.f;
        for (int tile = 0; tile < 32; ++tile)
            s += g_kvp[((size_t)lh * 32 + tile) * 1024 + idx];
        g_kv[lh * 1024 + idx] = s;
    }
    if (t < 32) {
        float s = 0.f;
        for (int tile = 0; tile < 32; ++tile)
            s += g_ksp[((size_t)lh * 32 + tile) * 32 + t];
        g_ksum[lh * 32 + t] = s;
    }
}

__global__ void __launch_bounds__(256) cfold_kernel(const float* __restrict__ Wo_g)
{
    int l = blockIdx.x, t = threadIdx.x;
    int j = t >> 1, oc = (t & 1) * 64;
    int h = j >> 5, e = j & 31;
    float acc[64];
    #pragma unroll
    for (int o = 0; o < 64; ++o) acc[o] = 0.f;
    for (int ep = 0; ep < 32; ++ep) {
        float kv = g_kv[(l * 4 + h) * 1024 + e * 32 + ep];
        const float4* wr = (const float4*)(Wo_g + ((size_t)(l * 128 + h * 32 + ep)) * 128 + oc);
        #pragma unroll
        for (int g = 0; g < 16; ++g) {
            float4 w4 = __ldg(wr + g);
            acc[g*4+0] = fmaf(kv, w4.x, acc[g*4+0]);
            acc[g*4+1] = fmaf(kv, w4.y, acc[g*4+1]);
            acc[g*4+2] = fmaf(kv, w4.z, acc[g*4+2]);
            acc[g*4+3] = fmaf(kv, w4.w, acc[g*4+3]);
        }
    }
    float4* dst = (float4*)(g_C + (size_t)l * 16384 + j * 128 + oc);
    #pragma unroll
    for (int g = 0; g < 16; ++g)
        dst[g] = make_float4(acc[g*4], acc[g*4+1], acc[g*4+2], acc[g*4+3]);
}

// ---------------------------------------------------------------------------
// wprep: weights to fp16, transposed to [n][k]. grid (2, 6).
// ---------------------------------------------------------------------------
__global__ void __launch_bounds__(256) wprep_kernel(
    const float* __restrict__ Wq, const float* __restrict__ W1,
    const float* __restrict__ W2)
{
    int b = blockIdx.x, inv = blockIdx.y;
    int l = inv >> 1, mode = inv & 1;
    __half* dh = g_ws + ((size_t)(inv * 2 + b)) * 16384;
    for (int i = threadIdx.x; i < 16384; i += 256) {
        int n = i >> 7, k = i & 127;
        float v;
        if (b == 0)
            v = mode ? W1[(size_t)l * 16384 + k * 128 + n]
                     : Wq[(size_t)l * 16384 + (n >> 5) * 4096 + k * 32 + (n & 31)];
        else
            v = mode ? W2[(size_t)l * 16384 + k * 128 + n]
                     : g_C[(size_t)l * 16384 + k * 128 + n];
        dh[i] = __float2half_rn(v);
    }
}

// ---------------------------------------------------------------------------
// Persistent layer kernel: mma.sync m16n8k16 fp16 single-pass.
// smem = 3 tiles (A, B1, B2) -> 2 CTAs/SM; epilogue/staging of one CTA
// overlaps the co-resident CTA's tensor work.
// ---------------------------------------------------------------------------
#define TS 272                       // smem row stride in bytes
#define TILE_B (128 * TS)            // 34816
#define LAY_SMEM (3 * TILE_B + 1536) // 105984  (2 CTAs/SM)
#define NTILES 2048
#define LAY_GRID 296

__device__ __forceinline__ void do_gemm(
    float d[2][8][4], const char* A,
    const char* B, int rowbase, int colbase, int g, int tg)
{
    #pragma unroll
    for (int ks = 0; ks < 8; ++ks) {
        int kb = ks * 32 + tg * 4;
        uint32_t a[2][4];
        #pragma unroll
        for (int mt = 0; mt < 2; ++mt) {
            const char* ap = A + (rowbase + mt * 16 + g) * TS + kb;
            a[mt][0] = *(const uint32_t*)(ap);
            a[mt][1] = *(const uint32_t*)(ap + 8 * TS);
            a[mt][2] = *(const uint32_t*)(ap + 16);
            a[mt][3] = *(const uint32_t*)(ap + 8 * TS + 16);
        }
        #pragma unroll
        for (int nt = 0; nt < 8; ++nt) {
            const char* bp = B + (colbase + nt * 8 + g) * TS + kb;
            uint32_t b0 = *(const uint32_t*)(bp);
            uint32_t b1 = *(const uint32_t*)(bp + 16);
            mma16816(d[0][nt], a[0], b0, b1);
            mma16816(d[1][nt], a[1], b0, b1);
        }
    }
}

__global__ void __launch_bounds__(256, 2) layer_mma(
    int mode, int l, const float* __restrict__ b1p, const float* __restrict__ b2p)
{
    char* sm = smem_raw;
    char* sA  = sm;
    char* sB1 = sm + 1 * TILE_B;
    char* sB2 = sm + 2 * TILE_B;
    float* fB1 = (float*)(sm + 3 * TILE_B);
    float* fB2 = fB1 + 128;
    float* fKs = fB2 + 128;

    int t = threadIdx.x, wid = t >> 5, lane = t & 31;
    int g = lane >> 2, tg = lane & 3;
    const float* ain  = mode ? (const float*)g_x : (const float*)g_h;
    float*       aout = mode ? (float*)g_h : (float*)g_x;
    int rowbase = (wid & 3) * 32, colbase = (wid >> 2) * 64;

    // ---- stage both B tiles once per CTA (cp.async, stride TS) ----
    {
        const __half* ws = g_ws + (size_t)(l * 2 + mode) * 2 * 16384;
        #pragma unroll
        for (int tile2 = 0; tile2 < 2; ++tile2) {
            char* dst = sB1 + tile2 * TILE_B;
            const __half* src = ws + tile2 * 16384;
            #pragma unroll 2
            for (int it = 0; it < 8; ++it) {
                int idx = t + it * 256;
                int n = idx >> 4, c = idx & 15;
                cp_async16(dst + n * TS + c * 16, src + n * 128 + c * 8);
            }
        }
        cp_async_commit();
    }
    if (t < 128) {
        fB1[t] = b1p[t];
        fB2[t] = b2p[t];
        fKs[t] = (mode == 0) ? g_ksum[l * 128 + t] : 0.f;
    }
    bool first = true;

    for (int tile = blockIdx.x; tile < NTILES; tile += LAY_GRID) {
        size_t pt0 = (size_t)tile * 128;

        if (!first) __syncthreads();   // prior GEMM2 reads of sA done

        // ---- stage A (fp32 -> fp16, row-major stride TS) ----
        {
            const float* src = ain + pt0 * 128;
            #pragma unroll 4
            for (int it = 0; it < 16; ++it) {
                int i4 = t + it * 256;
                int row = i4 >> 5, c4 = (i4 & 31) * 4;
                float4 v = *(const float4*)(src + row * 128 + c4);
                uint32_t u01 = pack_h2(v.x, v.y);
                uint32_t u23 = pack_h2(v.z, v.w);
                *(unsigned long long*)(sA + row * TS + c4 * 2) =
                    ((unsigned long long)u23 << 32) | u01;
            }
        }
        if (first) { cp_async_wait_all(); first = false; }
        __syncthreads();

        // ---- GEMM 1 ----
        float d[2][8][4];
        #pragma unroll
        for (int mt = 0; mt < 2; ++mt)
            #pragma unroll
            for (int nt = 0; nt < 8; ++nt)
                { d[mt][nt][0]=0.f; d[mt][nt][1]=0.f; d[mt][nt][2]=0.f; d[mt][nt][3]=0.f; }
        do_gemm(d, sA, sB1, rowbase, colbase, g, tg);

        // ---- epilogue 1 ----
        if (mode == 0) {
            float s[2][2][2];   // [mt][j(row)][head]
            #pragma unroll
            for (int mt = 0; mt < 2; ++mt)
                { s[mt][0][0]=0.f; s[mt][0][1]=0.f; s[mt][1][0]=0.f; s[mt][1][1]=0.f; }
            #pragma unroll
            for (int nt = 0; nt < 8; ++nt) {
                int c = colbase + nt * 8 + tg * 2;
                float2 bb = *(const float2*)(fB1 + c);
                float2 kk = *(const float2*)(fKs + c);
                int hh = nt >> 2;
                #pragma unroll
                for (int mt = 0; mt < 2; ++mt) {
                    float u0 = d[mt][nt][0] + bb.x; u0 *= u0; d[mt][nt][0] = u0;
                    float u1 = d[mt][nt][1] + bb.y; u1 *= u1; d[mt][nt][1] = u1;
                    float u2 = d[mt][nt][2] + bb.x; u2 *= u2; d[mt][nt][2] = u2;
                    float u3 = d[mt][nt][3] + bb.y; u3 *= u3; d[mt][nt][3] = u3;
                    s[mt][0][hh] = fmaf(u0, kk.x, fmaf(u1, kk.y, s[mt][0][hh]));
                    s[mt][1][hh] = fmaf(u2, kk.x, fmaf(u3, kk.y, s[mt][1][hh]));
                }
            }
            float z[2][2][2];
            #pragma unroll
            for (int mt = 0; mt < 2; ++mt)
                #pragma unroll
                for (int j = 0; j < 2; ++j)
                    #pragma unroll
                    for (int hh = 0; hh < 2; ++hh) {
                        float v = s[mt][j][hh];
                        v += __shfl_xor_sync(0xffffffffu, v, 1);
                        v += __shfl_xor_sync(0xffffffffu, v, 2);
                        z[mt][j][hh] = 1.0f / (v + 1e-6f);
                    }
            #pragma unroll
            for (int nt = 0; nt < 8; ++nt) {
                int hh = nt >> 2;
                #pragma unroll
                for (int mt = 0; mt < 2; ++mt) {
                    d[mt][nt][0] *= z[mt][0][hh];
                    d[mt][nt][1] *= z[mt][0][hh];
                    d[mt][nt][2] *= z[mt][1][hh];
                    d[mt][nt][3] *= z[mt][1][hh];
                }
            }
        } else {
            #pragma unroll
            for (int nt = 0; nt < 8; ++nt) {
                int c = colbase + nt * 8 + tg * 2;
                float2 bb = *(const float2*)(fB1 + c);
                #pragma unroll
                for (int mt = 0; mt < 2; ++mt) {
                    d[mt][nt][0] = geluf(d[mt][nt][0] + bb.x);
                    d[mt][nt][1] = geluf(d[mt][nt][1] + bb.y);
                    d[mt][nt][2] = geluf(d[mt][nt][2] + bb.x);
                    d[mt][nt][3] = geluf(d[mt][nt][3] + bb.y);
                }
            }
        }
        __syncthreads();   // all warps done reading A before overwrite

        // ---- write A' (fp16) back to smem ----
        #pragma unroll
        for (int mt = 0; mt < 2; ++mt) {
            #pragma unroll
            for (int j = 0; j < 2; ++j) {
                int row = rowbase + mt * 16 + g + j * 8;
                #pragma unroll
                for (int nt = 0; nt < 8; ++nt) {
                    int cb = (colbase + nt * 8 + tg * 2) * 2;
                    *(uint32_t*)(sA + row * TS + cb) =
                        pack_h2(d[mt][nt][2 * j], d[mt][nt][2 * j + 1]);
                }
            }
        }
        __syncthreads();

        // ---- GEMM 2 ----
        #pragma unroll
        for (int mt = 0; mt < 2; ++mt)
            #pragma unroll
            for (int nt = 0; nt < 8; ++nt)
                { d[mt][nt][0]=0.f; d[mt][nt][1]=0.f; d[mt][nt][2]=0.f; d[mt][nt][3]=0.f; }
        do_gemm(d, sA, sB2, rowbase, colbase, g, tg);

        // ---- epilogue 2: out = residual + D + bias2 ----
        #pragma unroll
        for (int mt = 0; mt < 2; ++mt) {
            #pragma unroll
            for (int j = 0; j < 2; ++j) {
                int row = rowbase + mt * 16 + g + j * 8;
                const float* res = ain + (pt0 + row) * 128;
                float* dst = aout + (pt0 + row) * 128;
                #pragma unroll
                for (int nt = 0; nt < 8; ++nt) {
                    int c = colbase + nt * 8 + tg * 2;
                    float2 rv = *(const float2*)(res + c);
                    float2 bb = *(const float2*)(fB2 + c);
                    float2 o;
                    o.x = rv.x + d[mt][nt][2 * j]     + bb.x;
                    o.y = rv.y + d[mt][nt][2 * j + 1] + bb.y;
                    *(float2*)(dst + c) = o;
                }
            }
        }
    }
}

// ---------------------------------------------------------------------------
// Final projector (fp32): out = gelu(h @ pw1 + pb1) @ pw2 + pb2
// ---------------------------------------------------------------------------
#define FIN_SMEM (20812 * 4)
__global__ void __launch_bounds__(256) final_kernel(
    const float* __restrict__ pw1, const float* __restrict__ pb1,
    const float* __restrict__ pw2, const float* __restrict__ pb2,
    float* __restrict__ out)
{
    float* sm = (float*)smem_raw;
    float* sH   = sm;
    float* sW1  = sH + 8192;
    float* sT   = sW1 + 8192;
    float* spw2 = sT + 4160;
    float* spb1 = spw2 + 192;
    float* spb2 = spb1 + 64;
    int t = threadIdx.x;
    size_t pt0 = (size_t)blockIdx.x * 64;
    {
        const float4* src = (const float4*)(g_h + pt0 * 128);
        for (int i = t; i < 2048; i += 256) ((float4*)sH)[i] = src[i];
    }
    for (int i = t; i < 2048; i += 256) ((float4*)sW1)[i] = ((const float4*)pw1)[i];
    if (t < 192) spw2[t] = pw2[t];
    if (t < 64)  spb1[t] = pb1[t];
    if (t < 3)   spb2[t] = pb2[t];
    __syncthreads();
    int wid = t >> 5, lane = t & 31;
    int m0 = wid * 8, jc = lane * 2;
    float acc[8][2];
    #pragma unroll
    for (int i = 0; i < 8; ++i) { acc[i][0] = acc[i][1] = 0.f; }
    #pragma unroll 2
    for (int k = 0; k < 128; ++k) {
        float2 b2v = *(const float2*)(sW1 + k * 64 + jc);
        #pragma unroll
        for (int i = 0; i < 8; ++i) {
            float a = sH[(m0 + i) * 128 + k];
            acc[i][0] = fmaf(a, b2v.x, acc[i][0]);
            acc[i][1] = fmaf(a, b2v.y, acc[i][1]);
        }
    }
    float c0 = spb1[jc], c1 = spb1[jc + 1];
    #pragma unroll
    for (int i = 0; i < 8; ++i) {
        sT[(m0 + i) * 65 + jc]     = geluf(acc[i][0] + c0);
        sT[(m0 + i) * 65 + jc + 1] = geluf(acc[i][1] + c1);
    }
    __syncthreads();
    if (t < 192) {
        int n = t / 3, c = t - n * 3;
        float s = spb2[c];
        #pragma unroll 4
        for (int k = 0; k < 64; ++k) s = fmaf(sT[n * 65 + k], spw2[k * 3 + c], s);
        out[(pt0 + n) * 3 + c] = s;
    }
}

// ---------------------------------------------------------------------------
extern "C" void kernel_launch(void* const* d_in, const int* in_sizes, int n_in,
                              void* d_out, int out_size)
{
    const float* qp    = (const float*)d_in[0];
    const float* bp    = (const float*)d_in[1];
    const float* pe_w  = (const float*)d_in[2];
    const float* pe_b  = (const float*)d_in[3];
    const float* bpe_w = (const float*)d_in[4];
    const float* bpe_b = (const float*)d_in[5];
    const float* Wq    = (const float*)d_in[6];
    const float* bq    = (const float*)d_in[7];
    const float* Wk    = (const float*)d_in[8];
    const float* bk    = (const float*)d_in[9];
    const float* Wv    = (const float*)d_in[10];
    const float* bv    = (const float*)d_in[11];
    const float* Wo    = (const float*)d_in[12];
    const float* bo    = (const float*)d_in[13];
    const float* W1    = (const float*)d_in[14];
    const float* b1    = (const float*)d_in[15];
    const float* W2    = (const float*)d_in[16];
    const float* b2    = (const float*)d_in[17];
    const float* pw1   = (const float*)d_in[18];
    const float* pb1   = (const float*)d_in[19];
    const float* pw2   = (const float*)d_in[20];
    const float* pb2   = (const float*)d_in[21];
    float* out = (float*)d_out;

    cudaFuncSetAttribute(bkv_kernel,   cudaFuncAttributeMaxDynamicSharedMemorySize, BKV_SMEM);
    cudaFuncSetAttribute(layer_mma,    cudaFuncAttributeMaxDynamicSharedMemorySize, LAY_SMEM);
    cudaFuncSetAttribute(final_kernel, cudaFuncAttributeMaxDynamicSharedMemorySize, FIN_SMEM);

    encode_kernel<<<64,   256>>>(bp, bpe_w, bpe_b, 1);
    encode_kernel<<<4096, 256>>>(qp, pe_w,  pe_b,  0);
    bkv_kernel<<<dim3(32, 12), 256, BKV_SMEM>>>(Wk, bk, Wv, bv);
    kvreduce_kernel<<<12, 256>>>();
    cfold_kernel<<<3, 256>>>(Wo);
    wprep_kernel<<<dim3(2, 6), 256>>>(Wq, W1, W2);
    for (int l = 0; l < 3; ++l) {
        layer_mma<<<LAY_GRID, 256, LAY_SMEM>>>(0, l, bq + l * 128, bo + l * 128);
        layer_mma<<<LAY_GRID, 256, LAY_SMEM>>>(1, l, b1 + l * 128, b2 + l * 128);
    }
    final_kernel<<<4096, 256, FIN_SMEM>>>(pw1, pb1, pw2, pb2, out);
}

// round 17
// speedup vs baseline: 4.4118x; 1.1491x over previous
#include <cuda_runtime.h>
#include <cuda_fp16.h>
#include <cstdint>

#define NQ 262144
#define MB 4096
#define PI_F 3.14159265358979323846f

extern __shared__ char smem_raw[];

// ------------------------- device scratch (no allocs) -----------------------
__device__ __align__(16) float g_h[(size_t)NQ * 128];
__device__ __align__(16) float g_x[(size_t)NQ * 128];
__device__ __align__(16) float g_benc[MB * 128];
__device__ __align__(16) float g_kvp[12 * 32 * 1024];
__device__ __align__(16) float g_ksp[12 * 32 * 32];
__device__ __align__(16) float g_kv[12 * 1024];
__device__ __align__(16) float g_ksum[384];
__device__ __align__(16) float g_C[3 * 16384];
// fp16 weights: [inv=l*2+mode][tile=B1,B2][n*128+k]
__device__ __align__(16) __half g_ws[6 * 2 * 16384];
// fp16 final projector weight pw1^T: [n=0..63][k=0..127]
__device__ __align__(16) __half g_fw[64 * 128];

__device__ __forceinline__ float geluf(float u) {
    return 0.5f * u * (1.0f + erff(u * 0.70710678118654752f));
}

__device__ __forceinline__ void cp_async16(void* dst_smem, const void* src) {
    uint32_t d = (uint32_t)__cvta_generic_to_shared(dst_smem);
    asm volatile("cp.async.cg.shared.global [%0], [%1], 16;" :: "r"(d), "l"(src));
}
__device__ __forceinline__ void cp_async_commit() {
    asm volatile("cp.async.commit_group;");
}
__device__ __forceinline__ void cp_async_wait_all() {
    asm volatile("cp.async.wait_group 0;");
}

// pack two fp32 into one fp16x2 register (x -> low half, y -> high half)
__device__ __forceinline__ uint32_t pack_h2(float x, float y) {
    __half2 h = __float22half2_rn(make_float2(x, y));
    uint32_t u;
    memcpy(&u, &h, 4);
    return u;
}

__device__ __forceinline__ void mma16816(float* d, const uint32_t* a,
                                         uint32_t b0, uint32_t b1) {
    asm volatile(
        "mma.sync.aligned.m16n8k16.row.col.f32.f16.f16.f32 "
        "{%0,%1,%2,%3}, {%4,%5,%6,%7}, {%8,%9}, {%0,%1,%2,%3};"
        : "+f"(d[0]), "+f"(d[1]), "+f"(d[2]), "+f"(d[3])
        : "r"(a[0]), "r"(a[1]), "r"(a[2]), "r"(a[3]), "r"(b0), "r"(b1));
}

// ---------------------------------------------------------------------------
// Positional encoder (fp32): dst[p][:] = sin(mfe(pts[p]) @ W + b). 64 pts/CTA.
// ---------------------------------------------------------------------------
__global__ void __launch_bounds__(256) encode_kernel(
    const float* __restrict__ pts, const float* __restrict__ w,
    const float* __restrict__ b, int which)
{
    __shared__ float sW[3840];
    __shared__ float sB[128];
    __shared__ float sF[64 * 32];
    int t = threadIdx.x;
    for (int i = t; i < 960; i += 256) ((float4*)sW)[i] = ((const float4*)w)[i];
    if (t < 128) sB[t] = b[t];
    size_t pt0 = (size_t)blockIdx.x * 64;
    if (t < 64) {
        float2 xy = ((const float2*)pts)[pt0 + t];
        float* F = sF + t * 32;
        #pragma unroll
        for (int c = 0; c < 2; ++c) {
            float v = c ? xy.y : xy.x;
            float a15 = v - 1.5f, a45 = v - 4.5f, pv = PI_F * v;
            F[0 + c] = v;           F[2 + c] = v * v;
            F[4 + c] = a15 * a15;   F[6 + c] = a45 * a45;
            F[8 + c]  = 1.f / (1.f + expf(-v));
            F[10 + c] = 1.f / (1.f + expf(-a15));
            F[12 + c] = 1.f / (1.f + expf(-a45));
            F[14 + c] = a15;        F[16 + c] = a45;
            F[18 + c] = sinf(pv);          F[20 + c] = cosf(pv);
            F[22 + c] = sinf(pv * 0.25f);  F[24 + c] = cosf(pv * 0.25f);
            F[26 + c] = sinf(pv * 0.5f);   F[28 + c] = cosf(pv * 0.5f);
        }
    }
    __syncthreads();
    int wid = t >> 5, lane = t & 31;
    int m0 = wid * 8, jc = lane * 4;
    float acc[8][4];
    #pragma unroll
    for (int i = 0; i < 8; ++i) { acc[i][0]=acc[i][1]=acc[i][2]=acc[i][3]=0.f; }
    #pragma unroll 2
    for (int k = 0; k < 30; ++k) {
        float4 b4 = *(const float4*)(sW + k * 128 + jc);
        #pragma unroll
        for (int i = 0; i < 8; ++i) {
            float a = sF[(m0 + i) * 32 + k];
            acc[i][0] = fmaf(a, b4.x, acc[i][0]);
            acc[i][1] = fmaf(a, b4.y, acc[i][1]);
            acc[i][2] = fmaf(a, b4.z, acc[i][2]);
            acc[i][3] = fmaf(a, b4.w, acc[i][3]);
        }
    }
    float b0 = sB[jc], b1 = sB[jc+1], b2 = sB[jc+2], b3 = sB[jc+3];
    float* dst = which ? g_benc : g_h;
    #pragma unroll
    for (int i = 0; i < 8; ++i) {
        float4 o;
        o.x = sinf(acc[i][0] + b0); o.y = sinf(acc[i][1] + b1);
        o.z = sinf(acc[i][2] + b2); o.w = sinf(acc[i][3] + b3);
        *(float4*)(dst + (pt0 + m0 + i) * 128 + jc) = o;
    }
}

// ---------------------------------------------------------------------------
// Boundary kv (fp32, tiny): per (tile, lh) partial kv / ksum.
// ---------------------------------------------------------------------------
#define BKV_SMEM (34372 * 4)
__global__ void __launch_bounds__(256) bkv_kernel(
    const float* __restrict__ Wk_g, const float* __restrict__ bk_g,
    const float* __restrict__ Wv_g, const float* __restrict__ bv_g)
{
    float* sm = (float*)smem_raw;
    float* sE  = sm;
    float* sWk = sE + 16896;
    float* sWv = sWk + 4100;
    float* sKh = sWv + 4096;
    float* sVh = sKh + 4608;
    float* sbk = sVh + 4608;
    float* sbv = sbk + 32;
    int t = threadIdx.x;
    int tile = blockIdx.x, lh = blockIdx.y;
    {
        const float4* src = (const float4*)(g_benc + (size_t)tile * 128 * 128);
        for (int i = t; i < 4096; i += 256) {
            int r = i >> 5, c = i & 31;
            *(float4*)(sE + r * 132 + c * 4) = src[i];
        }
    }
    for (int i = t; i < 1024; i += 256) {
        ((float4*)sWk)[i] = ((const float4*)(Wk_g + (size_t)lh * 4096))[i];
        ((float4*)sWv)[i] = ((const float4*)(Wv_g + (size_t)lh * 4096))[i];
    }
    if (t < 32) { sbk[t] = bk_g[lh * 32 + t]; sbv[t] = bv_g[lh * 32 + t]; }
    __syncthreads();
    {
        int m = t >> 1, kind = t & 1;
        const float* W  = kind ? sWv : sWk;
        const float* sb = kind ? sbv : sbk;
        float4 acc[8];
        #pragma unroll
        for (int g = 0; g < 8; ++g) acc[g] = make_float4(0.f, 0.f, 0.f, 0.f);
        for (int d = 0; d < 128; ++d) {
            float v = sE[m * 132 + d];
            #pragma unroll
            for (int g = 0; g < 8; ++g) {
                float4 w4 = *(const float4*)(W + d * 32 + g * 4);
                acc[g].x = fmaf(v, w4.x, acc[g].x);
                acc[g].y = fmaf(v, w4.y, acc[g].y);
                acc[g].z = fmaf(v, w4.z, acc[g].z);
                acc[g].w = fmaf(v, w4.w, acc[g].w);
            }
        }
        float* dst = (kind ? sVh : sKh) + m * 36;
        #pragma unroll
        for (int g = 0; g < 8; ++g) {
            float4 a = acc[g];
            a.x += sb[g*4+0]; a.y += sb[g*4+1]; a.z += sb[g*4+2]; a.w += sb[g*4+3];
            if (!kind) { a.x *= a.x; a.y *= a.y; a.z *= a.z; a.w *= a.w; }
            *(float4*)(dst + g * 4) = a;
        }
    }
    __syncthreads();
    {
        int e = t >> 3, c4 = (t & 7) * 4;
        float4 acc = make_float4(0.f, 0.f, 0.f, 0.f);
        for (int m = 0; m < 128; ++m) {
            float kh = sKh[m * 36 + e];
            float4 v4 = *(const float4*)(sVh + m * 36 + c4);
            acc.x = fmaf(kh, v4.x, acc.x); acc.y = fmaf(kh, v4.y, acc.y);
            acc.z = fmaf(kh, v4.z, acc.z); acc.w = fmaf(kh, v4.w, acc.w);
        }
        *(float4*)(g_kvp + ((size_t)lh * 32 + tile) * 1024 + e * 32 + c4) = acc;
        if (t < 32) {
            float s = 0.f;
            for (int m = 0; m < 128; ++m) s += sKh[m * 36 + t];
            g_ksp[((size_t)lh * 32 + tile) * 32 + t] = s;
        }
    }
}

__global__ void __launch_bounds__(256) kvreduce_kernel()
{
    int lh = blockIdx.x, t = threadIdx.x;
    for (int idx = t; idx < 1024; idx += 256) {
        float s = 0.f;
        for (int tile = 0; tile < 32; ++tile)
            s += g_kvp[((size_t)lh * 32 + tile) * 1024 + idx];
        g_kv[lh * 1024 + idx] = s;
    }
    if (t < 32) {
        float s = 0.f;
        for (int tile = 0; tile < 32; ++tile)
            s += g_ksp[((size_t)lh * 32 + tile) * 32 + t];
        g_ksum[lh * 32 + t] = s;
    }
}

__global__ void __launch_bounds__(256) cfold_kernel(const float* __restrict__ Wo_g)
{
    int l = blockIdx.x, t = threadIdx.x;
    int j = t >> 1, oc = (t & 1) * 64;
    int h = j >> 5, e = j & 31;
    float acc[64];
    #pragma unroll
    for (int o = 0; o < 64; ++o) acc[o] = 0.f;
    for (int ep = 0; ep < 32; ++ep) {
        float kv = g_kv[(l * 4 + h) * 1024 + e * 32 + ep];
        const float4* wr = (const float4*)(Wo_g + ((size_t)(l * 128 + h * 32 + ep)) * 128 + oc);
        #pragma unroll
        for (int g = 0; g < 16; ++g) {
            float4 w4 = __ldg(wr + g);
            acc[g*4+0] = fmaf(kv, w4.x, acc[g*4+0]);
            acc[g*4+1] = fmaf(kv, w4.y, acc[g*4+1]);
            acc[g*4+2] = fmaf(kv, w4.z, acc[g*4+2]);
            acc[g*4+3] = fmaf(kv, w4.w, acc[g*4+3]);
        }
    }
    float4* dst = (float4*)(g_C + (size_t)l * 16384 + j * 128 + oc);
    #pragma unroll
    for (int g = 0; g < 16; ++g)
        dst[g] = make_float4(acc[g*4], acc[g*4+1], acc[g*4+2], acc[g*4+3]);
}

// ---------------------------------------------------------------------------
// wprep: weights to fp16, transposed to [n][k]. grid (2, 6).
// ---------------------------------------------------------------------------
__global__ void __launch_bounds__(256) wprep_kernel(
    const float* __restrict__ Wq, const float* __restrict__ W1,
    const float* __restrict__ W2)
{
    int b = blockIdx.x, inv = blockIdx.y;
    int l = inv >> 1, mode = inv & 1;
    __half* dh = g_ws + ((size_t)(inv * 2 + b)) * 16384;
    for (int i = threadIdx.x; i < 16384; i += 256) {
        int n = i >> 7, k = i & 127;
        float v;
        if (b == 0)
            v = mode ? W1[(size_t)l * 16384 + k * 128 + n]
                     : Wq[(size_t)l * 16384 + (n >> 5) * 4096 + k * 32 + (n & 31)];
        else
            v = mode ? W2[(size_t)l * 16384 + k * 128 + n]
                     : g_C[(size_t)l * 16384 + k * 128 + n];
        dh[i] = __float2half_rn(v);
    }
}

// fprep: pw1 [128][64] -> g_fw fp16 [n=64][k=128]
__global__ void __launch_bounds__(256) fprep_kernel(const float* __restrict__ pw1)
{
    for (int i = threadIdx.x; i < 8192; i += 256) {
        int n = i >> 7, k = i & 127;
        g_fw[i] = __float2half_rn(pw1[k * 64 + n]);
    }
}

// ---------------------------------------------------------------------------
// Persistent layer kernel: mma.sync m16n8k16 fp16 single-pass.
// smem = 3 tiles (A, B1, B2) -> 2 CTAs/SM.
// ---------------------------------------------------------------------------
#define TS 272                       // smem row stride in bytes
#define TILE_B (128 * TS)            // 34816
#define LAY_SMEM (3 * TILE_B + 1536) // 105984  (2 CTAs/SM)
#define NTILES 2048
#define LAY_GRID 296

__device__ __forceinline__ void do_gemm(
    float d[2][8][4], const char* A,
    const char* B, int rowbase, int colbase, int g, int tg)
{
    #pragma unroll
    for (int ks = 0; ks < 8; ++ks) {
        int kb = ks * 32 + tg * 4;
        uint32_t a[2][4];
        #pragma unroll
        for (int mt = 0; mt < 2; ++mt) {
            const char* ap = A + (rowbase + mt * 16 + g) * TS + kb;
            a[mt][0] = *(const uint32_t*)(ap);
            a[mt][1] = *(const uint32_t*)(ap + 8 * TS);
            a[mt][2] = *(const uint32_t*)(ap + 16);
            a[mt][3] = *(const uint32_t*)(ap + 8 * TS + 16);
        }
        #pragma unroll
        for (int nt = 0; nt < 8; ++nt) {
            const char* bp = B + (colbase + nt * 8 + g) * TS + kb;
            uint32_t b0 = *(const uint32_t*)(bp);
            uint32_t b1 = *(const uint32_t*)(bp + 16);
            mma16816(d[0][nt], a[0], b0, b1);
            mma16816(d[1][nt], a[1], b0, b1);
        }
    }
}

__global__ void __launch_bounds__(256, 2) layer_mma(
    int mode, int l, const float* __restrict__ b1p, const float* __restrict__ b2p)
{
    char* sm = smem_raw;
    char* sA  = sm;
    char* sB1 = sm + 1 * TILE_B;
    char* sB2 = sm + 2 * TILE_B;
    float* fB1 = (float*)(sm + 3 * TILE_B);
    float* fB2 = fB1 + 128;
    float* fKs = fB2 + 128;

    int t = threadIdx.x, wid = t >> 5, lane = t & 31;
    int g = lane >> 2, tg = lane & 3;
    const float* ain  = mode ? (const float*)g_x : (const float*)g_h;
    float*       aout = mode ? (float*)g_h : (float*)g_x;
    int rowbase = (wid & 3) * 32, colbase = (wid >> 2) * 64;

    // ---- stage both B tiles once per CTA (cp.async, stride TS) ----
    {
        const __half* ws = g_ws + (size_t)(l * 2 + mode) * 2 * 16384;
        #pragma unroll
        for (int tile2 = 0; tile2 < 2; ++tile2) {
            char* dst = sB1 + tile2 * TILE_B;
            const __half* src = ws + tile2 * 16384;
            #pragma unroll 2
            for (int it = 0; it < 8; ++it) {
                int idx = t + it * 256;
                int n = idx >> 4, c = idx & 15;
                cp_async16(dst + n * TS + c * 16, src + n * 128 + c * 8);
            }
        }
        cp_async_commit();
    }
    if (t < 128) {
        fB1[t] = b1p[t];
        fB2[t] = b2p[t];
        fKs[t] = (mode == 0) ? g_ksum[l * 128 + t] : 0.f;
    }
    bool first = true;

    for (int tile = blockIdx.x; tile < NTILES; tile += LAY_GRID) {
        size_t pt0 = (size_t)tile * 128;

        if (!first) __syncthreads();   // prior GEMM2 reads of sA done

        // ---- stage A (fp32 -> fp16, row-major stride TS) ----
        {
            const float* src = ain + pt0 * 128;
            #pragma unroll 4
            for (int it = 0; it < 16; ++it) {
                int i4 = t + it * 256;
                int row = i4 >> 5, c4 = (i4 & 31) * 4;
                float4 v = *(const float4*)(src + row * 128 + c4);
                uint32_t u01 = pack_h2(v.x, v.y);
                uint32_t u23 = pack_h2(v.z, v.w);
                *(unsigned long long*)(sA + row * TS + c4 * 2) =
                    ((unsigned long long)u23 << 32) | u01;
            }
        }
        if (first) { cp_async_wait_all(); first = false; }
        __syncthreads();

        // ---- GEMM 1 ----
        float d[2][8][4];
        #pragma unroll
        for (int mt = 0; mt < 2; ++mt)
            #pragma unroll
            for (int nt = 0; nt < 8; ++nt)
                { d[mt][nt][0]=0.f; d[mt][nt][1]=0.f; d[mt][nt][2]=0.f; d[mt][nt][3]=0.f; }
        do_gemm(d, sA, sB1, rowbase, colbase, g, tg);

        // ---- epilogue 1 ----
        if (mode == 0) {
            float s[2][2][2];   // [mt][j(row)][head]
            #pragma unroll
            for (int mt = 0; mt < 2; ++mt)
                { s[mt][0][0]=0.f; s[mt][0][1]=0.f; s[mt][1][0]=0.f; s[mt][1][1]=0.f; }
            #pragma unroll
            for (int nt = 0; nt < 8; ++nt) {
                int c = colbase + nt * 8 + tg * 2;
                float2 bb = *(const float2*)(fB1 + c);
                float2 kk = *(const float2*)(fKs + c);
                int hh = nt >> 2;
                #pragma unroll
                for (int mt = 0; mt < 2; ++mt) {
                    float u0 = d[mt][nt][0] + bb.x; u0 *= u0; d[mt][nt][0] = u0;
                    float u1 = d[mt][nt][1] + bb.y; u1 *= u1; d[mt][nt][1] = u1;
                    float u2 = d[mt][nt][2] + bb.x; u2 *= u2; d[mt][nt][2] = u2;
                    float u3 = d[mt][nt][3] + bb.y; u3 *= u3; d[mt][nt][3] = u3;
                    s[mt][0][hh] = fmaf(u0, kk.x, fmaf(u1, kk.y, s[mt][0][hh]));
                    s[mt][1][hh] = fmaf(u2, kk.x, fmaf(u3, kk.y, s[mt][1][hh]));
                }
            }
            float z[2][2][2];
            #pragma unroll
            for (int mt = 0; mt < 2; ++mt)
                #pragma unroll
                for (int j = 0; j < 2; ++j)
                    #pragma unroll
                    for (int hh = 0; hh < 2; ++hh) {
                        float v = s[mt][j][hh];
                        v += __shfl_xor_sync(0xffffffffu, v, 1);
                        v += __shfl_xor_sync(0xffffffffu, v, 2);
                        z[mt][j][hh] = 1.0f / (v + 1e-6f);
                    }
            #pragma unroll
            for (int nt = 0; nt < 8; ++nt) {
                int hh = nt >> 2;
                #pragma unroll
                for (int mt = 0; mt < 2; ++mt) {
                    d[mt][nt][0] *= z[mt][0][hh];
                    d[mt][nt][1] *= z[mt][0][hh];
                    d[mt][nt][2] *= z[mt][1][hh];
                    d[mt][nt][3] *= z[mt][1][hh];
                }
            }
        } else {
            #pragma unroll
            for (int nt = 0; nt < 8; ++nt) {
                int c = colbase + nt * 8 + tg * 2;
                float2 bb = *(const float2*)(fB1 + c);
                #pragma unroll
                for (int mt = 0; mt < 2; ++mt) {
                    d[mt][nt][0] = geluf(d[mt][nt][0] + bb.x);
                    d[mt][nt][1] = geluf(d[mt][nt][1] + bb.y);
                    d[mt][nt][2] = geluf(d[mt][nt][2] + bb.x);
                    d[mt][nt][3] = geluf(d[mt][nt][3] + bb.y);
                }
            }
        }
        __syncthreads();   // all warps done reading A before overwrite

        // ---- write A' (fp16) back to smem ----
        #pragma unroll
        for (int mt = 0; mt < 2; ++mt) {
            #pragma unroll
            for (int j = 0; j < 2; ++j) {
                int row = rowbase + mt * 16 + g + j * 8;
                #pragma unroll
                for (int nt = 0; nt < 8; ++nt) {
                    int cb = (colbase + nt * 8 + tg * 2) * 2;
                    *(uint32_t*)(sA + row * TS + cb) =
                        pack_h2(d[mt][nt][2 * j], d[mt][nt][2 * j + 1]);
                }
            }
        }
        __syncthreads();

        // ---- GEMM 2 ----
        #pragma unroll
        for (int mt = 0; mt < 2; ++mt)
            #pragma unroll
            for (int nt = 0; nt < 8; ++nt)
                { d[mt][nt][0]=0.f; d[mt][nt][1]=0.f; d[mt][nt][2]=0.f; d[mt][nt][3]=0.f; }
        do_gemm(d, sA, sB2, rowbase, colbase, g, tg);

        // ---- epilogue 2: out = residual + D + bias2 ----
        #pragma unroll
        for (int mt = 0; mt < 2; ++mt) {
            #pragma unroll
            for (int j = 0; j < 2; ++j) {
                int row = rowbase + mt * 16 + g + j * 8;
                const float* res = ain + (pt0 + row) * 128;
                float* dst = aout + (pt0 + row) * 128;
                #pragma unroll
                for (int nt = 0; nt < 8; ++nt) {
                    int c = colbase + nt * 8 + tg * 2;
                    float2 rv = *(const float2*)(res + c);
                    float2 bb = *(const float2*)(fB2 + c);
                    float2 o;
                    o.x = rv.x + d[mt][nt][2 * j]     + bb.x;
                    o.y = rv.y + d[mt][nt][2 * j + 1] + bb.y;
                    *(float2*)(dst + c) = o;
                }
            }
        }
    }
}

// ---------------------------------------------------------------------------
// Final projector (tensor): out = gelu(h @ pw1 + pb1) @ pw2 + pb2
// Persistent, 2 CTAs/SM. GEMM1 on fp16 MMA; tiny K=64 -> 3 GEMM2 in fp32.
// ---------------------------------------------------------------------------
#define FTS 72                                   // sT row stride (floats)
#define FIN_SMEM (TILE_B + 64 * TS + 128 * FTS * 4 + 1536)  // 90624
__global__ void __launch_bounds__(256, 2) final_mma(
    const float* __restrict__ pb1, const float* __restrict__ pw2,
    const float* __restrict__ pb2, float* __restrict__ out)
{
    char* sm = smem_raw;
    char* sA = sm;                                // 128 x TS (fp16)
    char* sW = sm + TILE_B;                       // 64 x TS  (fp16, pw1^T)
    float* sT  = (float*)(sm + TILE_B + 64 * TS); // 128 x FTS
    float* spb1 = (float*)(sm + TILE_B + 64 * TS + 128 * FTS * 4);
    float* spw2 = spb1 + 64;                      // 192
    float* spb2 = spw2 + 192;                     // 3

    int t = threadIdx.x, wid = t >> 5, lane = t & 31;
    int g = lane >> 2, tg = lane & 3;
    int rowbase = (wid & 3) * 32, colbase = (wid >> 2) * 32;

    // stage B = pw1^T fp16 (64 rows x 128 cols) once per CTA
    #pragma unroll
    for (int it = 0; it < 4; ++it) {
        int idx = t + it * 256;                    // 0..1023
        int n = idx >> 4, c = idx & 15;
        cp_async16(sW + n * TS + c * 16, g_fw + n * 128 + c * 8);
    }
    cp_async_commit();
    if (t < 64)  spb1[t] = pb1[t];
    if (t < 192) spw2[t] = pw2[t];
    if (t < 3)   spb2[t] = pb2[t];
    bool first = true;

    for (int tile = blockIdx.x; tile < NTILES; tile += LAY_GRID) {
        size_t pt0 = (size_t)tile * 128;

        if (!first) __syncthreads();   // prior GEMM1 reads of sA done

        // ---- stage A (fp32 -> fp16) ----
        {
            const float* src = g_h + pt0 * 128;
            #pragma unroll 4
            for (int it = 0; it < 16; ++it) {
                int i4 = t + it * 256;
                int row = i4 >> 5, c4 = (i4 & 31) * 4;
                float4 v = *(const float4*)(src + row * 128 + c4);
                uint32_t u01 = pack_h2(v.x, v.y);
                uint32_t u23 = pack_h2(v.z, v.w);
                *(unsigned long long*)(sA + row * TS + c4 * 2) =
                    ((unsigned long long)u23 << 32) | u01;
            }
        }
        if (first) { cp_async_wait_all(); first = false; }
        __syncthreads();

        // ---- GEMM1: [128x128] @ [128x64], warp tile 32x32 ----
        float d[2][4][4];
        #pragma unroll
        for (int mt = 0; mt < 2; ++mt)
            #pragma unroll
            for (int nt = 0; nt < 4; ++nt)
                { d[mt][nt][0]=0.f; d[mt][nt][1]=0.f; d[mt][nt][2]=0.f; d[mt][nt][3]=0.f; }
        #pragma unroll
        for (int ks = 0; ks < 8; ++ks) {
            int kb = ks * 32 + tg * 4;
            uint32_t a[2][4];
            #pragma unroll
            for (int mt = 0; mt < 2; ++mt) {
                const char* ap = sA + (rowbase + mt * 16 + g) * TS + kb;
                a[mt][0] = *(const uint32_t*)(ap);
                a[mt][1] = *(const uint32_t*)(ap + 8 * TS);
                a[mt][2] = *(const uint32_t*)(ap + 16);
                a[mt][3] = *(const uint32_t*)(ap + 8 * TS + 16);
            }
            #pragma unroll
            for (int nt = 0; nt < 4; ++nt) {
                const char* bp = sW + (colbase + nt * 8 + g) * TS + kb;
                uint32_t b0 = *(const uint32_t*)(bp);
                uint32_t b1 = *(const uint32_t*)(bp + 16);
                mma16816(d[0][nt], a[0], b0, b1);
                mma16816(d[1][nt], a[1], b0, b1);
            }
        }

        // ---- epilogue: gelu -> sT (fp32, stride FTS) ----
        #pragma unroll
        for (int nt = 0; nt < 4; ++nt) {
            int c = colbase + nt * 8 + tg * 2;
            float b0 = spb1[c], b1v = spb1[c + 1];
            #pragma unroll
            for (int mt = 0; mt < 2; ++mt) {
                #pragma unroll
                for (int j = 0; j < 2; ++j) {
                    int row = rowbase + mt * 16 + g + j * 8;
                    float2 o;
                    o.x = geluf(d[mt][nt][2 * j]     + b0);
                    o.y = geluf(d[mt][nt][2 * j + 1] + b1v);
                    *(float2*)(sT + row * FTS + c) = o;
                }
            }
        }
        __syncthreads();

        // ---- GEMM2: [128x64] @ [64x3] in fp32 scalar ----
        for (int task = t; task < 384; task += 256) {
            int n = task / 3, c = task - n * 3;
            float s = spb2[c];
            #pragma unroll 4
            for (int k = 0; k < 64; ++k)
                s = fmaf(sT[n * FTS + k], spw2[k * 3 + c], s);
            out[(pt0 + n) * 3 + c] = s;
        }
    }
}

// ---------------------------------------------------------------------------
extern "C" void kernel_launch(void* const* d_in, const int* in_sizes, int n_in,
                              void* d_out, int out_size)
{
    const float* qp    = (const float*)d_in[0];
    const float* bp    = (const float*)d_in[1];
    const float* pe_w  = (const float*)d_in[2];
    const float* pe_b  = (const float*)d_in[3];
    const float* bpe_w = (const float*)d_in[4];
    const float* bpe_b = (const float*)d_in[5];
    const float* Wq    = (const float*)d_in[6];
    const float* bq    = (const float*)d_in[7];
    const float* Wk    = (const float*)d_in[8];
    const float* bk    = (const float*)d_in[9];
    const float* Wv    = (const float*)d_in[10];
    const float* bv    = (const float*)d_in[11];
    const float* Wo    = (const float*)d_in[12];
    const float* bo    = (const float*)d_in[13];
    const float* W1    = (const float*)d_in[14];
    const float* b1    = (const float*)d_in[15];
    const float* W2    = (const float*)d_in[16];
    const float* b2    = (const float*)d_in[17];
    const float* pw1   = (const float*)d_in[18];
    const float* pb1   = (const float*)d_in[19];
    const float* pw2   = (const float*)d_in[20];
    const float* pb2   = (const float*)d_in[21];
    float* out = (float*)d_out;

    cudaFuncSetAttribute(bkv_kernel, cudaFuncAttributeMaxDynamicSharedMemorySize, BKV_SMEM);
    cudaFuncSetAttribute(layer_mma,  cudaFuncAttributeMaxDynamicSharedMemorySize, LAY_SMEM);
    cudaFuncSetAttribute(final_mma,  cudaFuncAttributeMaxDynamicSharedMemorySize, FIN_SMEM);

    encode_kernel<<<64,   256>>>(bp, bpe_w, bpe_b, 1);
    encode_kernel<<<4096, 256>>>(qp, pe_w,  pe_b,  0);
    bkv_kernel<<<dim3(32, 12), 256, BKV_SMEM>>>(Wk, bk, Wv, bv);
    kvreduce_kernel<<<12, 256>>>();
    cfold_kernel<<<3, 256>>>(Wo);
    wprep_kernel<<<dim3(2, 6), 256>>>(Wq, W1, W2);
    fprep_kernel<<<1, 256>>>(pw1);
    for (int l = 0; l < 3; ++l) {
        layer_mma<<<LAY_GRID, 256, LAY_SMEM>>>(0, l, bq + l * 128, bo + l * 128);
        layer_mma<<<LAY_GRID, 256, LAY_SMEM>>>(1, l, b1 + l * 128, b2 + l * 128);
    }
    final_mma<<<LAY_GRID, 256, FIN_SMEM>>>(pb1, pw2, pb2, out);
}